// round 2
// baseline (speedup 1.0000x reference)
#include <cuda_runtime.h>
#include <cuda_bf16.h>
#include <math.h>

#define NN 20000
#define FF 256
#define HH 8
#define DD 64
#define HD 512
#define MM 2
#define EE 320000
#define CC 5
#define HIDD 128

// ---------------- scratch (device globals; no allocation) ----------------
__device__ float g_feat[MM * NN * HD];      // projected features per metapath
__device__ float g_z[MM * NN * HD];         // GAT output per metapath
__device__ float g_el[MM * NN * HH];
__device__ float g_er[MM * NN * HH];
__device__ float g_den[MM * NN * HH];
__device__ int   g_hist[MM * NN];
__device__ int   g_rowptr[MM * (NN + 1)];
__device__ int   g_cursor[MM * NN];
__device__ int   g_src_s[MM * EE];
__device__ float g_ex_s[MM * EE * HH];
__device__ float g_c1[MM * NN * HIDD];
__device__ float g_s[MM * NN];
__device__ float g_sum[MM];
__device__ float g_beta[MM];

// ---------------- zero init ----------------
__global__ void zero_kernel() {
    int i = blockIdx.x * blockDim.x + threadIdx.x;
    int total = MM * NN * HH + MM * NN + MM;
    for (; i < total; i += gridDim.x * blockDim.x) {
        if (i < MM * NN * HH) g_den[i] = 0.0f;
        else if (i < MM * NN * HH + MM * NN) g_hist[i - MM * NN * HH] = 0;
        else g_sum[i - MM * NN * HH - MM * NN] = 0.0f;
    }
}

// ---------------- generic tiled fp32 GEMM: C = A[M,K] @ B[K,N] ----------------
// act==1: C = tanh(C + bias[col])
#define BM 64
#define BN 64
#define BK 16
__global__ void gemm_tiled(const float* __restrict__ A, const float* __restrict__ B,
                           float* __restrict__ C, int Mrows, int K, int Ncols,
                           const float* __restrict__ bias, int act,
                           long aStride, long bStride, long cStride) {
    int bz = blockIdx.z;
    A += (size_t)bz * aStride;
    B += (size_t)bz * bStride;
    C += (size_t)bz * cStride;

    __shared__ __align__(16) float As[BK][BM];
    __shared__ __align__(16) float Bs[BK][BN];

    int tid = threadIdx.x;
    int tx = tid & 15;
    int ty = tid >> 4;
    int rowBase = blockIdx.y * BM;
    int colBase = blockIdx.x * BN;

    int arow = tid >> 2;            // 0..63
    int acol = (tid & 3) * 4;       // 0,4,8,12
    int brow = tid >> 4;            // 0..15
    int bcol = (tid & 15) * 4;      // 0..60

    float acc[4][4];
#pragma unroll
    for (int i = 0; i < 4; i++)
#pragma unroll
        for (int j = 0; j < 4; j++) acc[i][j] = 0.0f;

    for (int k0 = 0; k0 < K; k0 += BK) {
        float4 av = make_float4(0.f, 0.f, 0.f, 0.f);
        int ga = rowBase + arow;
        if (ga < Mrows) av = *(const float4*)(A + (size_t)ga * K + k0 + acol);
        As[acol + 0][arow] = av.x;
        As[acol + 1][arow] = av.y;
        As[acol + 2][arow] = av.z;
        As[acol + 3][arow] = av.w;

        float4 bv = *(const float4*)(B + (size_t)(k0 + brow) * Ncols + colBase + bcol);
        *(float4*)&Bs[brow][bcol] = bv;
        __syncthreads();

#pragma unroll
        for (int k = 0; k < BK; k++) {
            float4 a = *(const float4*)&As[k][ty * 4];
            float4 b = *(const float4*)&Bs[k][tx * 4];
            acc[0][0] += a.x * b.x; acc[0][1] += a.x * b.y; acc[0][2] += a.x * b.z; acc[0][3] += a.x * b.w;
            acc[1][0] += a.y * b.x; acc[1][1] += a.y * b.y; acc[1][2] += a.y * b.z; acc[1][3] += a.y * b.w;
            acc[2][0] += a.z * b.x; acc[2][1] += a.z * b.y; acc[2][2] += a.z * b.z; acc[2][3] += a.z * b.w;
            acc[3][0] += a.w * b.x; acc[3][1] += a.w * b.y; acc[3][2] += a.w * b.z; acc[3][3] += a.w * b.w;
        }
        __syncthreads();
    }

#pragma unroll
    for (int i = 0; i < 4; i++) {
        int r = rowBase + ty * 4 + i;
        if (r >= Mrows) continue;
        int c0 = colBase + tx * 4;
        float4 v = make_float4(acc[i][0], acc[i][1], acc[i][2], acc[i][3]);
        if (act == 1) {
            v.x = tanhf(v.x + bias[c0 + 0]);
            v.y = tanhf(v.y + bias[c0 + 1]);
            v.z = tanhf(v.z + bias[c0 + 2]);
            v.w = tanhf(v.w + bias[c0 + 3]);
        }
        *(float4*)(C + (size_t)r * Ncols + c0) = v;
    }
}

// ---------------- el / er : per-(m,n,h) attention logits ----------------
__global__ void lr_kernel(const float* __restrict__ al, const float* __restrict__ ar) {
    int gw = (blockIdx.x * blockDim.x + threadIdx.x) >> 5;
    int lane = threadIdx.x & 31;
    if (gw >= MM * NN * HH) return;
    int m = gw / (NN * HH);
    int r = gw % (NN * HH);
    int n = r / HH;
    int h = r % HH;
    const float* f = g_feat + ((size_t)(m * NN + n)) * HD + h * DD;
    const float* a = al + (m * HH + h) * DD;
    const float* b = ar + (m * HH + h) * DD;
    float f1 = f[lane], f2 = f[lane + 32];
    float sl = f1 * a[lane] + f2 * a[lane + 32];
    float sr = f1 * b[lane] + f2 * b[lane + 32];
#pragma unroll
    for (int off = 16; off > 0; off >>= 1) {
        sl += __shfl_down_sync(0xffffffffu, sl, off);
        sr += __shfl_down_sync(0xffffffffu, sr, off);
    }
    if (lane == 0) {
        g_el[(m * NN + n) * HH + h] = sl;
        g_er[(m * NN + n) * HH + h] = sr;
    }
}

// ---------------- in-degree histogram ----------------
__global__ void hist_kernel(const int* __restrict__ dst) {
    int tid = blockIdx.x * blockDim.x + threadIdx.x;
    if (tid >= MM * EE) return;
    int m = tid / EE;
    atomicAdd(&g_hist[m * NN + dst[tid]], 1);
}

// ---------------- single-block exclusive scan per metapath ----------------
__global__ void scan_kernel() {
    int m = blockIdx.x;
    __shared__ int part[1024];
    int t = threadIdx.x;
    const int CH = 20;   // 1024*20 = 20480 >= NN
    int base = t * CH;
    int local[CH];
    int s = 0;
#pragma unroll
    for (int i = 0; i < CH; i++) {
        int idx = base + i;
        int v = (idx < NN) ? g_hist[m * NN + idx] : 0;
        local[i] = v;
        s += v;
    }
    part[t] = s;
    __syncthreads();
    for (int off = 1; off < 1024; off <<= 1) {
        int v = (t >= off) ? part[t - off] : 0;
        __syncthreads();
        part[t] += v;
        __syncthreads();
    }
    int run = part[t] - s;   // exclusive prefix
#pragma unroll
    for (int i = 0; i < CH; i++) {
        int idx = base + i;
        if (idx < NN) {
            g_rowptr[m * (NN + 1) + idx] = run;
            g_cursor[m * NN + idx] = run;
            run += local[i];
        }
    }
    if (t == 1023) g_rowptr[m * (NN + 1) + NN] = run;
}

// ---------------- edge pass: exp(leaky(el+er)), den accumulate, CSR scatter ----------------
__global__ void edge_kernel(const int* __restrict__ src, const int* __restrict__ dst) {
    int tid = blockIdx.x * blockDim.x + threadIdx.x;
    if (tid >= MM * EE) return;
    int m = tid / EE;
    int s = src[tid];
    int d = dst[tid];
    const float4* elp = (const float4*)(g_el + (size_t)(m * NN + s) * HH);
    const float4* erp = (const float4*)(g_er + (size_t)(m * NN + d) * HH);
    float4 e0 = elp[0], e1 = elp[1];
    float4 r0 = erp[0], r1 = erp[1];
    float ex[8];
    float v;
    v = e0.x + r0.x; v = v > 0.f ? v : 0.2f * v; ex[0] = expf(v);
    v = e0.y + r0.y; v = v > 0.f ? v : 0.2f * v; ex[1] = expf(v);
    v = e0.z + r0.z; v = v > 0.f ? v : 0.2f * v; ex[2] = expf(v);
    v = e0.w + r0.w; v = v > 0.f ? v : 0.2f * v; ex[3] = expf(v);
    v = e1.x + r1.x; v = v > 0.f ? v : 0.2f * v; ex[4] = expf(v);
    v = e1.y + r1.y; v = v > 0.f ? v : 0.2f * v; ex[5] = expf(v);
    v = e1.z + r1.z; v = v > 0.f ? v : 0.2f * v; ex[6] = expf(v);
    v = e1.w + r1.w; v = v > 0.f ? v : 0.2f * v; ex[7] = expf(v);

    float* denp = g_den + (size_t)(m * NN + d) * HH;
#pragma unroll
    for (int h = 0; h < 8; h++) atomicAdd(denp + h, ex[h]);

    int pos = atomicAdd(&g_cursor[m * NN + d], 1);
    int gp = m * EE + pos;
    g_src_s[gp] = s;
    float4* xp = (float4*)(g_ex_s + (size_t)gp * HH);
    xp[0] = make_float4(ex[0], ex[1], ex[2], ex[3]);
    xp[1] = make_float4(ex[4], ex[5], ex[6], ex[7]);
}

// ---------------- aggregation: one block per (node, metapath), atomic-free ----------------
__global__ void agg_kernel(const float* __restrict__ bg) {
    int n = blockIdx.x;
    int m = blockIdx.y;
    int t = threadIdx.x;           // 0..127, owns dims [4t, 4t+4)
    int h = t >> 4;
    float den = g_den[(m * NN + n) * HH + h];
    float inv = 1.0f / fmaxf(den, 1e-9f);
    int beg = g_rowptr[m * (NN + 1) + n];
    int end = g_rowptr[m * (NN + 1) + n + 1];
    float ax = 0.f, ay = 0.f, az = 0.f, aw = 0.f;
    for (int j = beg; j < end; j++) {
        int gp = m * EE + j;
        int s = g_src_s[gp];
        float a = g_ex_s[(size_t)gp * HH + h] * inv;
        float4 f = *(const float4*)(g_feat + ((size_t)(m * NN + s)) * HD + t * 4);
        ax += a * f.x; ay += a * f.y; az += a * f.z; aw += a * f.w;
    }
    const float* bp = bg + m * HD + t * 4;
    float o0 = ax + bp[0], o1 = ay + bp[1], o2 = az + bp[2], o3 = aw + bp[3];
    o0 = o0 > 0.f ? o0 : expf(o0) - 1.0f;
    o1 = o1 > 0.f ? o1 : expf(o1) - 1.0f;
    o2 = o2 > 0.f ? o2 : expf(o2) - 1.0f;
    o3 = o3 > 0.f ? o3 : expf(o3) - 1.0f;
    *(float4*)(g_z + ((size_t)(m * NN + n)) * HD + t * 4) = make_float4(o0, o1, o2, o3);
}

// ---------------- semantic score s[r] = c1[r] . W2 ----------------
__global__ void s_kernel(const float* __restrict__ sW2) {
    int gw = (blockIdx.x * blockDim.x + threadIdx.x) >> 5;
    int lane = threadIdx.x & 31;
    if (gw >= MM * NN) return;
    const float* c = g_c1 + (size_t)gw * HIDD;
    float v = c[lane] * sW2[lane] + c[lane + 32] * sW2[lane + 32] +
              c[lane + 64] * sW2[lane + 64] + c[lane + 96] * sW2[lane + 96];
#pragma unroll
    for (int off = 16; off > 0; off >>= 1) v += __shfl_down_sync(0xffffffffu, v, off);
    if (lane == 0) g_s[gw] = v;
}

// ---------------- mean over nodes per metapath ----------------
__global__ void reduce_kernel() {
    int m = blockIdx.y;
    int t = threadIdx.x;
    float s = 0.f;
    for (int i = blockIdx.x * blockDim.x + t; i < NN; i += gridDim.x * blockDim.x)
        s += g_s[m * NN + i];
    __shared__ float sh[256];
    sh[t] = s;
    __syncthreads();
    for (int off = 128; off > 0; off >>= 1) {
        if (t < off) sh[t] += sh[t + off];
        __syncthreads();
    }
    if (t == 0) atomicAdd(&g_sum[m], sh[0]);
}

__global__ void beta_kernel() {
    float a = g_sum[0] / (float)NN;
    float b = g_sum[1] / (float)NN;
    float mx = fmaxf(a, b);
    float e0 = expf(a - mx), e1 = expf(b - mx);
    float inv = 1.0f / (e0 + e1);
    g_beta[0] = e0 * inv;
    g_beta[1] = e1 * inv;
}

// ---------------- final: out = (beta0*z0 + beta1*z1) @ pred_W + pred_b ----------------
__global__ void final_kernel(const float* __restrict__ pW, const float* __restrict__ pb,
                             float* __restrict__ out) {
    int n = blockIdx.x;
    int t = threadIdx.x;         // 128 threads, dims [4t,4t+4)
    float b0 = g_beta[0], b1 = g_beta[1];
    float4 z0 = *(const float4*)(g_z + (size_t)n * HD + t * 4);
    float4 z1 = *(const float4*)(g_z + (size_t)(NN + n) * HD + t * 4);
    float hk[4] = {b0 * z0.x + b1 * z1.x, b0 * z0.y + b1 * z1.y,
                   b0 * z0.z + b1 * z1.z, b0 * z0.w + b1 * z1.w};
    float acc[5] = {0.f, 0.f, 0.f, 0.f, 0.f};
#pragma unroll
    for (int j = 0; j < 4; j++) {
        int k = t * 4 + j;
        const float* w = pW + k * CC;
#pragma unroll
        for (int c = 0; c < 5; c++) acc[c] += hk[j] * w[c];
    }
#pragma unroll
    for (int c = 0; c < 5; c++)
#pragma unroll
        for (int off = 16; off > 0; off >>= 1)
            acc[c] += __shfl_down_sync(0xffffffffu, acc[c], off);
    __shared__ float sh[4][5];
    int warp = t >> 5, lane = t & 31;
    if (lane == 0)
#pragma unroll
        for (int c = 0; c < 5; c++) sh[warp][c] = acc[c];
    __syncthreads();
    if (t < 5) {
        float v = pb[t];
#pragma unroll
        for (int w = 0; w < 4; w++) v += sh[w][t];
        out[n * CC + t] = v;
    }
}

// ---------------- launch ----------------
extern "C" void kernel_launch(void* const* d_in, const int* in_sizes, int n_in,
                              void* d_out, int out_size) {
    const float* h    = (const float*)d_in[0];
    const int*   src  = (const int*)d_in[1];
    const int*   dst  = (const int*)d_in[2];
    const float* W    = (const float*)d_in[3];
    const float* al   = (const float*)d_in[4];
    const float* ar   = (const float*)d_in[5];
    const float* bg   = (const float*)d_in[6];
    const float* sW1  = (const float*)d_in[7];
    const float* sb1  = (const float*)d_in[8];
    const float* sW2  = (const float*)d_in[9];
    const float* pW   = (const float*)d_in[10];
    const float* pb   = (const float*)d_in[11];
    float* out = (float*)d_out;

    float *p_feat, *p_z, *p_c1;
    cudaGetSymbolAddress((void**)&p_feat, g_feat);
    cudaGetSymbolAddress((void**)&p_z, g_z);
    cudaGetSymbolAddress((void**)&p_c1, g_c1);

    zero_kernel<<<1407, 256>>>();

    // feat[m] = h @ W[m]   (A batched with stride 0)
    gemm_tiled<<<dim3(HD / BN, (NN + BM - 1) / BM, MM), 256>>>(
        h, W, p_feat, NN, FF, HD, nullptr, 0,
        0L, (long)FF * HD, (long)NN * HD);

    lr_kernel<<<(MM * NN * HH * 32 + 255) / 256, 256>>>(al, ar);
    hist_kernel<<<(MM * EE + 255) / 256, 256>>>(dst);
    scan_kernel<<<MM, 1024>>>();
    edge_kernel<<<(MM * EE + 255) / 256, 256>>>(src, dst);
    agg_kernel<<<dim3(NN, MM), 128>>>(bg);

    // c1 = tanh(z @ sem_W1 + b1), rows = M*N
    gemm_tiled<<<dim3(HIDD / BN, (MM * NN) / BM, 1), 256>>>(
        p_z, sW1, p_c1, MM * NN, HD, HIDD, sb1, 1, 0L, 0L, 0L);

    s_kernel<<<(MM * NN * 32 + 255) / 256, 256>>>(sW2);
    reduce_kernel<<<dim3(40, MM), 256>>>();
    beta_kernel<<<1, 1>>>();
    final_kernel<<<NN, 128>>>(pW, pb, out);
}

// round 3
// speedup vs baseline: 2.5144x; 2.5144x over previous
#include <cuda_runtime.h>
#include <cuda_bf16.h>
#include <math.h>
#include <stdint.h>

#define NN 20000
#define FF 256
#define HH 8
#define DD 64
#define HD 512
#define MM 2
#define EE 320000
#define CC 5
#define HIDD 128

// ---------------- scratch (device globals; no allocation) ----------------
__device__ float g_feat[MM * NN * HD];
__device__ float g_z[MM * NN * HD];
__device__ float g_el[MM * NN * HH];
__device__ float g_er[MM * NN * HH];
__device__ int   g_hist[MM * NN];
__device__ int   g_rowptr[MM * (NN + 1)];
__device__ int   g_cursor[MM * NN];
__device__ int   g_src_s[MM * EE];
__device__ float g_ex_s[MM * EE * HH];
__device__ float g_c1[MM * NN * HIDD];
__device__ float g_s[MM * NN];
__device__ float g_sum[MM];
__device__ float g_beta[MM];

// ---------------- zero init (hist + sum only now) ----------------
__global__ void zero_kernel() {
    int i = blockIdx.x * blockDim.x + threadIdx.x;
    int total = MM * NN + MM;
    for (; i < total; i += gridDim.x * blockDim.x) {
        if (i < MM * NN) g_hist[i] = 0;
        else g_sum[i - MM * NN] = 0.0f;
    }
}

// ---------------- TF32 tensor-core GEMM: C = A[M,K] @ B[K,N] ----------------
// act==1: C = tanh(C + bias[col])
#define GBM 128
#define GBN 64
#define GBK 32
#define AS_STRIDE 36   // conflict-free A fragment reads
#define BS_STRIDE 72   // conflict-free B fragment reads (72 mod 32 == 8)

__device__ __forceinline__ uint32_t f2tf32(float x) {
    uint32_t r;
    asm("cvt.rna.tf32.f32 %0, %1;" : "=r"(r) : "f"(x));
    return r;
}

__device__ __forceinline__ void mma_tf32(float4& d,
                                         uint32_t a0, uint32_t a1, uint32_t a2, uint32_t a3,
                                         uint32_t b0, uint32_t b1) {
    asm volatile("mma.sync.aligned.m16n8k8.row.col.f32.tf32.tf32.f32 "
                 "{%0,%1,%2,%3}, {%4,%5,%6,%7}, {%8,%9}, {%0,%1,%2,%3};"
                 : "+f"(d.x), "+f"(d.y), "+f"(d.z), "+f"(d.w)
                 : "r"(a0), "r"(a1), "r"(a2), "r"(a3), "r"(b0), "r"(b1));
}

__global__ __launch_bounds__(256) void gemm_mma(
    const float* __restrict__ A, const float* __restrict__ B, float* __restrict__ C,
    int Mrows, int K, int Ncols, const float* __restrict__ bias, int act,
    long aStride, long bStride, long cStride) {
    int bz = blockIdx.z;
    A += (size_t)bz * aStride;
    B += (size_t)bz * bStride;
    C += (size_t)bz * cStride;

    __shared__ float As[GBM * AS_STRIDE];
    __shared__ float Bs[GBK * BS_STRIDE];

    int tid = threadIdx.x;
    int warp = tid >> 5;
    int lane = tid & 31;
    int warpM = warp >> 1;     // 0..3
    int warpN = warp & 1;      // 0..1
    int group = lane >> 2;     // 0..7
    int tig = lane & 3;        // 0..3

    int rowBase = blockIdx.y * GBM;
    int colBase = blockIdx.x * GBN;

    // global-load mapping
    int aRow = tid >> 1;               // 0..127
    int aCol = (tid & 1) * 16;         // 0 or 16
    int bRow = tid >> 3;               // 0..31
    int bCol = (tid & 7) * 8;          // 0..56

    float4 acc[2][4];
#pragma unroll
    for (int i = 0; i < 2; i++)
#pragma unroll
        for (int j = 0; j < 4; j++) acc[i][j] = make_float4(0.f, 0.f, 0.f, 0.f);

    float4 aReg[4];
    float4 bReg[2];

    int gaRow = rowBase + aRow;
    bool aValid = gaRow < Mrows;

    // preload tile 0
    {
        const float* Ap = A + (size_t)gaRow * K + aCol;
        if (aValid) {
#pragma unroll
            for (int i = 0; i < 4; i++) aReg[i] = *(const float4*)(Ap + 4 * i);
        } else {
#pragma unroll
            for (int i = 0; i < 4; i++) aReg[i] = make_float4(0.f, 0.f, 0.f, 0.f);
        }
        const float* Bp = B + (size_t)bRow * Ncols + colBase + bCol;
        bReg[0] = *(const float4*)(Bp);
        bReg[1] = *(const float4*)(Bp + 4);
    }

    for (int k0 = 0; k0 < K; k0 += GBK) {
        // store staged regs to smem (with tf32 conversion)
#pragma unroll
        for (int i = 0; i < 4; i++) {
            float* p = &As[aRow * AS_STRIDE + aCol + 4 * i];
            p[0] = __uint_as_float(f2tf32(aReg[i].x));
            p[1] = __uint_as_float(f2tf32(aReg[i].y));
            p[2] = __uint_as_float(f2tf32(aReg[i].z));
            p[3] = __uint_as_float(f2tf32(aReg[i].w));
        }
#pragma unroll
        for (int j = 0; j < 2; j++) {
            float* p = &Bs[bRow * BS_STRIDE + bCol + 4 * j];
            p[0] = __uint_as_float(f2tf32(bReg[j].x));
            p[1] = __uint_as_float(f2tf32(bReg[j].y));
            p[2] = __uint_as_float(f2tf32(bReg[j].z));
            p[3] = __uint_as_float(f2tf32(bReg[j].w));
        }
        __syncthreads();

        // prefetch next tile
        if (k0 + GBK < K) {
            const float* Ap = A + (size_t)gaRow * K + (k0 + GBK) + aCol;
            if (aValid) {
#pragma unroll
                for (int i = 0; i < 4; i++) aReg[i] = *(const float4*)(Ap + 4 * i);
            }
            const float* Bp = B + (size_t)(k0 + GBK + bRow) * Ncols + colBase + bCol;
            bReg[0] = *(const float4*)(Bp);
            bReg[1] = *(const float4*)(Bp + 4);
        }

        // compute 4 k-steps of m16n8k8
#pragma unroll
        for (int kk = 0; kk < 4; kk++) {
            int kc = kk * 8;
            uint32_t af[2][4];
#pragma unroll
            for (int mt = 0; mt < 2; mt++) {
                int r = warpM * 32 + mt * 16;
                af[mt][0] = __float_as_uint(As[(r + group) * AS_STRIDE + kc + tig]);
                af[mt][1] = __float_as_uint(As[(r + group + 8) * AS_STRIDE + kc + tig]);
                af[mt][2] = __float_as_uint(As[(r + group) * AS_STRIDE + kc + tig + 4]);
                af[mt][3] = __float_as_uint(As[(r + group + 8) * AS_STRIDE + kc + tig + 4]);
            }
            uint32_t bf[4][2];
#pragma unroll
            for (int nt = 0; nt < 4; nt++) {
                int c = warpN * 32 + nt * 8 + group;
                bf[nt][0] = __float_as_uint(Bs[(kc + tig) * BS_STRIDE + c]);
                bf[nt][1] = __float_as_uint(Bs[(kc + tig + 4) * BS_STRIDE + c]);
            }
#pragma unroll
            for (int mt = 0; mt < 2; mt++)
#pragma unroll
                for (int nt = 0; nt < 4; nt++)
                    mma_tf32(acc[mt][nt], af[mt][0], af[mt][1], af[mt][2], af[mt][3],
                             bf[nt][0], bf[nt][1]);
        }
        __syncthreads();
    }

    // epilogue
#pragma unroll
    for (int mt = 0; mt < 2; mt++) {
        int row0 = rowBase + warpM * 32 + mt * 16 + group;
        int row1 = row0 + 8;
#pragma unroll
        for (int nt = 0; nt < 4; nt++) {
            int col = colBase + warpN * 32 + nt * 8 + 2 * tig;
            float4 v = acc[mt][nt];
            if (act == 1) {
                float b0 = bias[col], b1 = bias[col + 1];
                v.x = tanhf(v.x + b0);
                v.y = tanhf(v.y + b1);
                v.z = tanhf(v.z + b0);
                v.w = tanhf(v.w + b1);
            }
            if (row0 < Mrows) *(float2*)(C + (size_t)row0 * Ncols + col) = make_float2(v.x, v.y);
            if (row1 < Mrows) *(float2*)(C + (size_t)row1 * Ncols + col) = make_float2(v.z, v.w);
        }
    }
}

// ---------------- el / er : per-(m,n,h) attention logits ----------------
__global__ void lr_kernel(const float* __restrict__ al, const float* __restrict__ ar) {
    int gw = (blockIdx.x * blockDim.x + threadIdx.x) >> 5;
    int lane = threadIdx.x & 31;
    if (gw >= MM * NN * HH) return;
    int m = gw / (NN * HH);
    int r = gw % (NN * HH);
    int n = r / HH;
    int h = r % HH;
    const float* f = g_feat + ((size_t)(m * NN + n)) * HD + h * DD;
    const float* a = al + (m * HH + h) * DD;
    const float* b = ar + (m * HH + h) * DD;
    float f1 = f[lane], f2 = f[lane + 32];
    float sl = f1 * a[lane] + f2 * a[lane + 32];
    float sr = f1 * b[lane] + f2 * b[lane + 32];
#pragma unroll
    for (int off = 16; off > 0; off >>= 1) {
        sl += __shfl_down_sync(0xffffffffu, sl, off);
        sr += __shfl_down_sync(0xffffffffu, sr, off);
    }
    if (lane == 0) {
        g_el[(m * NN + n) * HH + h] = sl;
        g_er[(m * NN + n) * HH + h] = sr;
    }
}

// ---------------- in-degree histogram ----------------
__global__ void hist_kernel(const int* __restrict__ dst) {
    int tid = blockIdx.x * blockDim.x + threadIdx.x;
    if (tid >= MM * EE) return;
    int m = tid / EE;
    atomicAdd(&g_hist[m * NN + dst[tid]], 1);
}

// ---------------- single-block exclusive scan per metapath ----------------
__global__ void scan_kernel() {
    int m = blockIdx.x;
    __shared__ int part[1024];
    int t = threadIdx.x;
    const int CH = 20;
    int base = t * CH;
    int local[CH];
    int s = 0;
#pragma unroll
    for (int i = 0; i < CH; i++) {
        int idx = base + i;
        int v = (idx < NN) ? g_hist[m * NN + idx] : 0;
        local[i] = v;
        s += v;
    }
    part[t] = s;
    __syncthreads();
    for (int off = 1; off < 1024; off <<= 1) {
        int v = (t >= off) ? part[t - off] : 0;
        __syncthreads();
        part[t] += v;
        __syncthreads();
    }
    int run = part[t] - s;
#pragma unroll
    for (int i = 0; i < CH; i++) {
        int idx = base + i;
        if (idx < NN) {
            g_rowptr[m * (NN + 1) + idx] = run;
            g_cursor[m * NN + idx] = run;
            run += local[i];
        }
    }
    if (t == 1023) g_rowptr[m * (NN + 1) + NN] = run;
}

// ---------------- edge pass: exp(leaky(el+er)) + CSR scatter (no den atomics) ---
__global__ void edge_kernel(const int* __restrict__ src, const int* __restrict__ dst) {
    int tid = blockIdx.x * blockDim.x + threadIdx.x;
    if (tid >= MM * EE) return;
    int m = tid / EE;
    int s = src[tid];
    int d = dst[tid];
    const float4* elp = (const float4*)(g_el + (size_t)(m * NN + s) * HH);
    const float4* erp = (const float4*)(g_er + (size_t)(m * NN + d) * HH);
    float4 e0 = elp[0], e1 = elp[1];
    float4 r0 = erp[0], r1 = erp[1];
    float ex[8];
    float v;
    v = e0.x + r0.x; v = v > 0.f ? v : 0.2f * v; ex[0] = expf(v);
    v = e0.y + r0.y; v = v > 0.f ? v : 0.2f * v; ex[1] = expf(v);
    v = e0.z + r0.z; v = v > 0.f ? v : 0.2f * v; ex[2] = expf(v);
    v = e0.w + r0.w; v = v > 0.f ? v : 0.2f * v; ex[3] = expf(v);
    v = e1.x + r1.x; v = v > 0.f ? v : 0.2f * v; ex[4] = expf(v);
    v = e1.y + r1.y; v = v > 0.f ? v : 0.2f * v; ex[5] = expf(v);
    v = e1.z + r1.z; v = v > 0.f ? v : 0.2f * v; ex[6] = expf(v);
    v = e1.w + r1.w; v = v > 0.f ? v : 0.2f * v; ex[7] = expf(v);

    int pos = atomicAdd(&g_cursor[m * NN + d], 1);
    int gp = m * EE + pos;
    g_src_s[gp] = s;
    float4* xp = (float4*)(g_ex_s + (size_t)gp * HH);
    xp[0] = make_float4(ex[0], ex[1], ex[2], ex[3]);
    xp[1] = make_float4(ex[4], ex[5], ex[6], ex[7]);
}

// ---------------- aggregation: one block per (node, metapath), inline den ------
__global__ void agg_kernel(const float* __restrict__ bg) {
    int n = blockIdx.x;
    int m = blockIdx.y;
    int t = threadIdx.x;           // 0..127, owns dims [4t, 4t+4)
    int h = t >> 4;
    int beg = g_rowptr[m * (NN + 1) + n];
    int end = g_rowptr[m * (NN + 1) + n + 1];
    float ax = 0.f, ay = 0.f, az = 0.f, aw = 0.f;
    float dsum = 0.f;
    for (int j = beg; j < end; j++) {
        int gp = m * EE + j;
        int s = g_src_s[gp];
        float exv = g_ex_s[(size_t)gp * HH + h];
        dsum += exv;
        float4 f = *(const float4*)(g_feat + ((size_t)(m * NN + s)) * HD + t * 4);
        ax += exv * f.x; ay += exv * f.y; az += exv * f.z; aw += exv * f.w;
    }
    float inv = 1.0f / fmaxf(dsum, 1e-9f);
    const float* bp = bg + m * HD + t * 4;
    float o0 = ax * inv + bp[0], o1 = ay * inv + bp[1];
    float o2 = az * inv + bp[2], o3 = aw * inv + bp[3];
    o0 = o0 > 0.f ? o0 : expf(o0) - 1.0f;
    o1 = o1 > 0.f ? o1 : expf(o1) - 1.0f;
    o2 = o2 > 0.f ? o2 : expf(o2) - 1.0f;
    o3 = o3 > 0.f ? o3 : expf(o3) - 1.0f;
    *(float4*)(g_z + ((size_t)(m * NN + n)) * HD + t * 4) = make_float4(o0, o1, o2, o3);
}

// ---------------- semantic score s[r] = c1[r] . W2 ----------------
__global__ void s_kernel(const float* __restrict__ sW2) {
    int gw = (blockIdx.x * blockDim.x + threadIdx.x) >> 5;
    int lane = threadIdx.x & 31;
    if (gw >= MM * NN) return;
    const float* c = g_c1 + (size_t)gw * HIDD;
    float v = c[lane] * sW2[lane] + c[lane + 32] * sW2[lane + 32] +
              c[lane + 64] * sW2[lane + 64] + c[lane + 96] * sW2[lane + 96];
#pragma unroll
    for (int off = 16; off > 0; off >>= 1) v += __shfl_down_sync(0xffffffffu, v, off);
    if (lane == 0) g_s[gw] = v;
}

// ---------------- mean over nodes per metapath ----------------
__global__ void reduce_kernel() {
    int m = blockIdx.y;
    int t = threadIdx.x;
    float s = 0.f;
    for (int i = blockIdx.x * blockDim.x + t; i < NN; i += gridDim.x * blockDim.x)
        s += g_s[m * NN + i];
    __shared__ float sh[256];
    sh[t] = s;
    __syncthreads();
    for (int off = 128; off > 0; off >>= 1) {
        if (t < off) sh[t] += sh[t + off];
        __syncthreads();
    }
    if (t == 0) atomicAdd(&g_sum[m], sh[0]);
}

__global__ void beta_kernel() {
    float a = g_sum[0] / (float)NN;
    float b = g_sum[1] / (float)NN;
    float mx = fmaxf(a, b);
    float e0 = expf(a - mx), e1 = expf(b - mx);
    float inv = 1.0f / (e0 + e1);
    g_beta[0] = e0 * inv;
    g_beta[1] = e1 * inv;
}

// ---------------- final: out = (beta0*z0 + beta1*z1) @ pred_W + pred_b ----------
__global__ void final_kernel(const float* __restrict__ pW, const float* __restrict__ pb,
                             float* __restrict__ out) {
    int n = blockIdx.x;
    int t = threadIdx.x;
    float b0 = g_beta[0], b1 = g_beta[1];
    float4 z0 = *(const float4*)(g_z + (size_t)n * HD + t * 4);
    float4 z1 = *(const float4*)(g_z + (size_t)(NN + n) * HD + t * 4);
    float hk[4] = {b0 * z0.x + b1 * z1.x, b0 * z0.y + b1 * z1.y,
                   b0 * z0.z + b1 * z1.z, b0 * z0.w + b1 * z1.w};
    float acc[5] = {0.f, 0.f, 0.f, 0.f, 0.f};
#pragma unroll
    for (int j = 0; j < 4; j++) {
        int k = t * 4 + j;
        const float* w = pW + k * CC;
#pragma unroll
        for (int c = 0; c < 5; c++) acc[c] += hk[j] * w[c];
    }
#pragma unroll
    for (int c = 0; c < 5; c++)
#pragma unroll
        for (int off = 16; off > 0; off >>= 1)
            acc[c] += __shfl_down_sync(0xffffffffu, acc[c], off);
    __shared__ float sh[4][5];
    int warp = t >> 5, lane = t & 31;
    if (lane == 0)
#pragma unroll
        for (int c = 0; c < 5; c++) sh[warp][c] = acc[c];
    __syncthreads();
    if (t < 5) {
        float v = pb[t];
#pragma unroll
        for (int w = 0; w < 4; w++) v += sh[w][t];
        out[n * CC + t] = v;
    }
}

// ---------------- launch ----------------
extern "C" void kernel_launch(void* const* d_in, const int* in_sizes, int n_in,
                              void* d_out, int out_size) {
    const float* h    = (const float*)d_in[0];
    const int*   src  = (const int*)d_in[1];
    const int*   dst  = (const int*)d_in[2];
    const float* W    = (const float*)d_in[3];
    const float* al   = (const float*)d_in[4];
    const float* ar   = (const float*)d_in[5];
    const float* bg   = (const float*)d_in[6];
    const float* sW1  = (const float*)d_in[7];
    const float* sb1  = (const float*)d_in[8];
    const float* sW2  = (const float*)d_in[9];
    const float* pW   = (const float*)d_in[10];
    const float* pb   = (const float*)d_in[11];
    float* out = (float*)d_out;

    float *p_feat, *p_z, *p_c1;
    cudaGetSymbolAddress((void**)&p_feat, g_feat);
    cudaGetSymbolAddress((void**)&p_z, g_z);
    cudaGetSymbolAddress((void**)&p_c1, g_c1);

    zero_kernel<<<157, 256>>>();

    // feat[m] = h @ W[m]   (A batched with stride 0)
    gemm_mma<<<dim3(HD / GBN, (NN + GBM - 1) / GBM, MM), 256>>>(
        h, W, p_feat, NN, FF, HD, nullptr, 0,
        0L, (long)FF * HD, (long)NN * HD);

    lr_kernel<<<(MM * NN * HH * 32 + 255) / 256, 256>>>(al, ar);
    hist_kernel<<<(MM * EE + 255) / 256, 256>>>(dst);
    scan_kernel<<<MM, 1024>>>();
    edge_kernel<<<(MM * EE + 255) / 256, 256>>>(src, dst);
    agg_kernel<<<dim3(NN, MM), 128>>>(bg);

    // c1 = tanh(z @ sem_W1 + b1), rows = M*N
    gemm_mma<<<dim3(HIDD / GBN, (MM * NN + GBM - 1) / GBM, 1), 256>>>(
        p_z, sW1, p_c1, MM * NN, HD, HIDD, sb1, 1, 0L, 0L, 0L);

    s_kernel<<<(MM * NN * 32 + 255) / 256, 256>>>(sW2);
    reduce_kernel<<<dim3(40, MM), 256>>>();
    beta_kernel<<<1, 1>>>();
    final_kernel<<<NN, 128>>>(pW, pb, out);
}

// round 4
// speedup vs baseline: 2.6149x; 1.0400x over previous
#include <cuda_runtime.h>
#include <cuda_bf16.h>
#include <math.h>
#include <stdint.h>

#define NN 20000
#define FF 256
#define HH 8
#define DD 64
#define HD 512
#define MM 2
#define EE 320000
#define CC 5
#define HIDD 128

// ---------------- scratch (device globals; no allocation) ----------------
__device__ float g_feat[MM * NN * HD];
__device__ float g_z[MM * NN * HD];
__device__ float g_el[MM * NN * HH];
__device__ float g_er[MM * NN * HH];
__device__ int   g_hist[MM * NN];
__device__ int   g_rowptr[MM * (NN + 1)];
__device__ int   g_cursor[MM * NN];
__device__ int   g_src_s[MM * EE];
__device__ float g_ex_s[MM * EE * HH];
__device__ float g_s[MM * NN];
__device__ float g_y[MM * NN * CC];
__device__ float g_sum[MM];
__device__ float g_beta[MM];

// ---------------- zero init: hist, s, sum ----------------
__global__ void zero_kernel() {
    int i = blockIdx.x * blockDim.x + threadIdx.x;
    int total = MM * NN + MM * NN + MM;
    for (; i < total; i += gridDim.x * blockDim.x) {
        if (i < MM * NN) g_hist[i] = 0;
        else if (i < 2 * MM * NN) g_s[i - MM * NN] = 0.0f;
        else g_sum[i - 2 * MM * NN] = 0.0f;
    }
}

// ---------------- in-degree histogram ----------------
__global__ void hist_kernel(const int* __restrict__ dst) {
    int tid = blockIdx.x * blockDim.x + threadIdx.x;
    if (tid >= MM * EE) return;
    int m = tid / EE;
    atomicAdd(&g_hist[m * NN + dst[tid]], 1);
}

// ---------------- single-block exclusive scan per metapath ----------------
__global__ void scan_kernel() {
    int m = blockIdx.x;
    __shared__ int part[1024];
    int t = threadIdx.x;
    const int CH = 20;
    int base = t * CH;
    int local[CH];
    int s = 0;
#pragma unroll
    for (int i = 0; i < CH; i++) {
        int idx = base + i;
        int v = (idx < NN) ? g_hist[m * NN + idx] : 0;
        local[i] = v;
        s += v;
    }
    part[t] = s;
    __syncthreads();
    for (int off = 1; off < 1024; off <<= 1) {
        int v = (t >= off) ? part[t - off] : 0;
        __syncthreads();
        part[t] += v;
        __syncthreads();
    }
    int run = part[t] - s;
#pragma unroll
    for (int i = 0; i < CH; i++) {
        int idx = base + i;
        if (idx < NN) {
            g_rowptr[m * (NN + 1) + idx] = run;
            g_cursor[m * NN + idx] = run;
            run += local[i];
        }
    }
    if (t == 1023) g_rowptr[m * (NN + 1) + NN] = run;
}

// ---------------- TF32 tensor-core GEMM with fused epilogues ----------------
// mode 2: write C raw + fused el/er (head = blockIdx.x, metapath = blockIdx.z)
// mode 3: no C write; s[row] += sum_col tanh(acc + bias[col]) * w2[col]
#define GBM 128
#define GBN 64
#define GBK 32
#define AS_STRIDE 36
#define BS_STRIDE 72

__device__ __forceinline__ uint32_t f2tf32(float x) {
    uint32_t r;
    asm("cvt.rna.tf32.f32 %0, %1;" : "=r"(r) : "f"(x));
    return r;
}

__device__ __forceinline__ void mma_tf32(float4& d,
                                         uint32_t a0, uint32_t a1, uint32_t a2, uint32_t a3,
                                         uint32_t b0, uint32_t b1) {
    asm volatile("mma.sync.aligned.m16n8k8.row.col.f32.tf32.tf32.f32 "
                 "{%0,%1,%2,%3}, {%4,%5,%6,%7}, {%8,%9}, {%0,%1,%2,%3};"
                 : "+f"(d.x), "+f"(d.y), "+f"(d.z), "+f"(d.w)
                 : "r"(a0), "r"(a1), "r"(a2), "r"(a3), "r"(b0), "r"(b1));
}

__global__ __launch_bounds__(256) void gemm_mma(
    const float* __restrict__ A, const float* __restrict__ B, float* __restrict__ C,
    int Mrows, int K, int Ncols, const float* __restrict__ bias, int mode,
    long aStride, long bStride, long cStride,
    const float* __restrict__ attl, const float* __restrict__ attr,
    const float* __restrict__ w2) {
    int bz = blockIdx.z;
    A += (size_t)bz * aStride;
    B += (size_t)bz * bStride;
    C += (size_t)bz * cStride;

    __shared__ float As[GBM * AS_STRIDE];
    __shared__ float Bs[GBK * BS_STRIDE];

    int tid = threadIdx.x;
    int warp = tid >> 5;
    int lane = tid & 31;
    int warpM = warp >> 1;
    int warpN = warp & 1;
    int group = lane >> 2;
    int tig = lane & 3;

    int rowBase = blockIdx.y * GBM;
    int colBase = blockIdx.x * GBN;

    int aRow = tid >> 1;
    int aCol = (tid & 1) * 16;
    int bRow = tid >> 3;
    int bCol = (tid & 7) * 8;

    float4 acc[2][4];
#pragma unroll
    for (int i = 0; i < 2; i++)
#pragma unroll
        for (int j = 0; j < 4; j++) acc[i][j] = make_float4(0.f, 0.f, 0.f, 0.f);

    float4 aReg[4];
    float4 bReg[2];

    int gaRow = rowBase + aRow;
    bool aValid = gaRow < Mrows;

    {
        const float* Ap = A + (size_t)gaRow * K + aCol;
        if (aValid) {
#pragma unroll
            for (int i = 0; i < 4; i++) aReg[i] = *(const float4*)(Ap + 4 * i);
        } else {
#pragma unroll
            for (int i = 0; i < 4; i++) aReg[i] = make_float4(0.f, 0.f, 0.f, 0.f);
        }
        const float* Bp = B + (size_t)bRow * Ncols + colBase + bCol;
        bReg[0] = *(const float4*)(Bp);
        bReg[1] = *(const float4*)(Bp + 4);
    }

    for (int k0 = 0; k0 < K; k0 += GBK) {
#pragma unroll
        for (int i = 0; i < 4; i++) {
            float* p = &As[aRow * AS_STRIDE + aCol + 4 * i];
            p[0] = __uint_as_float(f2tf32(aReg[i].x));
            p[1] = __uint_as_float(f2tf32(aReg[i].y));
            p[2] = __uint_as_float(f2tf32(aReg[i].z));
            p[3] = __uint_as_float(f2tf32(aReg[i].w));
        }
#pragma unroll
        for (int j = 0; j < 2; j++) {
            float* p = &Bs[bRow * BS_STRIDE + bCol + 4 * j];
            p[0] = __uint_as_float(f2tf32(bReg[j].x));
            p[1] = __uint_as_float(f2tf32(bReg[j].y));
            p[2] = __uint_as_float(f2tf32(bReg[j].z));
            p[3] = __uint_as_float(f2tf32(bReg[j].w));
        }
        __syncthreads();

        if (k0 + GBK < K) {
            const float* Ap = A + (size_t)gaRow * K + (k0 + GBK) + aCol;
            if (aValid) {
#pragma unroll
                for (int i = 0; i < 4; i++) aReg[i] = *(const float4*)(Ap + 4 * i);
            }
            const float* Bp = B + (size_t)(k0 + GBK + bRow) * Ncols + colBase + bCol;
            bReg[0] = *(const float4*)(Bp);
            bReg[1] = *(const float4*)(Bp + 4);
        }

#pragma unroll
        for (int kk = 0; kk < 4; kk++) {
            int kc = kk * 8;
            uint32_t af[2][4];
#pragma unroll
            for (int mt = 0; mt < 2; mt++) {
                int r = warpM * 32 + mt * 16;
                af[mt][0] = __float_as_uint(As[(r + group) * AS_STRIDE + kc + tig]);
                af[mt][1] = __float_as_uint(As[(r + group + 8) * AS_STRIDE + kc + tig]);
                af[mt][2] = __float_as_uint(As[(r + group) * AS_STRIDE + kc + tig + 4]);
                af[mt][3] = __float_as_uint(As[(r + group + 8) * AS_STRIDE + kc + tig + 4]);
            }
            uint32_t bf[4][2];
#pragma unroll
            for (int nt = 0; nt < 4; nt++) {
                int c = warpN * 32 + nt * 8 + group;
                bf[nt][0] = __float_as_uint(Bs[(kc + tig) * BS_STRIDE + c]);
                bf[nt][1] = __float_as_uint(Bs[(kc + tig + 4) * BS_STRIDE + c]);
            }
#pragma unroll
            for (int mt = 0; mt < 2; mt++)
#pragma unroll
                for (int nt = 0; nt < 4; nt++)
                    mma_tf32(acc[mt][nt], af[mt][0], af[mt][1], af[mt][2], af[mt][3],
                             bf[nt][0], bf[nt][1]);
        }
        __syncthreads();
    }

    if (mode == 2) {
        // write C raw + fused el/er for this head
        int head = blockIdx.x;
        const float* alp = attl + (bz * HH + head) * DD;
        const float* arp = attr + (bz * HH + head) * DD;
        float sl[2][2] = {{0.f, 0.f}, {0.f, 0.f}};
        float sr[2][2] = {{0.f, 0.f}, {0.f, 0.f}};
#pragma unroll
        for (int mt = 0; mt < 2; mt++) {
            int row0 = rowBase + warpM * 32 + mt * 16 + group;
            int row1 = row0 + 8;
#pragma unroll
            for (int nt = 0; nt < 4; nt++) {
                int cl = warpN * 32 + nt * 8 + 2 * tig;
                float4 v = acc[mt][nt];
                float a0 = alp[cl], a1 = alp[cl + 1];
                float r0 = arp[cl], r1 = arp[cl + 1];
                sl[mt][0] += v.x * a0 + v.y * a1;
                sl[mt][1] += v.z * a0 + v.w * a1;
                sr[mt][0] += v.x * r0 + v.y * r1;
                sr[mt][1] += v.z * r0 + v.w * r1;
                int col = colBase + cl;
                if (row0 < Mrows) *(float2*)(C + (size_t)row0 * Ncols + col) = make_float2(v.x, v.y);
                if (row1 < Mrows) *(float2*)(C + (size_t)row1 * Ncols + col) = make_float2(v.z, v.w);
            }
        }
        // quad reduce (tig dimension)
#pragma unroll
        for (int mt = 0; mt < 2; mt++)
#pragma unroll
            for (int r = 0; r < 2; r++) {
                sl[mt][r] += __shfl_xor_sync(0xffffffffu, sl[mt][r], 1);
                sl[mt][r] += __shfl_xor_sync(0xffffffffu, sl[mt][r], 2);
                sr[mt][r] += __shfl_xor_sync(0xffffffffu, sr[mt][r], 1);
                sr[mt][r] += __shfl_xor_sync(0xffffffffu, sr[mt][r], 2);
            }
        __syncthreads();
        float* redl = As;              // [128][2]
        float* redr = As + 256;        // [128][2]
        if (tig == 0) {
#pragma unroll
            for (int mt = 0; mt < 2; mt++) {
                int rl0 = warpM * 32 + mt * 16 + group;
                redl[rl0 * 2 + warpN] = sl[mt][0];
                redl[(rl0 + 8) * 2 + warpN] = sl[mt][1];
                redr[rl0 * 2 + warpN] = sr[mt][0];
                redr[(rl0 + 8) * 2 + warpN] = sr[mt][1];
            }
        }
        __syncthreads();
        if (tid < 128) {
            int grow = rowBase + tid;
            if (grow < Mrows) {
                g_el[(bz * NN + grow) * HH + head] = redl[tid * 2] + redl[tid * 2 + 1];
                g_er[(bz * NN + grow) * HH + head] = redr[tid * 2] + redr[tid * 2 + 1];
            }
        }
    } else {
        // mode 3: semantic — no C write; accumulate s[row]
        float sp[2][2] = {{0.f, 0.f}, {0.f, 0.f}};
#pragma unroll
        for (int mt = 0; mt < 2; mt++) {
#pragma unroll
            for (int nt = 0; nt < 4; nt++) {
                int cl = warpN * 32 + nt * 8 + 2 * tig;
                int col = colBase + cl;
                float b0 = bias[col], b1 = bias[col + 1];
                float w0 = w2[col], w1 = w2[col + 1];
                float4 v = acc[mt][nt];
                sp[mt][0] += tanhf(v.x + b0) * w0 + tanhf(v.y + b1) * w1;
                sp[mt][1] += tanhf(v.z + b0) * w0 + tanhf(v.w + b1) * w1;
            }
        }
#pragma unroll
        for (int mt = 0; mt < 2; mt++)
#pragma unroll
            for (int r = 0; r < 2; r++) {
                sp[mt][r] += __shfl_xor_sync(0xffffffffu, sp[mt][r], 1);
                sp[mt][r] += __shfl_xor_sync(0xffffffffu, sp[mt][r], 2);
            }
        __syncthreads();
        float* red = As;  // [128][2]
        if (tig == 0) {
#pragma unroll
            for (int mt = 0; mt < 2; mt++) {
                int rl0 = warpM * 32 + mt * 16 + group;
                red[rl0 * 2 + warpN] = sp[mt][0];
                red[(rl0 + 8) * 2 + warpN] = sp[mt][1];
            }
        }
        __syncthreads();
        if (tid < 128) {
            int grow = rowBase + tid;
            if (grow < Mrows)
                atomicAdd(&g_s[grow], red[tid * 2] + red[tid * 2 + 1]);
        }
    }
}

// ---------------- edge pass: exp(leaky(el+er)) + CSR scatter ----------------
__global__ void edge_kernel(const int* __restrict__ src, const int* __restrict__ dst) {
    int tid = blockIdx.x * blockDim.x + threadIdx.x;
    if (tid >= MM * EE) return;
    int m = tid / EE;
    int s = src[tid];
    int d = dst[tid];
    const float4* elp = (const float4*)(g_el + (size_t)(m * NN + s) * HH);
    const float4* erp = (const float4*)(g_er + (size_t)(m * NN + d) * HH);
    float4 e0 = elp[0], e1 = elp[1];
    float4 r0 = erp[0], r1 = erp[1];
    float ex[8];
    float v;
    v = e0.x + r0.x; v = v > 0.f ? v : 0.2f * v; ex[0] = expf(v);
    v = e0.y + r0.y; v = v > 0.f ? v : 0.2f * v; ex[1] = expf(v);
    v = e0.z + r0.z; v = v > 0.f ? v : 0.2f * v; ex[2] = expf(v);
    v = e0.w + r0.w; v = v > 0.f ? v : 0.2f * v; ex[3] = expf(v);
    v = e1.x + r1.x; v = v > 0.f ? v : 0.2f * v; ex[4] = expf(v);
    v = e1.y + r1.y; v = v > 0.f ? v : 0.2f * v; ex[5] = expf(v);
    v = e1.z + r1.z; v = v > 0.f ? v : 0.2f * v; ex[6] = expf(v);
    v = e1.w + r1.w; v = v > 0.f ? v : 0.2f * v; ex[7] = expf(v);

    int pos = atomicAdd(&g_cursor[m * NN + d], 1);
    int gp = m * EE + pos;
    g_src_s[gp] = s;
    float4* xp = (float4*)(g_ex_s + (size_t)gp * HH);
    xp[0] = make_float4(ex[0], ex[1], ex[2], ex[3]);
    xp[1] = make_float4(ex[4], ex[5], ex[6], ex[7]);
}

// ---------------- aggregation + fused per-metapath classifier ----------------
__global__ void agg_kernel(const float* __restrict__ bg, const float* __restrict__ pW) {
    int n = blockIdx.x;
    int m = blockIdx.y;
    int t = threadIdx.x;           // 0..127, owns dims [4t, 4t+4)
    int h = t >> 4;
    int beg = g_rowptr[m * (NN + 1) + n];
    int end = g_rowptr[m * (NN + 1) + n + 1];
    float ax = 0.f, ay = 0.f, az = 0.f, aw = 0.f;
    float dsum = 0.f;
    for (int j = beg; j < end; j++) {
        int gp = m * EE + j;
        int s = g_src_s[gp];
        float exv = g_ex_s[(size_t)gp * HH + h];
        dsum += exv;
        float4 f = *(const float4*)(g_feat + ((size_t)(m * NN + s)) * HD + t * 4);
        ax += exv * f.x; ay += exv * f.y; az += exv * f.z; aw += exv * f.w;
    }
    float inv = 1.0f / fmaxf(dsum, 1e-9f);
    const float* bp = bg + m * HD + t * 4;
    float o0 = ax * inv + bp[0], o1 = ay * inv + bp[1];
    float o2 = az * inv + bp[2], o3 = aw * inv + bp[3];
    o0 = o0 > 0.f ? o0 : expf(o0) - 1.0f;
    o1 = o1 > 0.f ? o1 : expf(o1) - 1.0f;
    o2 = o2 > 0.f ? o2 : expf(o2) - 1.0f;
    o3 = o3 > 0.f ? o3 : expf(o3) - 1.0f;
    *(float4*)(g_z + ((size_t)(m * NN + n)) * HD + t * 4) = make_float4(o0, o1, o2, o3);

    // fused y[m,n,c] = z_row . pred_W[:,c]
    const float* w = pW + (size_t)t * 4 * CC;
    float yc[CC];
#pragma unroll
    for (int c = 0; c < CC; c++)
        yc[c] = o0 * w[c] + o1 * w[CC + c] + o2 * w[2 * CC + c] + o3 * w[3 * CC + c];
#pragma unroll
    for (int c = 0; c < CC; c++)
#pragma unroll
        for (int off = 16; off > 0; off >>= 1)
            yc[c] += __shfl_down_sync(0xffffffffu, yc[c], off);
    __shared__ float ysh[4][CC];
    int warp = t >> 5, lane = t & 31;
    if (lane == 0)
#pragma unroll
        for (int c = 0; c < CC; c++) ysh[warp][c] = yc[c];
    __syncthreads();
    if (t < CC) {
        float v = ysh[0][t] + ysh[1][t] + ysh[2][t] + ysh[3][t];
        g_y[((size_t)m * NN + n) * CC + t] = v;
    }
}

// ---------------- mean over nodes per metapath ----------------
__global__ void reduce_kernel() {
    int m = blockIdx.y;
    int t = threadIdx.x;
    float s = 0.f;
    for (int i = blockIdx.x * blockDim.x + t; i < NN; i += gridDim.x * blockDim.x)
        s += g_s[m * NN + i];
    __shared__ float sh[256];
    sh[t] = s;
    __syncthreads();
    for (int off = 128; off > 0; off >>= 1) {
        if (t < off) sh[t] += sh[t + off];
        __syncthreads();
    }
    if (t == 0) atomicAdd(&g_sum[m], sh[0]);
}

__global__ void beta_kernel() {
    float a = g_sum[0] / (float)NN;
    float b = g_sum[1] / (float)NN;
    float mx = fmaxf(a, b);
    float e0 = expf(a - mx), e1 = expf(b - mx);
    float inv = 1.0f / (e0 + e1);
    g_beta[0] = e0 * inv;
    g_beta[1] = e1 * inv;
}

// ---------------- tiny final: out = b0*y0 + b1*y1 + pb ----------------
__global__ void final_kernel(const float* __restrict__ pb, float* __restrict__ out) {
    int tid = blockIdx.x * blockDim.x + threadIdx.x;
    if (tid >= NN * CC) return;
    int c = tid % CC;
    float b0 = g_beta[0], b1 = g_beta[1];
    out[tid] = b0 * g_y[tid] + b1 * g_y[NN * CC + tid] + pb[c];
}

// ---------------- launch ----------------
extern "C" void kernel_launch(void* const* d_in, const int* in_sizes, int n_in,
                              void* d_out, int out_size) {
    const float* h    = (const float*)d_in[0];
    const int*   src  = (const int*)d_in[1];
    const int*   dst  = (const int*)d_in[2];
    const float* W    = (const float*)d_in[3];
    const float* al   = (const float*)d_in[4];
    const float* ar   = (const float*)d_in[5];
    const float* bg   = (const float*)d_in[6];
    const float* sW1  = (const float*)d_in[7];
    const float* sb1  = (const float*)d_in[8];
    const float* sW2  = (const float*)d_in[9];
    const float* pW   = (const float*)d_in[10];
    const float* pb   = (const float*)d_in[11];
    float* out = (float*)d_out;

    float *p_feat, *p_z;
    cudaGetSymbolAddress((void**)&p_feat, g_feat);
    cudaGetSymbolAddress((void**)&p_z, g_z);

    zero_kernel<<<313, 256>>>();                                   // 1
    hist_kernel<<<(MM * EE + 255) / 256, 256>>>(dst);              // 2
    scan_kernel<<<MM, 1024>>>();                                   // 3

    // 4: feat[m] = h @ W[m], fused el/er epilogue
    gemm_mma<<<dim3(HD / GBN, (NN + GBM - 1) / GBM, MM), 256>>>(
        h, W, p_feat, NN, FF, HD, nullptr, 2,
        0L, (long)FF * HD, (long)NN * HD, al, ar, nullptr);

    edge_kernel<<<(MM * EE + 255) / 256, 256>>>(src, dst);         // 5
    agg_kernel<<<dim3(NN, MM), 128>>>(bg, pW);                     // 6 (ncu captures this)

    // 7: semantic — s[row] += sum tanh(z@W1 + b1) * W2, no C write
    gemm_mma<<<dim3(HIDD / GBN, (MM * NN + GBM - 1) / GBM, 1), 256>>>(
        p_z, sW1, nullptr, MM * NN, HD, HIDD, sb1, 3,
        0L, 0L, 0L, nullptr, nullptr, sW2);

    reduce_kernel<<<dim3(40, MM), 256>>>();                        // 8
    beta_kernel<<<1, 1>>>();                                       // 9
    final_kernel<<<(NN * CC + 255) / 256, 256>>>(pb, out);         // 10
}

// round 5
// speedup vs baseline: 2.7465x; 1.0503x over previous
#include <cuda_runtime.h>
#include <cuda_bf16.h>
#include <math.h>
#include <stdint.h>

#define NN 20000
#define FF 256
#define HH 8
#define DD 64
#define HD 512
#define MM 2
#define EE 320000
#define CC 5
#define HIDD 128

// ---------------- scratch (device globals; no allocation) ----------------
__device__ float g_feat[MM * NN * HD];
__device__ float g_z[MM * NN * HD];
__device__ float g_el[MM * NN * HH];
__device__ float g_er[MM * NN * HH];
__device__ int   g_hist[MM * NN];
__device__ int   g_rowptr[MM * (NN + 1)];
__device__ int   g_cursor[MM * NN];
__device__ int   g_src_s[MM * EE];
__device__ float g_ex_s[MM * EE * HH];
__device__ float g_s[MM * NN];
__device__ float g_y[MM * NN * CC];
__device__ float g_sum[MM];
__device__ float g_beta[MM];

// ---------------- zero init: hist, s, sum ----------------
__global__ void zero_kernel() {
    int i = blockIdx.x * blockDim.x + threadIdx.x;
    int total = MM * NN + MM * NN + MM;
    for (; i < total; i += gridDim.x * blockDim.x) {
        if (i < MM * NN) g_hist[i] = 0;
        else if (i < 2 * MM * NN) g_s[i - MM * NN] = 0.0f;
        else g_sum[i - 2 * MM * NN] = 0.0f;
    }
}

// ---------------- in-degree histogram ----------------
__global__ void hist_kernel(const int* __restrict__ dst) {
    int tid = blockIdx.x * blockDim.x + threadIdx.x;
    if (tid >= MM * EE) return;
    int m = tid / EE;
    atomicAdd(&g_hist[m * NN + dst[tid]], 1);
}

// ---------------- single-block exclusive scan per metapath ----------------
__global__ void scan_kernel() {
    int m = blockIdx.x;
    __shared__ int part[1024];
    int t = threadIdx.x;
    const int CH = 20;
    int base = t * CH;
    int local[CH];
    int s = 0;
#pragma unroll
    for (int i = 0; i < CH; i++) {
        int idx = base + i;
        int v = (idx < NN) ? g_hist[m * NN + idx] : 0;
        local[i] = v;
        s += v;
    }
    part[t] = s;
    __syncthreads();
    for (int off = 1; off < 1024; off <<= 1) {
        int v = (t >= off) ? part[t - off] : 0;
        __syncthreads();
        part[t] += v;
        __syncthreads();
    }
    int run = part[t] - s;
#pragma unroll
    for (int i = 0; i < CH; i++) {
        int idx = base + i;
        if (idx < NN) {
            g_rowptr[m * (NN + 1) + idx] = run;
            g_cursor[m * NN + idx] = run;
            run += local[i];
        }
    }
    if (t == 1023) g_rowptr[m * (NN + 1) + NN] = run;
}

// ---------------- TF32 tensor-core GEMM, ldmatrix fragment path ------------
// mode 2: write C raw + fused el/er (head = blockIdx.x, metapath = blockIdx.z)
// mode 3: no C write; s[row] += sum_col tanh(acc + bias[col]) * w2[col]
#define GBM 128
#define GBN 64
#define GBK 32
#define SMS 36   // smem row stride in floats (32 + 4 pad); 144B, 16B-aligned

__device__ __forceinline__ uint32_t f2tf32(float x) {
    uint32_t r;
    asm("cvt.rna.tf32.f32 %0, %1;" : "=r"(r) : "f"(x));
    return r;
}

__device__ __forceinline__ float4 cvt4(float a, float b, float c, float d) {
    return make_float4(__uint_as_float(f2tf32(a)), __uint_as_float(f2tf32(b)),
                       __uint_as_float(f2tf32(c)), __uint_as_float(f2tf32(d)));
}

#define LDSM4(r, addr)                                                          \
    asm volatile("ldmatrix.sync.aligned.m8n8.x4.shared.b16 {%0,%1,%2,%3}, [%4];" \
                 : "=r"((r)[0]), "=r"((r)[1]), "=r"((r)[2]), "=r"((r)[3])        \
                 : "r"(addr))

__device__ __forceinline__ void mma_tf32(float4& d,
                                         uint32_t a0, uint32_t a1, uint32_t a2, uint32_t a3,
                                         uint32_t b0, uint32_t b1) {
    asm volatile("mma.sync.aligned.m16n8k8.row.col.f32.tf32.tf32.f32 "
                 "{%0,%1,%2,%3}, {%4,%5,%6,%7}, {%8,%9}, {%0,%1,%2,%3};"
                 : "+f"(d.x), "+f"(d.y), "+f"(d.z), "+f"(d.w)
                 : "r"(a0), "r"(a1), "r"(a2), "r"(a3), "r"(b0), "r"(b1));
}

__global__ __launch_bounds__(256) void gemm_mma(
    const float* __restrict__ A, const float* __restrict__ B, float* __restrict__ C,
    int Mrows, int K, int Ncols, const float* __restrict__ bias, int mode,
    long aStride, long bStride, long cStride,
    const float* __restrict__ attl, const float* __restrict__ attr,
    const float* __restrict__ w2) {
    int bz = blockIdx.z;
    A += (size_t)bz * aStride;
    B += (size_t)bz * bStride;
    C += (size_t)bz * cStride;

    __shared__ __align__(16) float As[GBM * SMS];   // [row][k]
    __shared__ __align__(16) float Bs[GBN * SMS];   // [n][k]  (transposed)

    int tid = threadIdx.x;
    int warp = tid >> 5;
    int lane = tid & 31;
    int warpM = warp >> 1;
    int warpN = warp & 1;
    int group = lane >> 2;
    int tig = lane & 3;

    int rowBase = blockIdx.y * GBM;
    int colBase = blockIdx.x * GBN;

    // A staging: thread loads 16 floats of one row half
    int aRow = tid >> 1;
    int aCol = (tid & 1) * 16;
    // B staging: thread loads 8 k-consecutive floats at one n (transposed store)
    int bN = tid & 63;
    int bK = (tid >> 6) * 8;

    // ldmatrix source pointers (u32 shared addresses)
    uint32_t AsU = (uint32_t)__cvta_generic_to_shared(As);
    uint32_t BsU = (uint32_t)__cvta_generic_to_shared(Bs);
    uint32_t aPtr = AsU + (uint32_t)(((warpM * 32 + (lane & 15)) * SMS + (lane >> 4) * 4) * 4);
    uint32_t bPtr = BsU + (uint32_t)(((warpN * 32 + (lane >> 4) * 8 + (lane & 7)) * SMS
                                      + ((lane >> 3) & 1) * 4) * 4);

    float4 acc[2][4];
#pragma unroll
    for (int i = 0; i < 2; i++)
#pragma unroll
        for (int j = 0; j < 4; j++) acc[i][j] = make_float4(0.f, 0.f, 0.f, 0.f);

    float4 aReg[4];
    float bRegT[8];

    int gaRow = rowBase + aRow;
    bool aValid = gaRow < Mrows;

    // preload tile 0
    {
        const float* Ap = A + (size_t)gaRow * K + aCol;
        if (aValid) {
#pragma unroll
            for (int i = 0; i < 4; i++) aReg[i] = *(const float4*)(Ap + 4 * i);
        } else {
#pragma unroll
            for (int i = 0; i < 4; i++) aReg[i] = make_float4(0.f, 0.f, 0.f, 0.f);
        }
        const float* Bp = B + (size_t)bK * Ncols + colBase + bN;
#pragma unroll
        for (int j = 0; j < 8; j++) bRegT[j] = Bp[(size_t)j * Ncols];
    }

    for (int k0 = 0; k0 < K; k0 += GBK) {
        // staged regs -> smem (tf32-converted, vectorized stores)
#pragma unroll
        for (int i = 0; i < 4; i++)
            *(float4*)&As[aRow * SMS + aCol + 4 * i] =
                cvt4(aReg[i].x, aReg[i].y, aReg[i].z, aReg[i].w);
        *(float4*)&Bs[bN * SMS + bK]     = cvt4(bRegT[0], bRegT[1], bRegT[2], bRegT[3]);
        *(float4*)&Bs[bN * SMS + bK + 4] = cvt4(bRegT[4], bRegT[5], bRegT[6], bRegT[7]);
        __syncthreads();

        // prefetch next tile
        if (k0 + GBK < K) {
            const float* Ap = A + (size_t)gaRow * K + (k0 + GBK) + aCol;
            if (aValid) {
#pragma unroll
                for (int i = 0; i < 4; i++) aReg[i] = *(const float4*)(Ap + 4 * i);
            }
            const float* Bp = B + (size_t)(k0 + GBK + bK) * Ncols + colBase + bN;
#pragma unroll
            for (int j = 0; j < 8; j++) bRegT[j] = Bp[(size_t)j * Ncols];
        }

#pragma unroll
        for (int kk = 0; kk < 4; kk++) {
            uint32_t kc4 = kk * 32;   // kc * 4 bytes, kc = kk*8
            uint32_t af[2][4];
            LDSM4(af[0], aPtr + kc4);
            LDSM4(af[1], aPtr + 16 * SMS * 4 + kc4);
            uint32_t bfr[2][4];       // [pair p][{b0 s0, b1 s0, b0 s1, b1 s1}]
            LDSM4(bfr[0], bPtr + kc4);
            LDSM4(bfr[1], bPtr + 16 * SMS * 4 + kc4);
#pragma unroll
            for (int mt = 0; mt < 2; mt++)
#pragma unroll
                for (int nt = 0; nt < 4; nt++)
                    mma_tf32(acc[mt][nt], af[mt][0], af[mt][1], af[mt][2], af[mt][3],
                             bfr[nt >> 1][(nt & 1) * 2], bfr[nt >> 1][(nt & 1) * 2 + 1]);
        }
        __syncthreads();
    }

    if (mode == 2) {
        int head = blockIdx.x;
        const float* alp = attl + (bz * HH + head) * DD;
        const float* arp = attr + (bz * HH + head) * DD;
        float sl[2][2] = {{0.f, 0.f}, {0.f, 0.f}};
        float sr[2][2] = {{0.f, 0.f}, {0.f, 0.f}};
#pragma unroll
        for (int mt = 0; mt < 2; mt++) {
            int row0 = rowBase + warpM * 32 + mt * 16 + group;
            int row1 = row0 + 8;
#pragma unroll
            for (int nt = 0; nt < 4; nt++) {
                int cl = warpN * 32 + nt * 8 + 2 * tig;
                float4 v = acc[mt][nt];
                float a0 = alp[cl], a1 = alp[cl + 1];
                float r0 = arp[cl], r1 = arp[cl + 1];
                sl[mt][0] += v.x * a0 + v.y * a1;
                sl[mt][1] += v.z * a0 + v.w * a1;
                sr[mt][0] += v.x * r0 + v.y * r1;
                sr[mt][1] += v.z * r0 + v.w * r1;
                int col = colBase + cl;
                if (row0 < Mrows) *(float2*)(C + (size_t)row0 * Ncols + col) = make_float2(v.x, v.y);
                if (row1 < Mrows) *(float2*)(C + (size_t)row1 * Ncols + col) = make_float2(v.z, v.w);
            }
        }
#pragma unroll
        for (int mt = 0; mt < 2; mt++)
#pragma unroll
            for (int r = 0; r < 2; r++) {
                sl[mt][r] += __shfl_xor_sync(0xffffffffu, sl[mt][r], 1);
                sl[mt][r] += __shfl_xor_sync(0xffffffffu, sl[mt][r], 2);
                sr[mt][r] += __shfl_xor_sync(0xffffffffu, sr[mt][r], 1);
                sr[mt][r] += __shfl_xor_sync(0xffffffffu, sr[mt][r], 2);
            }
        __syncthreads();
        float* redl = As;
        float* redr = As + 256;
        if (tig == 0) {
#pragma unroll
            for (int mt = 0; mt < 2; mt++) {
                int rl0 = warpM * 32 + mt * 16 + group;
                redl[rl0 * 2 + warpN] = sl[mt][0];
                redl[(rl0 + 8) * 2 + warpN] = sl[mt][1];
                redr[rl0 * 2 + warpN] = sr[mt][0];
                redr[(rl0 + 8) * 2 + warpN] = sr[mt][1];
            }
        }
        __syncthreads();
        if (tid < 128) {
            int grow = rowBase + tid;
            if (grow < Mrows) {
                g_el[(bz * NN + grow) * HH + head] = redl[tid * 2] + redl[tid * 2 + 1];
                g_er[(bz * NN + grow) * HH + head] = redr[tid * 2] + redr[tid * 2 + 1];
            }
        }
    } else {
        // mode 3: semantic — no C write; accumulate s[row]
        float sp[2][2] = {{0.f, 0.f}, {0.f, 0.f}};
#pragma unroll
        for (int mt = 0; mt < 2; mt++) {
#pragma unroll
            for (int nt = 0; nt < 4; nt++) {
                int cl = warpN * 32 + nt * 8 + 2 * tig;
                int col = colBase + cl;
                float b0 = bias[col], b1 = bias[col + 1];
                float w0 = w2[col], w1 = w2[col + 1];
                float4 v = acc[mt][nt];
                sp[mt][0] += tanhf(v.x + b0) * w0 + tanhf(v.y + b1) * w1;
                sp[mt][1] += tanhf(v.z + b0) * w0 + tanhf(v.w + b1) * w1;
            }
        }
#pragma unroll
        for (int mt = 0; mt < 2; mt++)
#pragma unroll
            for (int r = 0; r < 2; r++) {
                sp[mt][r] += __shfl_xor_sync(0xffffffffu, sp[mt][r], 1);
                sp[mt][r] += __shfl_xor_sync(0xffffffffu, sp[mt][r], 2);
            }
        __syncthreads();
        float* red = As;
        if (tig == 0) {
#pragma unroll
            for (int mt = 0; mt < 2; mt++) {
                int rl0 = warpM * 32 + mt * 16 + group;
                red[rl0 * 2 + warpN] = sp[mt][0];
                red[(rl0 + 8) * 2 + warpN] = sp[mt][1];
            }
        }
        __syncthreads();
        if (tid < 128) {
            int grow = rowBase + tid;
            if (grow < Mrows)
                atomicAdd(&g_s[grow], red[tid * 2] + red[tid * 2 + 1]);
        }
    }
}

// ---------------- edge pass: exp(leaky(el+er)) + CSR scatter ----------------
__global__ void edge_kernel(const int* __restrict__ src, const int* __restrict__ dst) {
    int tid = blockIdx.x * blockDim.x + threadIdx.x;
    if (tid >= MM * EE) return;
    int m = tid / EE;
    int s = src[tid];
    int d = dst[tid];
    const float4* elp = (const float4*)(g_el + (size_t)(m * NN + s) * HH);
    const float4* erp = (const float4*)(g_er + (size_t)(m * NN + d) * HH);
    float4 e0 = elp[0], e1 = elp[1];
    float4 r0 = erp[0], r1 = erp[1];
    float ex[8];
    float v;
    v = e0.x + r0.x; v = v > 0.f ? v : 0.2f * v; ex[0] = expf(v);
    v = e0.y + r0.y; v = v > 0.f ? v : 0.2f * v; ex[1] = expf(v);
    v = e0.z + r0.z; v = v > 0.f ? v : 0.2f * v; ex[2] = expf(v);
    v = e0.w + r0.w; v = v > 0.f ? v : 0.2f * v; ex[3] = expf(v);
    v = e1.x + r1.x; v = v > 0.f ? v : 0.2f * v; ex[4] = expf(v);
    v = e1.y + r1.y; v = v > 0.f ? v : 0.2f * v; ex[5] = expf(v);
    v = e1.z + r1.z; v = v > 0.f ? v : 0.2f * v; ex[6] = expf(v);
    v = e1.w + r1.w; v = v > 0.f ? v : 0.2f * v; ex[7] = expf(v);

    int pos = atomicAdd(&g_cursor[m * NN + d], 1);
    int gp = m * EE + pos;
    g_src_s[gp] = s;
    float4* xp = (float4*)(g_ex_s + (size_t)gp * HH);
    xp[0] = make_float4(ex[0], ex[1], ex[2], ex[3]);
    xp[1] = make_float4(ex[4], ex[5], ex[6], ex[7]);
}

// ---------------- aggregation + fused per-metapath classifier ----------------
__global__ void agg_kernel(const float* __restrict__ bg, const float* __restrict__ pW) {
    int n = blockIdx.x;
    int m = blockIdx.y;
    int t = threadIdx.x;           // 0..127, owns dims [4t, 4t+4)
    int h = t >> 4;
    int beg = g_rowptr[m * (NN + 1) + n];
    int end = g_rowptr[m * (NN + 1) + n + 1];
    float ax = 0.f, ay = 0.f, az = 0.f, aw = 0.f;
    float dsum = 0.f;
    for (int j = beg; j < end; j++) {
        int gp = m * EE + j;
        int s = g_src_s[gp];
        float exv = g_ex_s[(size_t)gp * HH + h];
        dsum += exv;
        float4 f = *(const float4*)(g_feat + ((size_t)(m * NN + s)) * HD + t * 4);
        ax += exv * f.x; ay += exv * f.y; az += exv * f.z; aw += exv * f.w;
    }
    float inv = 1.0f / fmaxf(dsum, 1e-9f);
    const float* bp = bg + m * HD + t * 4;
    float o0 = ax * inv + bp[0], o1 = ay * inv + bp[1];
    float o2 = az * inv + bp[2], o3 = aw * inv + bp[3];
    o0 = o0 > 0.f ? o0 : expf(o0) - 1.0f;
    o1 = o1 > 0.f ? o1 : expf(o1) - 1.0f;
    o2 = o2 > 0.f ? o2 : expf(o2) - 1.0f;
    o3 = o3 > 0.f ? o3 : expf(o3) - 1.0f;
    *(float4*)(g_z + ((size_t)(m * NN + n)) * HD + t * 4) = make_float4(o0, o1, o2, o3);

    // fused y[m,n,c] = z_row . pred_W[:,c]
    const float* w = pW + (size_t)t * 4 * CC;
    float yc[CC];
#pragma unroll
    for (int c = 0; c < CC; c++)
        yc[c] = o0 * w[c] + o1 * w[CC + c] + o2 * w[2 * CC + c] + o3 * w[3 * CC + c];
#pragma unroll
    for (int c = 0; c < CC; c++)
#pragma unroll
        for (int off = 16; off > 0; off >>= 1)
            yc[c] += __shfl_down_sync(0xffffffffu, yc[c], off);
    __shared__ float ysh[4][CC];
    int warp = t >> 5, lane = t & 31;
    if (lane == 0)
#pragma unroll
        for (int c = 0; c < CC; c++) ysh[warp][c] = yc[c];
    __syncthreads();
    if (t < CC) {
        float v = ysh[0][t] + ysh[1][t] + ysh[2][t] + ysh[3][t];
        g_y[((size_t)m * NN + n) * CC + t] = v;
    }
}

// ---------------- mean over nodes per metapath ----------------
__global__ void reduce_kernel() {
    int m = blockIdx.y;
    int t = threadIdx.x;
    float s = 0.f;
    for (int i = blockIdx.x * blockDim.x + t; i < NN; i += gridDim.x * blockDim.x)
        s += g_s[m * NN + i];
    __shared__ float sh[256];
    sh[t] = s;
    __syncthreads();
    for (int off = 128; off > 0; off >>= 1) {
        if (t < off) sh[t] += sh[t + off];
        __syncthreads();
    }
    if (t == 0) atomicAdd(&g_sum[m], sh[0]);
}

__global__ void beta_kernel() {
    float a = g_sum[0] / (float)NN;
    float b = g_sum[1] / (float)NN;
    float mx = fmaxf(a, b);
    float e0 = expf(a - mx), e1 = expf(b - mx);
    float inv = 1.0f / (e0 + e1);
    g_beta[0] = e0 * inv;
    g_beta[1] = e1 * inv;
}

// ---------------- tiny final: out = b0*y0 + b1*y1 + pb ----------------
__global__ void final_kernel(const float* __restrict__ pb, float* __restrict__ out) {
    int tid = blockIdx.x * blockDim.x + threadIdx.x;
    if (tid >= NN * CC) return;
    int c = tid % CC;
    float b0 = g_beta[0], b1 = g_beta[1];
    out[tid] = b0 * g_y[tid] + b1 * g_y[NN * CC + tid] + pb[c];
}

// ---------------- launch ----------------
extern "C" void kernel_launch(void* const* d_in, const int* in_sizes, int n_in,
                              void* d_out, int out_size) {
    const float* h    = (const float*)d_in[0];
    const int*   src  = (const int*)d_in[1];
    const int*   dst  = (const int*)d_in[2];
    const float* W    = (const float*)d_in[3];
    const float* al   = (const float*)d_in[4];
    const float* ar   = (const float*)d_in[5];
    const float* bg   = (const float*)d_in[6];
    const float* sW1  = (const float*)d_in[7];
    const float* sb1  = (const float*)d_in[8];
    const float* sW2  = (const float*)d_in[9];
    const float* pW   = (const float*)d_in[10];
    const float* pb   = (const float*)d_in[11];
    float* out = (float*)d_out;

    float *p_feat, *p_z;
    cudaGetSymbolAddress((void**)&p_feat, g_feat);
    cudaGetSymbolAddress((void**)&p_z, g_z);

    zero_kernel<<<313, 256>>>();                                   // 1
    hist_kernel<<<(MM * EE + 255) / 256, 256>>>(dst);              // 2
    scan_kernel<<<MM, 1024>>>();                                   // 3

    // 4: feat[m] = h @ W[m], fused el/er epilogue
    gemm_mma<<<dim3(HD / GBN, (NN + GBM - 1) / GBM, MM), 256>>>(
        h, W, p_feat, NN, FF, HD, nullptr, 2,
        0L, (long)FF * HD, (long)NN * HD, al, ar, nullptr);

    edge_kernel<<<(MM * EE + 255) / 256, 256>>>(src, dst);         // 5
    agg_kernel<<<dim3(NN, MM), 128>>>(bg, pW);                     // 6 (ncu captures this)

    // 7: semantic — s[row] += sum tanh(z@W1 + b1) * W2, no C write
    gemm_mma<<<dim3(HIDD / GBN, (MM * NN + GBM - 1) / GBM, 1), 256>>>(
        p_z, sW1, nullptr, MM * NN, HD, HIDD, sb1, 3,
        0L, 0L, 0L, nullptr, nullptr, sW2);

    reduce_kernel<<<dim3(40, MM), 256>>>();                        // 8
    beta_kernel<<<1, 1>>>();                                       // 9
    final_kernel<<<(NN * CC + 255) / 256, 256>>>(pb, out);         // 10
}

// round 6
// speedup vs baseline: 3.1112x; 1.1328x over previous
#include <cuda_runtime.h>
#include <cuda_bf16.h>
#include <cuda_fp16.h>
#include <math.h>
#include <stdint.h>

#define NN 20000
#define FF 256
#define HH 8
#define DD 64
#define HD 512
#define MM 2
#define EE 320000
#define CC 5
#define HIDD 128

// ---------------- scratch (device globals; no allocation) ----------------
__device__ float g_feat[MM * NN * HD];
__device__ float g_z[MM * NN * HD];
__device__ float g_el[MM * NN * HH];
__device__ float g_er[MM * NN * HH];
__device__ int   g_hist[MM * NN];
__device__ int   g_rowptr[MM * (NN + 1)];
__device__ int   g_cursor[MM * NN];
__device__ int   g_src_s[MM * EE];
__device__ float g_ex_s[MM * EE * HH];
__device__ float g_s[MM * NN];
__device__ float g_y[MM * NN * CC];
__device__ float g_sum[MM];
__device__ float g_beta[MM];

// ---------------- zero init: hist, s, sum ----------------
__global__ void zero_kernel() {
    int i = blockIdx.x * blockDim.x + threadIdx.x;
    int total = MM * NN + MM * NN + MM;
    for (; i < total; i += gridDim.x * blockDim.x) {
        if (i < MM * NN) g_hist[i] = 0;
        else if (i < 2 * MM * NN) g_s[i - MM * NN] = 0.0f;
        else g_sum[i - 2 * MM * NN] = 0.0f;
    }
}

// ---------------- in-degree histogram ----------------
__global__ void hist_kernel(const int* __restrict__ dst) {
    int tid = blockIdx.x * blockDim.x + threadIdx.x;
    if (tid >= MM * EE) return;
    int m = tid / EE;
    atomicAdd(&g_hist[m * NN + dst[tid]], 1);
}

// ---------------- single-block exclusive scan per metapath ----------------
__global__ void scan_kernel() {
    int m = blockIdx.x;
    __shared__ int part[1024];
    int t = threadIdx.x;
    const int CH = 20;
    int base = t * CH;
    int local[CH];
    int s = 0;
#pragma unroll
    for (int i = 0; i < CH; i++) {
        int idx = base + i;
        int v = (idx < NN) ? g_hist[m * NN + idx] : 0;
        local[i] = v;
        s += v;
    }
    part[t] = s;
    __syncthreads();
    for (int off = 1; off < 1024; off <<= 1) {
        int v = (t >= off) ? part[t - off] : 0;
        __syncthreads();
        part[t] += v;
        __syncthreads();
    }
    int run = part[t] - s;
#pragma unroll
    for (int i = 0; i < CH; i++) {
        int idx = base + i;
        if (idx < NN) {
            g_rowptr[m * (NN + 1) + idx] = run;
            g_cursor[m * NN + idx] = run;
            run += local[i];
        }
    }
    if (t == 1023) g_rowptr[m * (NN + 1) + NN] = run;
}

// ---------------- FP16 tensor-core GEMM (fp32 accum), ldmatrix path --------
// mode 2: write C raw + fused el/er (head = blockIdx.x, metapath = blockIdx.z)
// mode 3: no C write; s[row] += sum_col tanh(acc + bias[col]) * w2[col]
#define GBM 128
#define GBN 64
#define GBK 32
#define SMSH 40   // smem row stride in halfs (32 + 8 pad) = 80B; conflict-free ldmatrix

__device__ __forceinline__ uint32_t f2h2(float a, float b) {
    __half2 h = __floats2half2_rn(a, b);
    return *(uint32_t*)&h;
}

#define LDSM4(r, addr)                                                          \
    asm volatile("ldmatrix.sync.aligned.m8n8.x4.shared.b16 {%0,%1,%2,%3}, [%4];" \
                 : "=r"((r)[0]), "=r"((r)[1]), "=r"((r)[2]), "=r"((r)[3])        \
                 : "r"(addr))

__device__ __forceinline__ void mma_f16(float4& d,
                                        uint32_t a0, uint32_t a1, uint32_t a2, uint32_t a3,
                                        uint32_t b0, uint32_t b1) {
    asm volatile("mma.sync.aligned.m16n8k16.row.col.f32.f16.f16.f32 "
                 "{%0,%1,%2,%3}, {%4,%5,%6,%7}, {%8,%9}, {%0,%1,%2,%3};"
                 : "+f"(d.x), "+f"(d.y), "+f"(d.z), "+f"(d.w)
                 : "r"(a0), "r"(a1), "r"(a2), "r"(a3), "r"(b0), "r"(b1));
}

__global__ __launch_bounds__(256) void gemm_mma(
    const float* __restrict__ A, const float* __restrict__ B, float* __restrict__ C,
    int Mrows, int K, int Ncols, const float* __restrict__ bias, int mode,
    long aStride, long bStride, long cStride,
    const float* __restrict__ attl, const float* __restrict__ attr,
    const float* __restrict__ w2) {
    int bz = blockIdx.z;
    A += (size_t)bz * aStride;
    B += (size_t)bz * bStride;
    C += (size_t)bz * cStride;

    __shared__ __align__(16) __half As[GBM * SMSH];   // [row][k]
    __shared__ __align__(16) __half Bs[GBN * SMSH];   // [n][k]  (transposed)

    int tid = threadIdx.x;
    int warp = tid >> 5;
    int lane = tid & 31;
    int warpM = warp >> 1;
    int warpN = warp & 1;
    int group = lane >> 2;
    int tig = lane & 3;

    int rowBase = blockIdx.y * GBM;
    int colBase = blockIdx.x * GBN;

    // A staging: thread loads 16 floats of one row half
    int aRow = tid >> 1;
    int aCol = (tid & 1) * 16;      // in halfs == in floats of source
    // B staging: thread loads 8 k-consecutive floats at one n (transposed store)
    int bN = tid & 63;
    int bK = (tid >> 6) * 8;

    // ldmatrix source pointers (u32 shared addresses, byte offsets)
    uint32_t AsU = (uint32_t)__cvta_generic_to_shared(As);
    uint32_t BsU = (uint32_t)__cvta_generic_to_shared(Bs);
    // A: lanes 0-15 -> rows 0-15 @k0 ; lanes 16-31 -> rows 0-15 @k+8 halfs (16B)
    uint32_t aPtr = AsU + (uint32_t)(((warpM * 32 + (lane & 15)) * SMSH) * 2 + (lane >> 4) * 16);
    // B: lanes 0-7 n0-7@k0, 8-15 n0-7@k8, 16-23 n8-15@k0, 24-31 n8-15@k8
    uint32_t bPtr = BsU + (uint32_t)(((warpN * 32 + (lane >> 4) * 8 + (lane & 7)) * SMSH) * 2
                                     + (((lane >> 3) & 1) * 16));

    float4 acc[2][4];
#pragma unroll
    for (int i = 0; i < 2; i++)
#pragma unroll
        for (int j = 0; j < 4; j++) acc[i][j] = make_float4(0.f, 0.f, 0.f, 0.f);

    float4 aReg[4];
    float bRegT[8];

    int gaRow = rowBase + aRow;
    bool aValid = gaRow < Mrows;

    // preload tile 0
    {
        const float* Ap = A + (size_t)gaRow * K + aCol;
        if (aValid) {
#pragma unroll
            for (int i = 0; i < 4; i++) aReg[i] = *(const float4*)(Ap + 4 * i);
        } else {
#pragma unroll
            for (int i = 0; i < 4; i++) aReg[i] = make_float4(0.f, 0.f, 0.f, 0.f);
        }
        const float* Bp = B + (size_t)bK * Ncols + colBase + bN;
#pragma unroll
        for (int j = 0; j < 8; j++) bRegT[j] = Bp[(size_t)j * Ncols];
    }

    for (int k0 = 0; k0 < K; k0 += GBK) {
        // staged regs -> smem (fp16-converted, vectorized 16B stores)
        {
            uint4 v0 = make_uint4(f2h2(aReg[0].x, aReg[0].y), f2h2(aReg[0].z, aReg[0].w),
                                  f2h2(aReg[1].x, aReg[1].y), f2h2(aReg[1].z, aReg[1].w));
            uint4 v1 = make_uint4(f2h2(aReg[2].x, aReg[2].y), f2h2(aReg[2].z, aReg[2].w),
                                  f2h2(aReg[3].x, aReg[3].y), f2h2(aReg[3].z, aReg[3].w));
            *(uint4*)&As[aRow * SMSH + aCol] = v0;
            *(uint4*)&As[aRow * SMSH + aCol + 8] = v1;
            uint4 bv = make_uint4(f2h2(bRegT[0], bRegT[1]), f2h2(bRegT[2], bRegT[3]),
                                  f2h2(bRegT[4], bRegT[5]), f2h2(bRegT[6], bRegT[7]));
            *(uint4*)&Bs[bN * SMSH + bK] = bv;
        }
        __syncthreads();

        // prefetch next tile
        if (k0 + GBK < K) {
            const float* Ap = A + (size_t)gaRow * K + (k0 + GBK) + aCol;
            if (aValid) {
#pragma unroll
                for (int i = 0; i < 4; i++) aReg[i] = *(const float4*)(Ap + 4 * i);
            }
            const float* Bp = B + (size_t)(k0 + GBK + bK) * Ncols + colBase + bN;
#pragma unroll
            for (int j = 0; j < 8; j++) bRegT[j] = Bp[(size_t)j * Ncols];
        }

        // 2 k-steps of m16n8k16
#pragma unroll
        for (int kk = 0; kk < 2; kk++) {
            uint32_t kb = kk * 32;   // 16 halfs = 32 bytes per k-step
            uint32_t af[2][4];
            LDSM4(af[0], aPtr + kb);
            LDSM4(af[1], aPtr + 16 * SMSH * 2 + kb);
            uint32_t bfr[2][4];      // [half of n32][{b0 n-blk0, b1 n-blk0, b0 n-blk1, b1 n-blk1}]
            LDSM4(bfr[0], bPtr + kb);
            LDSM4(bfr[1], bPtr + 16 * SMSH * 2 + kb);
#pragma unroll
            for (int mt = 0; mt < 2; mt++)
#pragma unroll
                for (int nt = 0; nt < 4; nt++)
                    mma_f16(acc[mt][nt], af[mt][0], af[mt][1], af[mt][2], af[mt][3],
                            bfr[nt >> 1][(nt & 1) * 2], bfr[nt >> 1][(nt & 1) * 2 + 1]);
        }
        __syncthreads();
    }

    if (mode == 2) {
        int head = blockIdx.x;
        const float* alp = attl + (bz * HH + head) * DD;
        const float* arp = attr + (bz * HH + head) * DD;
        float sl[2][2] = {{0.f, 0.f}, {0.f, 0.f}};
        float sr[2][2] = {{0.f, 0.f}, {0.f, 0.f}};
#pragma unroll
        for (int mt = 0; mt < 2; mt++) {
            int row0 = rowBase + warpM * 32 + mt * 16 + group;
            int row1 = row0 + 8;
#pragma unroll
            for (int nt = 0; nt < 4; nt++) {
                int cl = warpN * 32 + nt * 8 + 2 * tig;
                float4 v = acc[mt][nt];
                float a0 = alp[cl], a1 = alp[cl + 1];
                float r0 = arp[cl], r1 = arp[cl + 1];
                sl[mt][0] += v.x * a0 + v.y * a1;
                sl[mt][1] += v.z * a0 + v.w * a1;
                sr[mt][0] += v.x * r0 + v.y * r1;
                sr[mt][1] += v.z * r0 + v.w * r1;
                int col = colBase + cl;
                if (row0 < Mrows) *(float2*)(C + (size_t)row0 * Ncols + col) = make_float2(v.x, v.y);
                if (row1 < Mrows) *(float2*)(C + (size_t)row1 * Ncols + col) = make_float2(v.z, v.w);
            }
        }
#pragma unroll
        for (int mt = 0; mt < 2; mt++)
#pragma unroll
            for (int r = 0; r < 2; r++) {
                sl[mt][r] += __shfl_xor_sync(0xffffffffu, sl[mt][r], 1);
                sl[mt][r] += __shfl_xor_sync(0xffffffffu, sl[mt][r], 2);
                sr[mt][r] += __shfl_xor_sync(0xffffffffu, sr[mt][r], 1);
                sr[mt][r] += __shfl_xor_sync(0xffffffffu, sr[mt][r], 2);
            }
        __syncthreads();
        float* redl = (float*)As;
        float* redr = (float*)As + 256;
        if (tig == 0) {
#pragma unroll
            for (int mt = 0; mt < 2; mt++) {
                int rl0 = warpM * 32 + mt * 16 + group;
                redl[rl0 * 2 + warpN] = sl[mt][0];
                redl[(rl0 + 8) * 2 + warpN] = sl[mt][1];
                redr[rl0 * 2 + warpN] = sr[mt][0];
                redr[(rl0 + 8) * 2 + warpN] = sr[mt][1];
            }
        }
        __syncthreads();
        if (tid < 128) {
            int grow = rowBase + tid;
            if (grow < Mrows) {
                g_el[(bz * NN + grow) * HH + head] = redl[tid * 2] + redl[tid * 2 + 1];
                g_er[(bz * NN + grow) * HH + head] = redr[tid * 2] + redr[tid * 2 + 1];
            }
        }
    } else {
        // mode 3: semantic — no C write; accumulate s[row]
        float sp[2][2] = {{0.f, 0.f}, {0.f, 0.f}};
#pragma unroll
        for (int mt = 0; mt < 2; mt++) {
#pragma unroll
            for (int nt = 0; nt < 4; nt++) {
                int cl = warpN * 32 + nt * 8 + 2 * tig;
                int col = colBase + cl;
                float b0 = bias[col], b1 = bias[col + 1];
                float w0 = w2[col], w1 = w2[col + 1];
                float4 v = acc[mt][nt];
                sp[mt][0] += tanhf(v.x + b0) * w0 + tanhf(v.y + b1) * w1;
                sp[mt][1] += tanhf(v.z + b0) * w0 + tanhf(v.w + b1) * w1;
            }
        }
#pragma unroll
        for (int mt = 0; mt < 2; mt++)
#pragma unroll
            for (int r = 0; r < 2; r++) {
                sp[mt][r] += __shfl_xor_sync(0xffffffffu, sp[mt][r], 1);
                sp[mt][r] += __shfl_xor_sync(0xffffffffu, sp[mt][r], 2);
            }
        __syncthreads();
        float* red = (float*)As;
        if (tig == 0) {
#pragma unroll
            for (int mt = 0; mt < 2; mt++) {
                int rl0 = warpM * 32 + mt * 16 + group;
                red[rl0 * 2 + warpN] = sp[mt][0];
                red[(rl0 + 8) * 2 + warpN] = sp[mt][1];
            }
        }
        __syncthreads();
        if (tid < 128) {
            int grow = rowBase + tid;
            if (grow < Mrows)
                atomicAdd(&g_s[grow], red[tid * 2] + red[tid * 2 + 1]);
        }
    }
}

// ---------------- edge pass: exp(leaky(el+er)) + CSR scatter ----------------
__global__ void edge_kernel(const int* __restrict__ src, const int* __restrict__ dst) {
    int tid = blockIdx.x * blockDim.x + threadIdx.x;
    if (tid >= MM * EE) return;
    int m = tid / EE;
    int s = src[tid];
    int d = dst[tid];
    const float4* elp = (const float4*)(g_el + (size_t)(m * NN + s) * HH);
    const float4* erp = (const float4*)(g_er + (size_t)(m * NN + d) * HH);
    float4 e0 = elp[0], e1 = elp[1];
    float4 r0 = erp[0], r1 = erp[1];
    float ex[8];
    float v;
    v = e0.x + r0.x; v = v > 0.f ? v : 0.2f * v; ex[0] = expf(v);
    v = e0.y + r0.y; v = v > 0.f ? v : 0.2f * v; ex[1] = expf(v);
    v = e0.z + r0.z; v = v > 0.f ? v : 0.2f * v; ex[2] = expf(v);
    v = e0.w + r0.w; v = v > 0.f ? v : 0.2f * v; ex[3] = expf(v);
    v = e1.x + r1.x; v = v > 0.f ? v : 0.2f * v; ex[4] = expf(v);
    v = e1.y + r1.y; v = v > 0.f ? v : 0.2f * v; ex[5] = expf(v);
    v = e1.z + r1.z; v = v > 0.f ? v : 0.2f * v; ex[6] = expf(v);
    v = e1.w + r1.w; v = v > 0.f ? v : 0.2f * v; ex[7] = expf(v);

    int pos = atomicAdd(&g_cursor[m * NN + d], 1);
    int gp = m * EE + pos;
    g_src_s[gp] = s;
    float4* xp = (float4*)(g_ex_s + (size_t)gp * HH);
    xp[0] = make_float4(ex[0], ex[1], ex[2], ex[3]);
    xp[1] = make_float4(ex[4], ex[5], ex[6], ex[7]);
}

// ---------------- aggregation + fused per-metapath classifier ----------------
__global__ void agg_kernel(const float* __restrict__ bg, const float* __restrict__ pW) {
    int n = blockIdx.x;
    int m = blockIdx.y;
    int t = threadIdx.x;           // 0..127, owns dims [4t, 4t+4)
    int h = t >> 4;
    int beg = g_rowptr[m * (NN + 1) + n];
    int end = g_rowptr[m * (NN + 1) + n + 1];
    float ax = 0.f, ay = 0.f, az = 0.f, aw = 0.f;
    float dsum = 0.f;
    for (int j = beg; j < end; j++) {
        int gp = m * EE + j;
        int s = g_src_s[gp];
        float exv = g_ex_s[(size_t)gp * HH + h];
        dsum += exv;
        float4 f = *(const float4*)(g_feat + ((size_t)(m * NN + s)) * HD + t * 4);
        ax += exv * f.x; ay += exv * f.y; az += exv * f.z; aw += exv * f.w;
    }
    float inv = 1.0f / fmaxf(dsum, 1e-9f);
    const float* bp = bg + m * HD + t * 4;
    float o0 = ax * inv + bp[0], o1 = ay * inv + bp[1];
    float o2 = az * inv + bp[2], o3 = aw * inv + bp[3];
    o0 = o0 > 0.f ? o0 : expf(o0) - 1.0f;
    o1 = o1 > 0.f ? o1 : expf(o1) - 1.0f;
    o2 = o2 > 0.f ? o2 : expf(o2) - 1.0f;
    o3 = o3 > 0.f ? o3 : expf(o3) - 1.0f;
    *(float4*)(g_z + ((size_t)(m * NN + n)) * HD + t * 4) = make_float4(o0, o1, o2, o3);

    // fused y[m,n,c] = z_row . pred_W[:,c]
    const float* w = pW + (size_t)t * 4 * CC;
    float yc[CC];
#pragma unroll
    for (int c = 0; c < CC; c++)
        yc[c] = o0 * w[c] + o1 * w[CC + c] + o2 * w[2 * CC + c] + o3 * w[3 * CC + c];
#pragma unroll
    for (int c = 0; c < CC; c++)
#pragma unroll
        for (int off = 16; off > 0; off >>= 1)
            yc[c] += __shfl_down_sync(0xffffffffu, yc[c], off);
    __shared__ float ysh[4][CC];
    int warp = t >> 5, lane = t & 31;
    if (lane == 0)
#pragma unroll
        for (int c = 0; c < CC; c++) ysh[warp][c] = yc[c];
    __syncthreads();
    if (t < CC) {
        float v = ysh[0][t] + ysh[1][t] + ysh[2][t] + ysh[3][t];
        g_y[((size_t)m * NN + n) * CC + t] = v;
    }
}

// ---------------- mean over nodes per metapath ----------------
__global__ void reduce_kernel() {
    int m = blockIdx.y;
    int t = threadIdx.x;
    float s = 0.f;
    for (int i = blockIdx.x * blockDim.x + t; i < NN; i += gridDim.x * blockDim.x)
        s += g_s[m * NN + i];
    __shared__ float sh[256];
    sh[t] = s;
    __syncthreads();
    for (int off = 128; off > 0; off >>= 1) {
        if (t < off) sh[t] += sh[t + off];
        __syncthreads();
    }
    if (t == 0) atomicAdd(&g_sum[m], sh[0]);
}

__global__ void beta_kernel() {
    float a = g_sum[0] / (float)NN;
    float b = g_sum[1] / (float)NN;
    float mx = fmaxf(a, b);
    float e0 = expf(a - mx), e1 = expf(b - mx);
    float inv = 1.0f / (e0 + e1);
    g_beta[0] = e0 * inv;
    g_beta[1] = e1 * inv;
}

// ---------------- tiny final: out = b0*y0 + b1*y1 + pb ----------------
__global__ void final_kernel(const float* __restrict__ pb, float* __restrict__ out) {
    int tid = blockIdx.x * blockDim.x + threadIdx.x;
    if (tid >= NN * CC) return;
    int c = tid % CC;
    float b0 = g_beta[0], b1 = g_beta[1];
    out[tid] = b0 * g_y[tid] + b1 * g_y[NN * CC + tid] + pb[c];
}

// ---------------- launch ----------------
extern "C" void kernel_launch(void* const* d_in, const int* in_sizes, int n_in,
                              void* d_out, int out_size) {
    const float* h    = (const float*)d_in[0];
    const int*   src  = (const int*)d_in[1];
    const int*   dst  = (const int*)d_in[2];
    const float* W    = (const float*)d_in[3];
    const float* al   = (const float*)d_in[4];
    const float* ar   = (const float*)d_in[5];
    const float* bg   = (const float*)d_in[6];
    const float* sW1  = (const float*)d_in[7];
    const float* sb1  = (const float*)d_in[8];
    const float* sW2  = (const float*)d_in[9];
    const float* pW   = (const float*)d_in[10];
    const float* pb   = (const float*)d_in[11];
    float* out = (float*)d_out;

    float *p_feat, *p_z;
    cudaGetSymbolAddress((void**)&p_feat, g_feat);
    cudaGetSymbolAddress((void**)&p_z, g_z);

    zero_kernel<<<313, 256>>>();                                   // 1
    hist_kernel<<<(MM * EE + 255) / 256, 256>>>(dst);              // 2
    scan_kernel<<<MM, 1024>>>();                                   // 3

    // 4: feat[m] = h @ W[m], fused el/er epilogue
    gemm_mma<<<dim3(HD / GBN, (NN + GBM - 1) / GBM, MM), 256>>>(
        h, W, p_feat, NN, FF, HD, nullptr, 2,
        0L, (long)FF * HD, (long)NN * HD, al, ar, nullptr);

    edge_kernel<<<(MM * EE + 255) / 256, 256>>>(src, dst);         // 5
    agg_kernel<<<dim3(NN, MM), 128>>>(bg, pW);                     // 6 (ncu captures this)

    // 7: semantic — s[row] += sum tanh(z@W1 + b1) * W2, no C write
    gemm_mma<<<dim3(HIDD / GBN, (MM * NN + GBM - 1) / GBM, 1), 256>>>(
        p_z, sW1, nullptr, MM * NN, HD, HIDD, sb1, 3,
        0L, 0L, 0L, nullptr, nullptr, sW2);

    reduce_kernel<<<dim3(40, MM), 256>>>();                        // 8
    beta_kernel<<<1, 1>>>();                                       // 9
    final_kernel<<<(NN * CC + 255) / 256, 256>>>(pb, out);         // 10
}

// round 8
// speedup vs baseline: 3.2191x; 1.0347x over previous
#include <cuda_runtime.h>
#include <cuda_bf16.h>
#include <cuda_fp16.h>
#include <math.h>
#include <stdint.h>

#define NN 20000
#define FF 256
#define HH 8
#define DD 64
#define HD 512
#define MM 2
#define EE 320000
#define CC 5
#define HIDD 128

// ---------------- scratch (device globals; no allocation) ----------------
__device__ float g_feat[MM * NN * HD];
__device__ float g_z[MM * NN * HD];
__device__ float g_el[MM * NN * HH];
__device__ float g_er[MM * NN * HH];
__device__ int   g_hist[MM * NN];
__device__ int   g_rowptr[MM * (NN + 1)];
__device__ int   g_cursor[MM * NN];
__device__ int   g_src_s[MM * EE];
__device__ float g_ex_s[MM * EE * HH];
__device__ float g_s[MM * NN];
__device__ float g_y[MM * NN * CC];
__device__ float g_sum[MM];
__device__ float g_beta[MM];

// ---------------- zero init: hist, s, sum ----------------
__global__ void zero_kernel() {
    int i = blockIdx.x * blockDim.x + threadIdx.x;
    int total = MM * NN + MM * NN + MM;
    for (; i < total; i += gridDim.x * blockDim.x) {
        if (i < MM * NN) g_hist[i] = 0;
        else if (i < 2 * MM * NN) g_s[i - MM * NN] = 0.0f;
        else g_sum[i - 2 * MM * NN] = 0.0f;
    }
}

// ---------------- in-degree histogram ----------------
__global__ void hist_kernel(const int* __restrict__ dst) {
    int tid = blockIdx.x * blockDim.x + threadIdx.x;
    if (tid >= MM * EE) return;
    int m = tid / EE;
    atomicAdd(&g_hist[m * NN + dst[tid]], 1);
}

// ---------------- single-block exclusive scan per metapath ----------------
__global__ void scan_kernel() {
    int m = blockIdx.x;
    __shared__ int part[1024];
    int t = threadIdx.x;
    const int CH = 20;
    int base = t * CH;
    int local[CH];
    int s = 0;
#pragma unroll
    for (int i = 0; i < CH; i++) {
        int idx = base + i;
        int v = (idx < NN) ? g_hist[m * NN + idx] : 0;
        local[i] = v;
        s += v;
    }
    part[t] = s;
    __syncthreads();
    for (int off = 1; off < 1024; off <<= 1) {
        int v = (t >= off) ? part[t - off] : 0;
        __syncthreads();
        part[t] += v;
        __syncthreads();
    }
    int run = part[t] - s;
#pragma unroll
    for (int i = 0; i < CH; i++) {
        int idx = base + i;
        if (idx < NN) {
            g_rowptr[m * (NN + 1) + idx] = run;
            g_cursor[m * NN + idx] = run;
            run += local[i];
        }
    }
    if (t == 1023) g_rowptr[m * (NN + 1) + NN] = run;
}

// ---------------- FP16 MMA GEMM, 128x128 CTA tile, 32x64 warp tile ---------
// mode 2: write C raw + fused el/er (heads = blockIdx.x*2 + warpN, metapath = bz)
// mode 3: no C write; s[row] += sum_col tanh(acc + bias[col]) * w2[col]
#define GBM 128
#define GBN 128
#define GBK 16
#define SMSH 24   // smem row stride in halfs (16 + 8 pad) = 48B; conflict-free ldmatrix

__device__ __forceinline__ uint32_t f2h2(float a, float b) {
    __half2 h = __floats2half2_rn(a, b);
    return *(uint32_t*)&h;
}

#define LDSM4(r, addr)                                                          \
    asm volatile("ldmatrix.sync.aligned.m8n8.x4.shared.b16 {%0,%1,%2,%3}, [%4];" \
                 : "=r"((r)[0]), "=r"((r)[1]), "=r"((r)[2]), "=r"((r)[3])        \
                 : "r"(addr))

__device__ __forceinline__ void mma_f16(float4& d,
                                        uint32_t a0, uint32_t a1, uint32_t a2, uint32_t a3,
                                        uint32_t b0, uint32_t b1) {
    asm volatile("mma.sync.aligned.m16n8k16.row.col.f32.f16.f16.f32 "
                 "{%0,%1,%2,%3}, {%4,%5,%6,%7}, {%8,%9}, {%0,%1,%2,%3};"
                 : "+f"(d.x), "+f"(d.y), "+f"(d.z), "+f"(d.w)
                 : "r"(a0), "r"(a1), "r"(a2), "r"(a3), "r"(b0), "r"(b1));
}

__global__ __launch_bounds__(256) void gemm_mma(
    const float* __restrict__ A, const float* __restrict__ B, float* __restrict__ C,
    int Mrows, int K, int Ncols, const float* __restrict__ bias, int mode,
    long aStride, long bStride, long cStride,
    const float* __restrict__ attl, const float* __restrict__ attr,
    const float* __restrict__ w2) {
    int bz = blockIdx.z;
    A += (size_t)bz * aStride;
    B += (size_t)bz * bStride;
    C += (size_t)bz * cStride;

    __shared__ __align__(16) __half As[GBM * SMSH];   // [row][k]
    __shared__ __align__(16) __half Bs[GBN * SMSH];   // [n][k]  (transposed)

    int tid = threadIdx.x;
    int warp = tid >> 5;
    int lane = tid & 31;
    int warpM = warp >> 1;     // 0..3  (32-row slices)
    int warpN = warp & 1;      // 0..1  (64-col halves)
    int group = lane >> 2;
    int tig = lane & 3;

    int rowBase = blockIdx.y * GBM;
    int colBase = blockIdx.x * GBN;

    // A staging: thread loads 8 k-floats of one row
    int aRow = tid >> 1;
    int aCol = (tid & 1) * 8;
    // B staging: thread loads 8 k-floats at one n (transposed store)
    int bN = tid & 127;
    int bK = (tid >> 7) * 8;

    uint32_t AsU = (uint32_t)__cvta_generic_to_shared(As);
    uint32_t BsU = (uint32_t)__cvta_generic_to_shared(Bs);
    uint32_t aPtr = AsU + (uint32_t)(((warpM * 32 + (lane & 15)) * SMSH) * 2 + (lane >> 4) * 16);
    uint32_t bPtr = BsU + (uint32_t)(((warpN * 64 + (lane >> 4) * 8 + (lane & 7)) * SMSH) * 2
                                     + (((lane >> 3) & 1) * 16));

    float4 acc[2][8];
#pragma unroll
    for (int i = 0; i < 2; i++)
#pragma unroll
        for (int j = 0; j < 8; j++) acc[i][j] = make_float4(0.f, 0.f, 0.f, 0.f);

    float4 aReg[2];
    float bRegT[8];

    int gaRow = rowBase + aRow;
    bool aValid = gaRow < Mrows;

    // preload tile 0
    {
        const float* Ap = A + (size_t)gaRow * K + aCol;
        if (aValid) {
            aReg[0] = *(const float4*)(Ap);
            aReg[1] = *(const float4*)(Ap + 4);
        } else {
            aReg[0] = aReg[1] = make_float4(0.f, 0.f, 0.f, 0.f);
        }
        const float* Bp = B + (size_t)bK * Ncols + colBase + bN;
#pragma unroll
        for (int j = 0; j < 8; j++) bRegT[j] = Bp[(size_t)j * Ncols];
    }

    for (int k0 = 0; k0 < K; k0 += GBK) {
        // staged regs -> smem (fp16-converted, one 16B store each)
        {
            uint4 av = make_uint4(f2h2(aReg[0].x, aReg[0].y), f2h2(aReg[0].z, aReg[0].w),
                                  f2h2(aReg[1].x, aReg[1].y), f2h2(aReg[1].z, aReg[1].w));
            *(uint4*)&As[aRow * SMSH + aCol] = av;
            uint4 bv = make_uint4(f2h2(bRegT[0], bRegT[1]), f2h2(bRegT[2], bRegT[3]),
                                  f2h2(bRegT[4], bRegT[5]), f2h2(bRegT[6], bRegT[7]));
            *(uint4*)&Bs[bN * SMSH + bK] = bv;
        }
        __syncthreads();

        // prefetch next tile
        if (k0 + GBK < K) {
            const float* Ap = A + (size_t)gaRow * K + (k0 + GBK) + aCol;
            if (aValid) {
                aReg[0] = *(const float4*)(Ap);
                aReg[1] = *(const float4*)(Ap + 4);
            }
            const float* Bp = B + (size_t)(k0 + GBK + bK) * Ncols + colBase + bN;
#pragma unroll
            for (int j = 0; j < 8; j++) bRegT[j] = Bp[(size_t)j * Ncols];
        }

        // one m16n8k16 k-step
        {
            uint32_t af[2][4];
            LDSM4(af[0], aPtr);
            LDSM4(af[1], aPtr + 16 * SMSH * 2);
            uint32_t bfr[4][4];
#pragma unroll
            for (int p = 0; p < 4; p++) LDSM4(bfr[p], bPtr + p * 16 * SMSH * 2);
#pragma unroll
            for (int mt = 0; mt < 2; mt++)
#pragma unroll
                for (int nt = 0; nt < 8; nt++)
                    mma_f16(acc[mt][nt], af[mt][0], af[mt][1], af[mt][2], af[mt][3],
                            bfr[nt >> 1][(nt & 1) * 2], bfr[nt >> 1][(nt & 1) * 2 + 1]);
        }
        __syncthreads();
    }

    if (mode == 2) {
        // each warp owns a full head: head = blockIdx.x*2 + warpN
        int head = blockIdx.x * 2 + warpN;
        const float* alp = attl + (bz * HH + head) * DD;
        const float* arp = attr + (bz * HH + head) * DD;
        float sl[2][2] = {{0.f, 0.f}, {0.f, 0.f}};
        float sr[2][2] = {{0.f, 0.f}, {0.f, 0.f}};
#pragma unroll
        for (int mt = 0; mt < 2; mt++) {
            int row0 = rowBase + warpM * 32 + mt * 16 + group;
            int row1 = row0 + 8;
#pragma unroll
            for (int nt = 0; nt < 8; nt++) {
                int cl = nt * 8 + 2 * tig;           // 0..63 within head
                float4 v = acc[mt][nt];
                float a0 = alp[cl], a1 = alp[cl + 1];
                float r0 = arp[cl], r1 = arp[cl + 1];
                sl[mt][0] += v.x * a0 + v.y * a1;
                sl[mt][1] += v.z * a0 + v.w * a1;
                sr[mt][0] += v.x * r0 + v.y * r1;
                sr[mt][1] += v.z * r0 + v.w * r1;
                int col = colBase + warpN * 64 + cl;
                if (row0 < Mrows) *(float2*)(C + (size_t)row0 * Ncols + col) = make_float2(v.x, v.y);
                if (row1 < Mrows) *(float2*)(C + (size_t)row1 * Ncols + col) = make_float2(v.z, v.w);
            }
        }
#pragma unroll
        for (int mt = 0; mt < 2; mt++)
#pragma unroll
            for (int r = 0; r < 2; r++) {
                sl[mt][r] += __shfl_xor_sync(0xffffffffu, sl[mt][r], 1);
                sl[mt][r] += __shfl_xor_sync(0xffffffffu, sl[mt][r], 2);
                sr[mt][r] += __shfl_xor_sync(0xffffffffu, sr[mt][r], 1);
                sr[mt][r] += __shfl_xor_sync(0xffffffffu, sr[mt][r], 2);
            }
        if (tig == 0) {
#pragma unroll
            for (int mt = 0; mt < 2; mt++) {
                int row0 = rowBase + warpM * 32 + mt * 16 + group;
                int row1 = row0 + 8;
                if (row0 < Mrows) {
                    g_el[(bz * NN + row0) * HH + head] = sl[mt][0];
                    g_er[(bz * NN + row0) * HH + head] = sr[mt][0];
                }
                if (row1 < Mrows) {
                    g_el[(bz * NN + row1) * HH + head] = sl[mt][1];
                    g_er[(bz * NN + row1) * HH + head] = sr[mt][1];
                }
            }
        }
    } else {
        // mode 3: semantic — no C write; each warp covers 64 of the 128 cols
        float sp[2][2] = {{0.f, 0.f}, {0.f, 0.f}};
#pragma unroll
        for (int mt = 0; mt < 2; mt++) {
#pragma unroll
            for (int nt = 0; nt < 8; nt++) {
                int col = colBase + warpN * 64 + nt * 8 + 2 * tig;
                float b0 = bias[col], b1 = bias[col + 1];
                float w0 = w2[col], w1 = w2[col + 1];
                float4 v = acc[mt][nt];
                sp[mt][0] += tanhf(v.x + b0) * w0 + tanhf(v.y + b1) * w1;
                sp[mt][1] += tanhf(v.z + b0) * w0 + tanhf(v.w + b1) * w1;
            }
        }
#pragma unroll
        for (int mt = 0; mt < 2; mt++)
#pragma unroll
            for (int r = 0; r < 2; r++) {
                sp[mt][r] += __shfl_xor_sync(0xffffffffu, sp[mt][r], 1);
                sp[mt][r] += __shfl_xor_sync(0xffffffffu, sp[mt][r], 2);
            }
        if (tig == 0) {
#pragma unroll
            for (int mt = 0; mt < 2; mt++) {
                int row0 = rowBase + warpM * 32 + mt * 16 + group;
                int row1 = row0 + 8;
                if (row0 < Mrows) atomicAdd(&g_s[row0], sp[mt][0]);
                if (row1 < Mrows) atomicAdd(&g_s[row1], sp[mt][1]);
            }
        }
    }
}

// ---------------- edge pass: exp(leaky(el+er)) + CSR scatter ----------------
__global__ void edge_kernel(const int* __restrict__ src, const int* __restrict__ dst) {
    int tid = blockIdx.x * blockDim.x + threadIdx.x;
    if (tid >= MM * EE) return;
    int m = tid / EE;
    int s = src[tid];
    int d = dst[tid];
    const float4* elp = (const float4*)(g_el + (size_t)(m * NN + s) * HH);
    const float4* erp = (const float4*)(g_er + (size_t)(m * NN + d) * HH);
    float4 e0 = elp[0], e1 = elp[1];
    float4 r0 = erp[0], r1 = erp[1];
    float ex[8];
    float v;
    v = e0.x + r0.x; v = v > 0.f ? v : 0.2f * v; ex[0] = expf(v);
    v = e0.y + r0.y; v = v > 0.f ? v : 0.2f * v; ex[1] = expf(v);
    v = e0.z + r0.z; v = v > 0.f ? v : 0.2f * v; ex[2] = expf(v);
    v = e0.w + r0.w; v = v > 0.f ? v : 0.2f * v; ex[3] = expf(v);
    v = e1.x + r1.x; v = v > 0.f ? v : 0.2f * v; ex[4] = expf(v);
    v = e1.y + r1.y; v = v > 0.f ? v : 0.2f * v; ex[5] = expf(v);
    v = e1.z + r1.z; v = v > 0.f ? v : 0.2f * v; ex[6] = expf(v);
    v = e1.w + r1.w; v = v > 0.f ? v : 0.2f * v; ex[7] = expf(v);

    int pos = atomicAdd(&g_cursor[m * NN + d], 1);
    int gp = m * EE + pos;
    g_src_s[gp] = s;
    float4* xp = (float4*)(g_ex_s + (size_t)gp * HH);
    xp[0] = make_float4(ex[0], ex[1], ex[2], ex[3]);
    xp[1] = make_float4(ex[4], ex[5], ex[6], ex[7]);
}

// ---------------- aggregation + fused per-metapath classifier ----------------
__global__ void agg_kernel(const float* __restrict__ bg, const float* __restrict__ pW) {
    int n = blockIdx.x;
    int m = blockIdx.y;
    int t = threadIdx.x;           // 0..127, owns dims [4t, 4t+4)
    int h = t >> 4;
    int beg = g_rowptr[m * (NN + 1) + n];
    int end = g_rowptr[m * (NN + 1) + n + 1];
    float ax = 0.f, ay = 0.f, az = 0.f, aw = 0.f;
    float dsum = 0.f;
    for (int j = beg; j < end; j++) {
        int gp = m * EE + j;
        int s = g_src_s[gp];
        float exv = g_ex_s[(size_t)gp * HH + h];
        dsum += exv;
        float4 f = *(const float4*)(g_feat + ((size_t)(m * NN + s)) * HD + t * 4);
        ax += exv * f.x; ay += exv * f.y; az += exv * f.z; aw += exv * f.w;
    }
    float inv = 1.0f / fmaxf(dsum, 1e-9f);
    const float* bp = bg + m * HD + t * 4;
    float o0 = ax * inv + bp[0], o1 = ay * inv + bp[1];
    float o2 = az * inv + bp[2], o3 = aw * inv + bp[3];
    o0 = o0 > 0.f ? o0 : expf(o0) - 1.0f;
    o1 = o1 > 0.f ? o1 : expf(o1) - 1.0f;
    o2 = o2 > 0.f ? o2 : expf(o2) - 1.0f;
    o3 = o3 > 0.f ? o3 : expf(o3) - 1.0f;
    *(float4*)(g_z + ((size_t)(m * NN + n)) * HD + t * 4) = make_float4(o0, o1, o2, o3);

    // fused y[m,n,c] = z_row . pred_W[:,c]
    const float* w = pW + (size_t)t * 4 * CC;
    float yc[CC];
#pragma unroll
    for (int c = 0; c < CC; c++)
        yc[c] = o0 * w[c] + o1 * w[CC + c] + o2 * w[2 * CC + c] + o3 * w[3 * CC + c];
#pragma unroll
    for (int c = 0; c < CC; c++)
#pragma unroll
        for (int off = 16; off > 0; off >>= 1)
            yc[c] += __shfl_down_sync(0xffffffffu, yc[c], off);
    __shared__ float ysh[4][CC];
    int warp = t >> 5, lane = t & 31;
    if (lane == 0)
#pragma unroll
        for (int c = 0; c < CC; c++) ysh[warp][c] = yc[c];
    __syncthreads();
    if (t < CC) {
        float v = ysh[0][t] + ysh[1][t] + ysh[2][t] + ysh[3][t];
        g_y[((size_t)m * NN + n) * CC + t] = v;
    }
}

// ---------------- mean over nodes per metapath ----------------
__global__ void reduce_kernel() {
    int m = blockIdx.y;
    int t = threadIdx.x;
    float s = 0.f;
    for (int i = blockIdx.x * blockDim.x + t; i < NN; i += gridDim.x * blockDim.x)
        s += g_s[m * NN + i];
    __shared__ float sh[256];
    sh[t] = s;
    __syncthreads();
    for (int off = 128; off > 0; off >>= 1) {
        if (t < off) sh[t] += sh[t + off];
        __syncthreads();
    }
    if (t == 0) atomicAdd(&g_sum[m], sh[0]);
}

__global__ void beta_kernel() {
    float a = g_sum[0] / (float)NN;
    float b = g_sum[1] / (float)NN;
    float mx = fmaxf(a, b);
    float e0 = expf(a - mx), e1 = expf(b - mx);
    float inv = 1.0f / (e0 + e1);
    g_beta[0] = e0 * inv;
    g_beta[1] = e1 * inv;
}

// ---------------- tiny final: out = b0*y0 + b1*y1 + pb ----------------
__global__ void final_kernel(const float* __restrict__ pb, float* __restrict__ out) {
    int tid = blockIdx.x * blockDim.x + threadIdx.x;
    if (tid >= NN * CC) return;
    int c = tid % CC;
    float b0 = g_beta[0], b1 = g_beta[1];
    out[tid] = b0 * g_y[tid] + b1 * g_y[NN * CC + tid] + pb[c];
}

// ---------------- launch ----------------
extern "C" void kernel_launch(void* const* d_in, const int* in_sizes, int n_in,
                              void* d_out, int out_size) {
    const float* h    = (const float*)d_in[0];
    const int*   src  = (const int*)d_in[1];
    const int*   dst  = (const int*)d_in[2];
    const float* W    = (const float*)d_in[3];
    const float* al   = (const float*)d_in[4];
    const float* ar   = (const float*)d_in[5];
    const float* bg   = (const float*)d_in[6];
    const float* sW1  = (const float*)d_in[7];
    const float* sb1  = (const float*)d_in[8];
    const float* sW2  = (const float*)d_in[9];
    const float* pW   = (const float*)d_in[10];
    const float* pb   = (const float*)d_in[11];
    float* out = (float*)d_out;

    float *p_feat, *p_z;
    cudaGetSymbolAddress((void**)&p_feat, g_feat);
    cudaGetSymbolAddress((void**)&p_z, g_z);

    zero_kernel<<<313, 256>>>();                                   // 1
    hist_kernel<<<(MM * EE + 255) / 256, 256>>>(dst);              // 2
    scan_kernel<<<MM, 1024>>>();                                   // 3

    // 4: feat[m] = h @ W[m], fused el/er epilogue (2 heads per CTA)
    gemm_mma<<<dim3(HD / GBN, (NN + GBM - 1) / GBM, MM), 256>>>(
        h, W, p_feat, NN, FF, HD, nullptr, 2,
        0L, (long)FF * HD, (long)NN * HD, al, ar, nullptr);

    edge_kernel<<<(MM * EE + 255) / 256, 256>>>(src, dst);         // 5
    agg_kernel<<<dim3(NN, MM), 128>>>(bg, pW);                     // 6

    // 7: semantic — s[row] += sum tanh(z@W1 + b1) * W2, no C write
    gemm_mma<<<dim3(HIDD / GBN, (MM * NN + GBM - 1) / GBM, 1), 256>>>(
        p_z, sW1, nullptr, MM * NN, HD, HIDD, sb1, 3,
        0L, 0L, 0L, nullptr, nullptr, sW2);

    reduce_kernel<<<dim3(40, MM), 256>>>();                        // 8
    beta_kernel<<<1, 1>>>();                                       // 9
    final_kernel<<<(NN * CC + 255) / 256, 256>>>(pb, out);         // 10
}

// round 9
// speedup vs baseline: 3.4728x; 1.0788x over previous
#include <cuda_runtime.h>
#include <cuda_bf16.h>
#include <cuda_fp16.h>
#include <math.h>
#include <stdint.h>

#define NN 20000
#define FF 256
#define HH 8
#define DD 64
#define HD 512
#define MM 2
#define EE 320000
#define CC 5
#define HIDD 128

// ---------------- scratch (device globals; no allocation) ----------------
__device__ __half g_h16[NN * FF];           // h in fp16
__device__ __half g_Wt16[MM * HD * FF];     // W transposed [m][n][k] fp16
__device__ __half g_sW1t16[HIDD * HD];      // sem_W1 transposed [n][k] fp16
__device__ __half g_feat[MM * NN * HD];     // projected features (fp16)
__device__ __half g_z[MM * NN * HD];        // GAT output (fp16)
__device__ float g_el[MM * NN * HH];
__device__ float g_er[MM * NN * HH];
__device__ int   g_hist[MM * NN];
__device__ int   g_rowptr[MM * (NN + 1)];
__device__ int   g_cursor[MM * NN];
__device__ int   g_src_s[MM * EE];
__device__ __half g_ex_s[MM * EE * HH];     // exp values (fp16)
__device__ float g_s[MM * NN];
__device__ float g_y[MM * NN * CC];
__device__ float g_sum[MM];
__device__ float g_beta[MM];

__device__ __forceinline__ uint32_t f2h2(float a, float b) {
    __half2 h = __floats2half2_rn(a, b);
    return *(uint32_t*)&h;
}

// ---------------- zero init: hist, s, sum ----------------
__global__ void zero_kernel() {
    int i = blockIdx.x * blockDim.x + threadIdx.x;
    int total = MM * NN + MM * NN + MM;
    for (; i < total; i += gridDim.x * blockDim.x) {
        if (i < MM * NN) g_hist[i] = 0;
        else if (i < 2 * MM * NN) g_s[i - MM * NN] = 0.0f;
        else g_sum[i - 2 * MM * NN] = 0.0f;
    }
}

// ---------------- pre-convert: h -> fp16, W^T -> fp16, sW1^T -> fp16 -------
__global__ void cvt_kernel(const float* __restrict__ h, const float* __restrict__ W,
                           const float* __restrict__ sW1) {
    int stride = gridDim.x * blockDim.x;
    int t0 = blockIdx.x * blockDim.x + threadIdx.x;
    // h: vectorized
    for (int i = t0; i < NN * FF / 4; i += stride) {
        float4 v = ((const float4*)h)[i];
        ((uint2*)g_h16)[i] = make_uint2(f2h2(v.x, v.y), f2h2(v.z, v.w));
    }
    // W transpose: Wt[m][n][k] = W[m][k][n]
    for (int i = t0; i < MM * HD * FF; i += stride) {
        int m = i / (HD * FF);
        int r = i % (HD * FF);
        int n = r / FF;
        int k = r % FF;
        g_Wt16[i] = __float2half(W[((size_t)m * FF + k) * HD + n]);
    }
    // sW1 transpose: sW1t[n][k] = sW1[k][n]
    for (int i = t0; i < HIDD * HD; i += stride) {
        int n = i / HD;
        int k = i % HD;
        g_sW1t16[i] = __float2half(sW1[(size_t)k * HIDD + n]);
    }
}

// ---------------- in-degree histogram ----------------
__global__ void hist_kernel(const int* __restrict__ dst) {
    int tid = blockIdx.x * blockDim.x + threadIdx.x;
    if (tid >= MM * EE) return;
    int m = tid / EE;
    atomicAdd(&g_hist[m * NN + dst[tid]], 1);
}

// ---------------- single-block exclusive scan per metapath ----------------
__global__ void scan_kernel() {
    int m = blockIdx.x;
    __shared__ int part[1024];
    int t = threadIdx.x;
    const int CH = 20;
    int base = t * CH;
    int local[CH];
    int s = 0;
#pragma unroll
    for (int i = 0; i < CH; i++) {
        int idx = base + i;
        int v = (idx < NN) ? g_hist[m * NN + idx] : 0;
        local[i] = v;
        s += v;
    }
    part[t] = s;
    __syncthreads();
    for (int off = 1; off < 1024; off <<= 1) {
        int v = (t >= off) ? part[t - off] : 0;
        __syncthreads();
        part[t] += v;
        __syncthreads();
    }
    int run = part[t] - s;
#pragma unroll
    for (int i = 0; i < CH; i++) {
        int idx = base + i;
        if (idx < NN) {
            g_rowptr[m * (NN + 1) + idx] = run;
            g_cursor[m * NN + idx] = run;
            run += local[i];
        }
    }
    if (t == 1023) g_rowptr[m * (NN + 1) + NN] = run;
}

// ---------------- FP16 MMA GEMM, half inputs (A row-major, B^T row-major) --
// mode 2: write C (half) + fused el/er;  mode 3: no C write, s[row] atomics
#define GBM 128
#define GBN 128
#define GBK 16
#define SMSH 24   // smem row stride in halfs (16 + 8 pad) = 48B

#define LDSM4(r, addr)                                                          \
    asm volatile("ldmatrix.sync.aligned.m8n8.x4.shared.b16 {%0,%1,%2,%3}, [%4];" \
                 : "=r"((r)[0]), "=r"((r)[1]), "=r"((r)[2]), "=r"((r)[3])        \
                 : "r"(addr))

__device__ __forceinline__ void mma_f16(float4& d,
                                        uint32_t a0, uint32_t a1, uint32_t a2, uint32_t a3,
                                        uint32_t b0, uint32_t b1) {
    asm volatile("mma.sync.aligned.m16n8k16.row.col.f32.f16.f16.f32 "
                 "{%0,%1,%2,%3}, {%4,%5,%6,%7}, {%8,%9}, {%0,%1,%2,%3};"
                 : "+f"(d.x), "+f"(d.y), "+f"(d.z), "+f"(d.w)
                 : "r"(a0), "r"(a1), "r"(a2), "r"(a3), "r"(b0), "r"(b1));
}

__global__ __launch_bounds__(256) void gemm_mma(
    const __half* __restrict__ A, const __half* __restrict__ Bt, __half* __restrict__ C,
    int Mrows, int K, int Ncols, const float* __restrict__ bias, int mode,
    long aStride, long bStride, long cStride,
    const float* __restrict__ attl, const float* __restrict__ attr,
    const float* __restrict__ w2) {
    int bz = blockIdx.z;
    A += (size_t)bz * aStride;
    Bt += (size_t)bz * bStride;
    C += (size_t)bz * cStride;

    __shared__ __align__(16) __half As[GBM * SMSH];   // [row][k]
    __shared__ __align__(16) __half Bs[GBN * SMSH];   // [n][k]

    int tid = threadIdx.x;
    int warp = tid >> 5;
    int lane = tid & 31;
    int warpM = warp >> 1;     // 0..3
    int warpN = warp & 1;      // 0..1
    int group = lane >> 2;
    int tig = lane & 3;

    int rowBase = blockIdx.y * GBM;
    int colBase = blockIdx.x * GBN;

    int aRow = tid >> 1;
    int aCol = (tid & 1) * 8;
    int bN = tid & 127;
    int bK = (tid >> 7) * 8;

    uint32_t AsU = (uint32_t)__cvta_generic_to_shared(As);
    uint32_t BsU = (uint32_t)__cvta_generic_to_shared(Bs);
    uint32_t aPtr = AsU + (uint32_t)(((warpM * 32 + (lane & 15)) * SMSH) * 2 + (lane >> 4) * 16);
    uint32_t bPtr = BsU + (uint32_t)(((warpN * 64 + (lane >> 4) * 8 + (lane & 7)) * SMSH) * 2
                                     + (((lane >> 3) & 1) * 16));

    float4 acc[2][8];
#pragma unroll
    for (int i = 0; i < 2; i++)
#pragma unroll
        for (int j = 0; j < 8; j++) acc[i][j] = make_float4(0.f, 0.f, 0.f, 0.f);

    uint4 aReg, bReg;

    int gaRow = rowBase + aRow;
    bool aValid = gaRow < Mrows;

    // preload tile 0
    {
        aReg = aValid ? *(const uint4*)(A + (size_t)gaRow * K + aCol)
                      : make_uint4(0, 0, 0, 0);
        bReg = *(const uint4*)(Bt + (size_t)(colBase + bN) * K + bK);
    }

    for (int k0 = 0; k0 < K; k0 += GBK) {
        *(uint4*)&As[aRow * SMSH + aCol] = aReg;
        *(uint4*)&Bs[bN * SMSH + bK] = bReg;
        __syncthreads();

        if (k0 + GBK < K) {
            if (aValid) aReg = *(const uint4*)(A + (size_t)gaRow * K + (k0 + GBK) + aCol);
            bReg = *(const uint4*)(Bt + (size_t)(colBase + bN) * K + (k0 + GBK) + bK);
        }

        {
            uint32_t af[2][4];
            LDSM4(af[0], aPtr);
            LDSM4(af[1], aPtr + 16 * SMSH * 2);
            uint32_t bfr[4][4];
#pragma unroll
            for (int p = 0; p < 4; p++) LDSM4(bfr[p], bPtr + p * 16 * SMSH * 2);
#pragma unroll
            for (int mt = 0; mt < 2; mt++)
#pragma unroll
                for (int nt = 0; nt < 8; nt++)
                    mma_f16(acc[mt][nt], af[mt][0], af[mt][1], af[mt][2], af[mt][3],
                            bfr[nt >> 1][(nt & 1) * 2], bfr[nt >> 1][(nt & 1) * 2 + 1]);
        }
        __syncthreads();
    }

    if (mode == 2) {
        int head = blockIdx.x * 2 + warpN;
        const float* alp = attl + (bz * HH + head) * DD;
        const float* arp = attr + (bz * HH + head) * DD;
        float sl[2][2] = {{0.f, 0.f}, {0.f, 0.f}};
        float sr[2][2] = {{0.f, 0.f}, {0.f, 0.f}};
#pragma unroll
        for (int mt = 0; mt < 2; mt++) {
            int row0 = rowBase + warpM * 32 + mt * 16 + group;
            int row1 = row0 + 8;
#pragma unroll
            for (int nt = 0; nt < 8; nt++) {
                int cl = nt * 8 + 2 * tig;
                float4 v = acc[mt][nt];
                float a0 = alp[cl], a1 = alp[cl + 1];
                float r0 = arp[cl], r1 = arp[cl + 1];
                sl[mt][0] += v.x * a0 + v.y * a1;
                sl[mt][1] += v.z * a0 + v.w * a1;
                sr[mt][0] += v.x * r0 + v.y * r1;
                sr[mt][1] += v.z * r0 + v.w * r1;
                int col = colBase + warpN * 64 + cl;
                if (row0 < Mrows) *(uint32_t*)(C + (size_t)row0 * Ncols + col) = f2h2(v.x, v.y);
                if (row1 < Mrows) *(uint32_t*)(C + (size_t)row1 * Ncols + col) = f2h2(v.z, v.w);
            }
        }
#pragma unroll
        for (int mt = 0; mt < 2; mt++)
#pragma unroll
            for (int r = 0; r < 2; r++) {
                sl[mt][r] += __shfl_xor_sync(0xffffffffu, sl[mt][r], 1);
                sl[mt][r] += __shfl_xor_sync(0xffffffffu, sl[mt][r], 2);
                sr[mt][r] += __shfl_xor_sync(0xffffffffu, sr[mt][r], 1);
                sr[mt][r] += __shfl_xor_sync(0xffffffffu, sr[mt][r], 2);
            }
        if (tig == 0) {
#pragma unroll
            for (int mt = 0; mt < 2; mt++) {
                int row0 = rowBase + warpM * 32 + mt * 16 + group;
                int row1 = row0 + 8;
                if (row0 < Mrows) {
                    g_el[(bz * NN + row0) * HH + head] = sl[mt][0];
                    g_er[(bz * NN + row0) * HH + head] = sr[mt][0];
                }
                if (row1 < Mrows) {
                    g_el[(bz * NN + row1) * HH + head] = sl[mt][1];
                    g_er[(bz * NN + row1) * HH + head] = sr[mt][1];
                }
            }
        }
    } else {
        float sp[2][2] = {{0.f, 0.f}, {0.f, 0.f}};
#pragma unroll
        for (int mt = 0; mt < 2; mt++) {
#pragma unroll
            for (int nt = 0; nt < 8; nt++) {
                int col = colBase + warpN * 64 + nt * 8 + 2 * tig;
                float b0 = bias[col], b1 = bias[col + 1];
                float w0 = w2[col], w1 = w2[col + 1];
                float4 v = acc[mt][nt];
                sp[mt][0] += tanhf(v.x + b0) * w0 + tanhf(v.y + b1) * w1;
                sp[mt][1] += tanhf(v.z + b0) * w0 + tanhf(v.w + b1) * w1;
            }
        }
#pragma unroll
        for (int mt = 0; mt < 2; mt++)
#pragma unroll
            for (int r = 0; r < 2; r++) {
                sp[mt][r] += __shfl_xor_sync(0xffffffffu, sp[mt][r], 1);
                sp[mt][r] += __shfl_xor_sync(0xffffffffu, sp[mt][r], 2);
            }
        if (tig == 0) {
#pragma unroll
            for (int mt = 0; mt < 2; mt++) {
                int row0 = rowBase + warpM * 32 + mt * 16 + group;
                int row1 = row0 + 8;
                if (row0 < Mrows) atomicAdd(&g_s[row0], sp[mt][0]);
                if (row1 < Mrows) atomicAdd(&g_s[row1], sp[mt][1]);
            }
        }
    }
}

// ---------------- edge pass: exp(leaky(el+er)) + CSR scatter (fp16 ex) ------
__global__ void edge_kernel(const int* __restrict__ src, const int* __restrict__ dst) {
    int tid = blockIdx.x * blockDim.x + threadIdx.x;
    if (tid >= MM * EE) return;
    int m = tid / EE;
    int s = src[tid];
    int d = dst[tid];
    const float4* elp = (const float4*)(g_el + (size_t)(m * NN + s) * HH);
    const float4* erp = (const float4*)(g_er + (size_t)(m * NN + d) * HH);
    float4 e0 = elp[0], e1 = elp[1];
    float4 r0 = erp[0], r1 = erp[1];
    float ex[8];
    float v;
    v = e0.x + r0.x; v = v > 0.f ? v : 0.2f * v; ex[0] = expf(v);
    v = e0.y + r0.y; v = v > 0.f ? v : 0.2f * v; ex[1] = expf(v);
    v = e0.z + r0.z; v = v > 0.f ? v : 0.2f * v; ex[2] = expf(v);
    v = e0.w + r0.w; v = v > 0.f ? v : 0.2f * v; ex[3] = expf(v);
    v = e1.x + r1.x; v = v > 0.f ? v : 0.2f * v; ex[4] = expf(v);
    v = e1.y + r1.y; v = v > 0.f ? v : 0.2f * v; ex[5] = expf(v);
    v = e1.z + r1.z; v = v > 0.f ? v : 0.2f * v; ex[6] = expf(v);
    v = e1.w + r1.w; v = v > 0.f ? v : 0.2f * v; ex[7] = expf(v);

    int pos = atomicAdd(&g_cursor[m * NN + d], 1);
    int gp = m * EE + pos;
    g_src_s[gp] = s;
    *(uint4*)(g_ex_s + (size_t)gp * HH) =
        make_uint4(f2h2(ex[0], ex[1]), f2h2(ex[2], ex[3]),
                   f2h2(ex[4], ex[5]), f2h2(ex[6], ex[7]));
}

// ---------------- aggregation + fused per-metapath classifier ----------------
__global__ void agg_kernel(const float* __restrict__ bg, const float* __restrict__ pW) {
    int n = blockIdx.x;
    int m = blockIdx.y;
    int t = threadIdx.x;           // 0..127, owns dims [4t, 4t+4)
    int h = t >> 4;
    int beg = g_rowptr[m * (NN + 1) + n];
    int end = g_rowptr[m * (NN + 1) + n + 1];
    float ax = 0.f, ay = 0.f, az = 0.f, aw = 0.f;
    float dsum = 0.f;
    for (int j = beg; j < end; j++) {
        int gp = m * EE + j;
        int s = g_src_s[gp];
        float exv = __half2float(g_ex_s[(size_t)gp * HH + h]);
        dsum += exv;
        uint2 fv = *(const uint2*)(g_feat + ((size_t)(m * NN + s)) * HD + t * 4);
        float2 f01 = __half22float2(*(__half2*)&fv.x);
        float2 f23 = __half22float2(*(__half2*)&fv.y);
        ax += exv * f01.x; ay += exv * f01.y; az += exv * f23.x; aw += exv * f23.y;
    }
    float inv = 1.0f / fmaxf(dsum, 1e-9f);
    const float* bp = bg + m * HD + t * 4;
    float o0 = ax * inv + bp[0], o1 = ay * inv + bp[1];
    float o2 = az * inv + bp[2], o3 = aw * inv + bp[3];
    o0 = o0 > 0.f ? o0 : expf(o0) - 1.0f;
    o1 = o1 > 0.f ? o1 : expf(o1) - 1.0f;
    o2 = o2 > 0.f ? o2 : expf(o2) - 1.0f;
    o3 = o3 > 0.f ? o3 : expf(o3) - 1.0f;
    *(uint2*)(g_z + ((size_t)(m * NN + n)) * HD + t * 4) =
        make_uint2(f2h2(o0, o1), f2h2(o2, o3));

    // fused y[m,n,c] = z_row . pred_W[:,c]   (uses fp32 o values)
    const float* w = pW + (size_t)t * 4 * CC;
    float yc[CC];
#pragma unroll
    for (int c = 0; c < CC; c++)
        yc[c] = o0 * w[c] + o1 * w[CC + c] + o2 * w[2 * CC + c] + o3 * w[3 * CC + c];
#pragma unroll
    for (int c = 0; c < CC; c++)
#pragma unroll
        for (int off = 16; off > 0; off >>= 1)
            yc[c] += __shfl_down_sync(0xffffffffu, yc[c], off);
    __shared__ float ysh[4][CC];
    int warp = t >> 5, lane = t & 31;
    if (lane == 0)
#pragma unroll
        for (int c = 0; c < CC; c++) ysh[warp][c] = yc[c];
    __syncthreads();
    if (t < CC) {
        float v = ysh[0][t] + ysh[1][t] + ysh[2][t] + ysh[3][t];
        g_y[((size_t)m * NN + n) * CC + t] = v;
    }
}

// ---------------- mean over nodes per metapath ----------------
__global__ void reduce_kernel() {
    int m = blockIdx.y;
    int t = threadIdx.x;
    float s = 0.f;
    for (int i = blockIdx.x * blockDim.x + t; i < NN; i += gridDim.x * blockDim.x)
        s += g_s[m * NN + i];
    __shared__ float sh[256];
    sh[t] = s;
    __syncthreads();
    for (int off = 128; off > 0; off >>= 1) {
        if (t < off) sh[t] += sh[t + off];
        __syncthreads();
    }
    if (t == 0) atomicAdd(&g_sum[m], sh[0]);
}

__global__ void beta_kernel() {
    float a = g_sum[0] / (float)NN;
    float b = g_sum[1] / (float)NN;
    float mx = fmaxf(a, b);
    float e0 = expf(a - mx), e1 = expf(b - mx);
    float inv = 1.0f / (e0 + e1);
    g_beta[0] = e0 * inv;
    g_beta[1] = e1 * inv;
}

// ---------------- tiny final: out = b0*y0 + b1*y1 + pb ----------------
__global__ void final_kernel(const float* __restrict__ pb, float* __restrict__ out) {
    int tid = blockIdx.x * blockDim.x + threadIdx.x;
    if (tid >= NN * CC) return;
    int c = tid % CC;
    float b0 = g_beta[0], b1 = g_beta[1];
    out[tid] = b0 * g_y[tid] + b1 * g_y[NN * CC + tid] + pb[c];
}

// ---------------- launch ----------------
extern "C" void kernel_launch(void* const* d_in, const int* in_sizes, int n_in,
                              void* d_out, int out_size) {
    const float* h    = (const float*)d_in[0];
    const int*   src  = (const int*)d_in[1];
    const int*   dst  = (const int*)d_in[2];
    const float* W    = (const float*)d_in[3];
    const float* al   = (const float*)d_in[4];
    const float* ar   = (const float*)d_in[5];
    const float* bg   = (const float*)d_in[6];
    const float* sW1  = (const float*)d_in[7];
    const float* sb1  = (const float*)d_in[8];
    const float* sW2  = (const float*)d_in[9];
    const float* pW   = (const float*)d_in[10];
    const float* pb   = (const float*)d_in[11];
    float* out = (float*)d_out;

    __half *p_h16, *p_Wt16, *p_sW1t16, *p_feat, *p_z;
    cudaGetSymbolAddress((void**)&p_h16, g_h16);
    cudaGetSymbolAddress((void**)&p_Wt16, g_Wt16);
    cudaGetSymbolAddress((void**)&p_sW1t16, g_sW1t16);
    cudaGetSymbolAddress((void**)&p_feat, g_feat);
    cudaGetSymbolAddress((void**)&p_z, g_z);

    zero_kernel<<<313, 256>>>();                                   // 1
    cvt_kernel<<<304, 256>>>(h, W, sW1);                           // 2
    hist_kernel<<<(MM * EE + 255) / 256, 256>>>(dst);              // 3
    scan_kernel<<<MM, 1024>>>();                                   // 4

    // 5: feat[m] = h @ W[m], fused el/er epilogue (2 heads per CTA)
    gemm_mma<<<dim3(HD / GBN, (NN + GBM - 1) / GBM, MM), 256>>>(
        p_h16, p_Wt16, p_feat, NN, FF, HD, nullptr, 2,
        0L, (long)HD * FF, (long)NN * HD, al, ar, nullptr);

    edge_kernel<<<(MM * EE + 255) / 256, 256>>>(src, dst);         // 6
    agg_kernel<<<dim3(NN, MM), 128>>>(bg, pW);                     // 7

    // 8: semantic — s[row] += sum tanh(z@W1 + b1) * W2, no C write
    gemm_mma<<<dim3(HIDD / GBN, (MM * NN + GBM - 1) / GBM, 1), 256>>>(
        p_z, p_sW1t16, nullptr, MM * NN, HD, HIDD, sb1, 3,
        0L, 0L, 0L, nullptr, nullptr, sW2);

    reduce_kernel<<<dim3(40, MM), 256>>>();                        // 9
    beta_kernel<<<1, 1>>>();                                       // 10
    final_kernel<<<(NN * CC + 255) / 256, 256>>>(pb, out);         // 11
}

// round 10
// speedup vs baseline: 3.6821x; 1.0603x over previous
#include <cuda_runtime.h>
#include <cuda_bf16.h>
#include <cuda_fp16.h>
#include <math.h>
#include <stdint.h>

#define NN 20000
#define FF 256
#define HH 8
#define DD 64
#define HD 512
#define MM 2
#define EE 320000
#define CC 5
#define HIDD 128
#define SB 40          // scan blocks per metapath (40*512 >= NN)

// ---------------- scratch (device globals; no allocation) ----------------
__device__ __half g_h16[NN * FF];
__device__ __half g_Wt16[MM * HD * FF];
__device__ __half g_sW1t16[HIDD * HD];
__device__ __half g_feat[MM * NN * HD];
__device__ __half g_z[MM * NN * HD];
__device__ float g_el[MM * NN * HH];
__device__ float g_er[MM * NN * HH];
__device__ int   g_hist[MM * NN];
__device__ int   g_rowptr[MM * (NN + 1)];
__device__ int   g_cursor[MM * NN];
__device__ int   g_bsum[MM * SB];
__device__ int   g_src_s[MM * EE];
__device__ __half g_ex_s[MM * EE * HH];
__device__ float g_s[MM * NN];
__device__ float g_y[MM * NN * CC];
__device__ float g_sum[MM];
__device__ float g_beta[MM];

__device__ __forceinline__ uint32_t f2h2(float a, float b) {
    __half2 h = __floats2half2_rn(a, b);
    return *(uint32_t*)&h;
}

// ---------------- prep: zero hist/s/sum + fp16 conversions ----------------
__global__ void prep_kernel(const float* __restrict__ h, const float* __restrict__ W,
                            const float* __restrict__ sW1) {
    int stride = gridDim.x * blockDim.x;
    int t0 = blockIdx.x * blockDim.x + threadIdx.x;
    for (int i = t0; i < MM * NN; i += stride) {
        g_hist[i] = 0;
        g_s[i] = 0.0f;
    }
    if (t0 < MM) g_sum[t0] = 0.0f;
    for (int i = t0; i < NN * FF / 4; i += stride) {
        float4 v = ((const float4*)h)[i];
        ((uint2*)g_h16)[i] = make_uint2(f2h2(v.x, v.y), f2h2(v.z, v.w));
    }
    for (int i = t0; i < MM * HD * FF; i += stride) {
        int m = i / (HD * FF);
        int r = i % (HD * FF);
        int n = r / FF;
        int k = r % FF;
        g_Wt16[i] = __float2half(W[((size_t)m * FF + k) * HD + n]);
    }
    for (int i = t0; i < HIDD * HD; i += stride) {
        int n = i / HD;
        int k = i % HD;
        g_sW1t16[i] = __float2half(sW1[(size_t)k * HIDD + n]);
    }
}

// ---------------- in-degree histogram ----------------
__global__ void hist_kernel(const int* __restrict__ dst) {
    int tid = blockIdx.x * blockDim.x + threadIdx.x;
    if (tid >= MM * EE) return;
    int m = tid / EE;
    atomicAdd(&g_hist[m * NN + dst[tid]], 1);
}

// ---------------- hierarchical scan: pass 1 (block-local) ----------------
__global__ void scan1_kernel() {
    int m = blockIdx.y, b = blockIdx.x, t = threadIdx.x;
    int idx = b * 512 + t;
    int v = (idx < NN) ? g_hist[m * NN + idx] : 0;
    __shared__ int sh[512];
    sh[t] = v;
    __syncthreads();
    for (int off = 1; off < 512; off <<= 1) {
        int x = (t >= off) ? sh[t - off] : 0;
        __syncthreads();
        sh[t] += x;
        __syncthreads();
    }
    int incl = sh[t];
    if (idx < NN) g_rowptr[m * (NN + 1) + idx] = incl - v;   // block-local exclusive
    if (t == 511) g_bsum[m * SB + b] = incl;                 // block total
}

// ---------------- hierarchical scan: pass 2 (apply offsets) ----------------
__global__ void scan2_kernel() {
    int m = blockIdx.y, b = blockIdx.x, t = threadIdx.x;
    __shared__ int off;
    if (t == 0) {
        int s = 0;
        for (int i = 0; i < b; i++) s += g_bsum[m * SB + i];
        off = s;
    }
    __syncthreads();
    int idx = b * 512 + t;
    if (idx < NN) {
        int r = g_rowptr[m * (NN + 1) + idx] + off;
        g_rowptr[m * (NN + 1) + idx] = r;
        g_cursor[m * NN + idx] = r;
    }
    if (b == 0 && t == 0) g_rowptr[m * (NN + 1) + NN] = EE;  // total is exact
}

// ---------------- FP16 MMA GEMM, double-buffered smem ----------------------
// mode 2: write C (half) + fused el/er;  mode 3: no C write, s[row] atomics
#define GBM 128
#define GBN 128
#define GBK 16
#define SMSH 24   // smem row stride in halfs (16 + 8 pad) = 48B
#define ASTG (GBM * SMSH * 2)   // bytes per A stage
#define BSTG (GBN * SMSH * 2)   // bytes per B stage

#define LDSM4(r, addr)                                                          \
    asm volatile("ldmatrix.sync.aligned.m8n8.x4.shared.b16 {%0,%1,%2,%3}, [%4];" \
                 : "=r"((r)[0]), "=r"((r)[1]), "=r"((r)[2]), "=r"((r)[3])        \
                 : "r"(addr))

__device__ __forceinline__ void mma_f16(float4& d,
                                        uint32_t a0, uint32_t a1, uint32_t a2, uint32_t a3,
                                        uint32_t b0, uint32_t b1) {
    asm volatile("mma.sync.aligned.m16n8k16.row.col.f32.f16.f16.f32 "
                 "{%0,%1,%2,%3}, {%4,%5,%6,%7}, {%8,%9}, {%0,%1,%2,%3};"
                 : "+f"(d.x), "+f"(d.y), "+f"(d.z), "+f"(d.w)
                 : "r"(a0), "r"(a1), "r"(a2), "r"(a3), "r"(b0), "r"(b1));
}

__global__ __launch_bounds__(256) void gemm_mma(
    const __half* __restrict__ A, const __half* __restrict__ Bt, __half* __restrict__ C,
    int Mrows, int K, int Ncols, const float* __restrict__ bias, int mode,
    long aStride, long bStride, long cStride,
    const float* __restrict__ attl, const float* __restrict__ attr,
    const float* __restrict__ w2) {
    int bz = blockIdx.z;
    A += (size_t)bz * aStride;
    Bt += (size_t)bz * bStride;
    C += (size_t)bz * cStride;

    __shared__ __align__(16) __half As[2][GBM * SMSH];
    __shared__ __align__(16) __half Bs[2][GBN * SMSH];

    int tid = threadIdx.x;
    int warp = tid >> 5;
    int lane = tid & 31;
    int warpM = warp >> 1;
    int warpN = warp & 1;
    int group = lane >> 2;
    int tig = lane & 3;

    int rowBase = blockIdx.y * GBM;
    int colBase = blockIdx.x * GBN;

    int aRow = tid >> 1;
    int aCol = (tid & 1) * 8;
    int bN = tid & 127;
    int bK = (tid >> 7) * 8;

    uint32_t AsU = (uint32_t)__cvta_generic_to_shared(&As[0][0]);
    uint32_t BsU = (uint32_t)__cvta_generic_to_shared(&Bs[0][0]);
    uint32_t aPtr = AsU + (uint32_t)(((warpM * 32 + (lane & 15)) * SMSH) * 2 + (lane >> 4) * 16);
    uint32_t bPtr = BsU + (uint32_t)(((warpN * 64 + (lane >> 4) * 8 + (lane & 7)) * SMSH) * 2
                                     + (((lane >> 3) & 1) * 16));

    float4 acc[2][8];
#pragma unroll
    for (int i = 0; i < 2; i++)
#pragma unroll
        for (int j = 0; j < 8; j++) acc[i][j] = make_float4(0.f, 0.f, 0.f, 0.f);

    uint4 aReg, bReg;

    int gaRow = rowBase + aRow;
    bool aValid = gaRow < Mrows;

    aReg = aValid ? *(const uint4*)(A + (size_t)gaRow * K + aCol) : make_uint4(0, 0, 0, 0);
    bReg = *(const uint4*)(Bt + (size_t)(colBase + bN) * K + bK);
    *(uint4*)&As[0][aRow * SMSH + aCol] = aReg;
    *(uint4*)&Bs[0][bN * SMSH + bK] = bReg;
    __syncthreads();

    int niter = K / GBK;
    for (int i = 0; i < niter; i++) {
        int s = i & 1;
        bool more = (i + 1 < niter);
        if (more) {
            int k0 = (i + 1) * GBK;
            if (aValid) aReg = *(const uint4*)(A + (size_t)gaRow * K + k0 + aCol);
            bReg = *(const uint4*)(Bt + (size_t)(colBase + bN) * K + k0 + bK);
        }
        {
            uint32_t aP = aPtr + s * ASTG;
            uint32_t bP = bPtr + s * BSTG;
            uint32_t af[2][4];
            LDSM4(af[0], aP);
            LDSM4(af[1], aP + 16 * SMSH * 2);
            uint32_t bfr[4][4];
#pragma unroll
            for (int p = 0; p < 4; p++) LDSM4(bfr[p], bP + p * 16 * SMSH * 2);
#pragma unroll
            for (int mt = 0; mt < 2; mt++)
#pragma unroll
                for (int nt = 0; nt < 8; nt++)
                    mma_f16(acc[mt][nt], af[mt][0], af[mt][1], af[mt][2], af[mt][3],
                            bfr[nt >> 1][(nt & 1) * 2], bfr[nt >> 1][(nt & 1) * 2 + 1]);
        }
        if (more) {
            *(uint4*)&As[s ^ 1][aRow * SMSH + aCol] = aReg;
            *(uint4*)&Bs[s ^ 1][bN * SMSH + bK] = bReg;
            __syncthreads();
        }
    }

    if (mode == 2) {
        int head = blockIdx.x * 2 + warpN;
        const float* alp = attl + (bz * HH + head) * DD;
        const float* arp = attr + (bz * HH + head) * DD;
        float sl[2][2] = {{0.f, 0.f}, {0.f, 0.f}};
        float sr[2][2] = {{0.f, 0.f}, {0.f, 0.f}};
#pragma unroll
        for (int mt = 0; mt < 2; mt++) {
            int row0 = rowBase + warpM * 32 + mt * 16 + group;
            int row1 = row0 + 8;
#pragma unroll
            for (int nt = 0; nt < 8; nt++) {
                int cl = nt * 8 + 2 * tig;
                float4 v = acc[mt][nt];
                float a0 = alp[cl], a1 = alp[cl + 1];
                float r0 = arp[cl], r1 = arp[cl + 1];
                sl[mt][0] += v.x * a0 + v.y * a1;
                sl[mt][1] += v.z * a0 + v.w * a1;
                sr[mt][0] += v.x * r0 + v.y * r1;
                sr[mt][1] += v.z * r0 + v.w * r1;
                int col = colBase + warpN * 64 + cl;
                if (row0 < Mrows) *(uint32_t*)(C + (size_t)row0 * Ncols + col) = f2h2(v.x, v.y);
                if (row1 < Mrows) *(uint32_t*)(C + (size_t)row1 * Ncols + col) = f2h2(v.z, v.w);
            }
        }
#pragma unroll
        for (int mt = 0; mt < 2; mt++)
#pragma unroll
            for (int r = 0; r < 2; r++) {
                sl[mt][r] += __shfl_xor_sync(0xffffffffu, sl[mt][r], 1);
                sl[mt][r] += __shfl_xor_sync(0xffffffffu, sl[mt][r], 2);
                sr[mt][r] += __shfl_xor_sync(0xffffffffu, sr[mt][r], 1);
                sr[mt][r] += __shfl_xor_sync(0xffffffffu, sr[mt][r], 2);
            }
        if (tig == 0) {
#pragma unroll
            for (int mt = 0; mt < 2; mt++) {
                int row0 = rowBase + warpM * 32 + mt * 16 + group;
                int row1 = row0 + 8;
                if (row0 < Mrows) {
                    g_el[(bz * NN + row0) * HH + head] = sl[mt][0];
                    g_er[(bz * NN + row0) * HH + head] = sr[mt][0];
                }
                if (row1 < Mrows) {
                    g_el[(bz * NN + row1) * HH + head] = sl[mt][1];
                    g_er[(bz * NN + row1) * HH + head] = sr[mt][1];
                }
            }
        }
    } else {
        float sp[2][2] = {{0.f, 0.f}, {0.f, 0.f}};
#pragma unroll
        for (int mt = 0; mt < 2; mt++) {
#pragma unroll
            for (int nt = 0; nt < 8; nt++) {
                int col = colBase + warpN * 64 + nt * 8 + 2 * tig;
                float b0 = bias[col], b1 = bias[col + 1];
                float w0 = w2[col], w1 = w2[col + 1];
                float4 v = acc[mt][nt];
                sp[mt][0] += tanhf(v.x + b0) * w0 + tanhf(v.y + b1) * w1;
                sp[mt][1] += tanhf(v.z + b0) * w0 + tanhf(v.w + b1) * w1;
            }
        }
#pragma unroll
        for (int mt = 0; mt < 2; mt++)
#pragma unroll
            for (int r = 0; r < 2; r++) {
                sp[mt][r] += __shfl_xor_sync(0xffffffffu, sp[mt][r], 1);
                sp[mt][r] += __shfl_xor_sync(0xffffffffu, sp[mt][r], 2);
            }
        if (tig == 0) {
#pragma unroll
            for (int mt = 0; mt < 2; mt++) {
                int row0 = rowBase + warpM * 32 + mt * 16 + group;
                int row1 = row0 + 8;
                if (row0 < Mrows) atomicAdd(&g_s[row0], sp[mt][0]);
                if (row1 < Mrows) atomicAdd(&g_s[row1], sp[mt][1]);
            }
        }
    }
}

// ---------------- edge pass: exp(leaky(el+er)) + CSR scatter (fp16 ex) ------
__global__ void edge_kernel(const int* __restrict__ src, const int* __restrict__ dst) {
    int tid = blockIdx.x * blockDim.x + threadIdx.x;
    if (tid >= MM * EE) return;
    int m = tid / EE;
    int s = src[tid];
    int d = dst[tid];
    const float4* elp = (const float4*)(g_el + (size_t)(m * NN + s) * HH);
    const float4* erp = (const float4*)(g_er + (size_t)(m * NN + d) * HH);
    float4 e0 = elp[0], e1 = elp[1];
    float4 r0 = erp[0], r1 = erp[1];
    float ex[8];
    float v;
    v = e0.x + r0.x; v = v > 0.f ? v : 0.2f * v; ex[0] = expf(v);
    v = e0.y + r0.y; v = v > 0.f ? v : 0.2f * v; ex[1] = expf(v);
    v = e0.z + r0.z; v = v > 0.f ? v : 0.2f * v; ex[2] = expf(v);
    v = e0.w + r0.w; v = v > 0.f ? v : 0.2f * v; ex[3] = expf(v);
    v = e1.x + r1.x; v = v > 0.f ? v : 0.2f * v; ex[4] = expf(v);
    v = e1.y + r1.y; v = v > 0.f ? v : 0.2f * v; ex[5] = expf(v);
    v = e1.z + r1.z; v = v > 0.f ? v : 0.2f * v; ex[6] = expf(v);
    v = e1.w + r1.w; v = v > 0.f ? v : 0.2f * v; ex[7] = expf(v);

    int pos = atomicAdd(&g_cursor[m * NN + d], 1);
    int gp = m * EE + pos;
    g_src_s[gp] = s;
    *(uint4*)(g_ex_s + (size_t)gp * HH) =
        make_uint4(f2h2(ex[0], ex[1]), f2h2(ex[2], ex[3]),
                   f2h2(ex[4], ex[5]), f2h2(ex[6], ex[7]));
}

// ---------------- aggregation + fused per-metapath classifier ----------------
__global__ void agg_kernel(const float* __restrict__ bg, const float* __restrict__ pW) {
    int n = blockIdx.x;
    int m = blockIdx.y;
    int t = threadIdx.x;           // 0..127, owns dims [4t, 4t+4)
    int h = t >> 4;
    int beg = g_rowptr[m * (NN + 1) + n];
    int end = g_rowptr[m * (NN + 1) + n + 1];
    float ax = 0.f, ay = 0.f, az = 0.f, aw = 0.f;
    float dsum = 0.f;
    for (int j = beg; j < end; j++) {
        int gp = m * EE + j;
        int s = g_src_s[gp];
        float exv = __half2float(g_ex_s[(size_t)gp * HH + h]);
        dsum += exv;
        uint2 fv = *(const uint2*)(g_feat + ((size_t)(m * NN + s)) * HD + t * 4);
        float2 f01 = __half22float2(*(__half2*)&fv.x);
        float2 f23 = __half22float2(*(__half2*)&fv.y);
        ax += exv * f01.x; ay += exv * f01.y; az += exv * f23.x; aw += exv * f23.y;
    }
    float inv = 1.0f / fmaxf(dsum, 1e-9f);
    const float* bp = bg + m * HD + t * 4;
    float o0 = ax * inv + bp[0], o1 = ay * inv + bp[1];
    float o2 = az * inv + bp[2], o3 = aw * inv + bp[3];
    o0 = o0 > 0.f ? o0 : expf(o0) - 1.0f;
    o1 = o1 > 0.f ? o1 : expf(o1) - 1.0f;
    o2 = o2 > 0.f ? o2 : expf(o2) - 1.0f;
    o3 = o3 > 0.f ? o3 : expf(o3) - 1.0f;
    *(uint2*)(g_z + ((size_t)(m * NN + n)) * HD + t * 4) =
        make_uint2(f2h2(o0, o1), f2h2(o2, o3));

    const float* w = pW + (size_t)t * 4 * CC;
    float yc[CC];
#pragma unroll
    for (int c = 0; c < CC; c++)
        yc[c] = o0 * w[c] + o1 * w[CC + c] + o2 * w[2 * CC + c] + o3 * w[3 * CC + c];
#pragma unroll
    for (int c = 0; c < CC; c++)
#pragma unroll
        for (int off = 16; off > 0; off >>= 1)
            yc[c] += __shfl_down_sync(0xffffffffu, yc[c], off);
    __shared__ float ysh[4][CC];
    int warp = t >> 5, lane = t & 31;
    if (lane == 0)
#pragma unroll
        for (int c = 0; c < CC; c++) ysh[warp][c] = yc[c];
    __syncthreads();
    if (t < CC) {
        float v = ysh[0][t] + ysh[1][t] + ysh[2][t] + ysh[3][t];
        g_y[((size_t)m * NN + n) * CC + t] = v;
    }
}

// ---------------- mean over nodes per metapath ----------------
__global__ void reduce_kernel() {
    int m = blockIdx.y;
    int t = threadIdx.x;
    float s = 0.f;
    for (int i = blockIdx.x * blockDim.x + t; i < NN; i += gridDim.x * blockDim.x)
        s += g_s[m * NN + i];
    __shared__ float sh[256];
    sh[t] = s;
    __syncthreads();
    for (int off = 128; off > 0; off >>= 1) {
        if (t < off) sh[t] += sh[t + off];
        __syncthreads();
    }
    if (t == 0) atomicAdd(&g_sum[m], sh[0]);
}

__global__ void beta_kernel() {
    float a = g_sum[0] / (float)NN;
    float b = g_sum[1] / (float)NN;
    float mx = fmaxf(a, b);
    float e0 = expf(a - mx), e1 = expf(b - mx);
    float inv = 1.0f / (e0 + e1);
    g_beta[0] = e0 * inv;
    g_beta[1] = e1 * inv;
}

// ---------------- tiny final: out = b0*y0 + b1*y1 + pb ----------------
__global__ void final_kernel(const float* __restrict__ pb, float* __restrict__ out) {
    int tid = blockIdx.x * blockDim.x + threadIdx.x;
    if (tid >= NN * CC) return;
    int c = tid % CC;
    float b0 = g_beta[0], b1 = g_beta[1];
    out[tid] = b0 * g_y[tid] + b1 * g_y[NN * CC + tid] + pb[c];
}

// ---------------- launch ----------------
extern "C" void kernel_launch(void* const* d_in, const int* in_sizes, int n_in,
                              void* d_out, int out_size) {
    const float* h    = (const float*)d_in[0];
    const int*   src  = (const int*)d_in[1];
    const int*   dst  = (const int*)d_in[2];
    const float* W    = (const float*)d_in[3];
    const float* al   = (const float*)d_in[4];
    const float* ar   = (const float*)d_in[5];
    const float* bg   = (const float*)d_in[6];
    const float* sW1  = (const float*)d_in[7];
    const float* sb1  = (const float*)d_in[8];
    const float* sW2  = (const float*)d_in[9];
    const float* pW   = (const float*)d_in[10];
    const float* pb   = (const float*)d_in[11];
    float* out = (float*)d_out;

    __half *p_h16, *p_Wt16, *p_sW1t16, *p_feat, *p_z;
    cudaGetSymbolAddress((void**)&p_h16, g_h16);
    cudaGetSymbolAddress((void**)&p_Wt16, g_Wt16);
    cudaGetSymbolAddress((void**)&p_sW1t16, g_sW1t16);
    cudaGetSymbolAddress((void**)&p_feat, g_feat);
    cudaGetSymbolAddress((void**)&p_z, g_z);

    prep_kernel<<<400, 256>>>(h, W, sW1);                          // 1
    hist_kernel<<<(MM * EE + 255) / 256, 256>>>(dst);              // 2
    scan1_kernel<<<dim3(SB, MM), 512>>>();                         // 3
    scan2_kernel<<<dim3(SB, MM), 512>>>();                         // 4

    // 5: feat[m] = h @ W[m], fused el/er epilogue (2 heads per CTA)
    gemm_mma<<<dim3(HD / GBN, (NN + GBM - 1) / GBM, MM), 256>>>(
        p_h16, p_Wt16, p_feat, NN, FF, HD, nullptr, 2,
        0L, (long)HD * FF, (long)NN * HD, al, ar, nullptr);

    edge_kernel<<<(MM * EE + 255) / 256, 256>>>(src, dst);         // 6
    agg_kernel<<<dim3(NN, MM), 128>>>(bg, pW);                     // 7

    // 8: semantic — s[row] += sum tanh(z@W1 + b1) * W2, no C write
    gemm_mma<<<dim3(HIDD / GBN, (MM * NN + GBM - 1) / GBM, 1), 256>>>(
        p_z, p_sW1t16, nullptr, MM * NN, HD, HIDD, sb1, 3,
        0L, 0L, 0L, nullptr, nullptr, sW2);

    reduce_kernel<<<dim3(40, MM), 256>>>();                        // 9
    beta_kernel<<<1, 1>>>();                                       // 10
    final_kernel<<<(NN * CC + 255) / 256, 256>>>(pb, out);         // 11
}

// round 11
// speedup vs baseline: 4.2258x; 1.1477x over previous
#include <cuda_runtime.h>
#include <cuda_bf16.h>
#include <cuda_fp16.h>
#include <math.h>
#include <stdint.h>

#define NN 20000
#define FF 256
#define HH 8
#define DD 64
#define HD 512
#define MM 2
#define EE 320000
#define CC 5
#define HIDD 128
#define SB 40          // scan blocks per metapath (40*512 >= NN)

// ---------------- scratch (device globals; no allocation) ----------------
__device__ __half g_h16[NN * FF];
__device__ __half g_Wt16[MM * HD * FF];
__device__ __half g_sW1t16[HIDD * HD];
__device__ __half g_feat[MM * NN * HD];
__device__ __half g_z[MM * NN * HD];
__device__ float g_el[MM * NN * HH];
__device__ float g_er[MM * NN * HH];
__device__ int   g_hist[MM * NN];
__device__ int   g_rowptr[MM * (NN + 1)];
__device__ int   g_cursor[MM * NN];
__device__ int   g_bsum[MM * SB];
__device__ int   g_src_s[MM * EE];
__device__ __half g_ex_s[MM * EE * HH];
__device__ float g_s[MM * NN];
__device__ float g_y[MM * NN * CC];
__device__ float g_sum[MM];
__device__ float g_beta[MM];

__device__ __forceinline__ uint32_t f2h2(float a, float b) {
    __half2 h = __floats2half2_rn(a, b);
    return *(uint32_t*)&h;
}

// ---------------- prep: zero hist/s/sum + fp16 conversions ----------------
__global__ void prep_kernel(const float* __restrict__ h, const float* __restrict__ W,
                            const float* __restrict__ sW1) {
    int stride = gridDim.x * blockDim.x;
    int t0 = blockIdx.x * blockDim.x + threadIdx.x;
    for (int i = t0; i < MM * NN; i += stride) {
        g_hist[i] = 0;
        g_s[i] = 0.0f;
    }
    if (t0 < MM) g_sum[t0] = 0.0f;
    for (int i = t0; i < NN * FF / 4; i += stride) {
        float4 v = ((const float4*)h)[i];
        ((uint2*)g_h16)[i] = make_uint2(f2h2(v.x, v.y), f2h2(v.z, v.w));
    }
    for (int i = t0; i < MM * HD * FF; i += stride) {
        int m = i / (HD * FF);
        int r = i % (HD * FF);
        int n = r / FF;
        int k = r % FF;
        g_Wt16[i] = __float2half(W[((size_t)m * FF + k) * HD + n]);
    }
    for (int i = t0; i < HIDD * HD; i += stride) {
        int n = i / HD;
        int k = i % HD;
        g_sW1t16[i] = __float2half(sW1[(size_t)k * HIDD + n]);
    }
}

// ---------------- in-degree histogram ----------------
__global__ void hist_kernel(const int* __restrict__ dst) {
    int tid = blockIdx.x * blockDim.x + threadIdx.x;
    if (tid >= MM * EE) return;
    int m = tid / EE;
    atomicAdd(&g_hist[m * NN + dst[tid]], 1);
}

// ---------------- hierarchical scan: pass 1 (block-local) ----------------
__global__ void scan1_kernel() {
    int m = blockIdx.y, b = blockIdx.x, t = threadIdx.x;
    int idx = b * 512 + t;
    int v = (idx < NN) ? g_hist[m * NN + idx] : 0;
    __shared__ int sh[512];
    sh[t] = v;
    __syncthreads();
    for (int off = 1; off < 512; off <<= 1) {
        int x = (t >= off) ? sh[t - off] : 0;
        __syncthreads();
        sh[t] += x;
        __syncthreads();
    }
    int incl = sh[t];
    if (idx < NN) g_rowptr[m * (NN + 1) + idx] = incl - v;
    if (t == 511) g_bsum[m * SB + b] = incl;
}

// ---------------- hierarchical scan: pass 2 (apply offsets) ----------------
__global__ void scan2_kernel() {
    int m = blockIdx.y, b = blockIdx.x, t = threadIdx.x;
    __shared__ int off;
    if (t == 0) {
        int s = 0;
        for (int i = 0; i < b; i++) s += g_bsum[m * SB + i];
        off = s;
    }
    __syncthreads();
    int idx = b * 512 + t;
    if (idx < NN) {
        int r = g_rowptr[m * (NN + 1) + idx] + off;
        g_rowptr[m * (NN + 1) + idx] = r;
        g_cursor[m * NN + idx] = r;
    }
    if (b == 0 && t == 0) g_rowptr[m * (NN + 1) + NN] = EE;
}

// ---------------- FP16 MMA GEMM, cp.async 2-stage pipeline, GBK=32 ---------
// mode 2: write C (half) + fused el/er;  mode 3: no C write, s[row] atomics
#define GBM 128
#define GBN 128
#define GBK 32
#define SMSH 40                    // smem row stride in halfs (32 + 8 pad)
#define ASTGB (GBM * SMSH * 2)     // bytes per A stage
#define BSTGB (GBN * SMSH * 2)     // bytes per B stage

#define LDSM4(r, addr)                                                          \
    asm volatile("ldmatrix.sync.aligned.m8n8.x4.shared.b16 {%0,%1,%2,%3}, [%4];" \
                 : "=r"((r)[0]), "=r"((r)[1]), "=r"((r)[2]), "=r"((r)[3])        \
                 : "r"(addr))

#define CP16(dst, src, sz)                                                       \
    asm volatile("cp.async.cg.shared.global [%0], [%1], 16, %2;"                 \
                 :: "r"(dst), "l"(src), "r"(sz))

__device__ __forceinline__ void mma_f16(float4& d,
                                        uint32_t a0, uint32_t a1, uint32_t a2, uint32_t a3,
                                        uint32_t b0, uint32_t b1) {
    asm volatile("mma.sync.aligned.m16n8k16.row.col.f32.f16.f16.f32 "
                 "{%0,%1,%2,%3}, {%4,%5,%6,%7}, {%8,%9}, {%0,%1,%2,%3};"
                 : "+f"(d.x), "+f"(d.y), "+f"(d.z), "+f"(d.w)
                 : "r"(a0), "r"(a1), "r"(a2), "r"(a3), "r"(b0), "r"(b1));
}

__global__ __launch_bounds__(256) void gemm_mma(
    const __half* __restrict__ A, const __half* __restrict__ Bt, __half* __restrict__ C,
    int Mrows, int K, int Ncols, const float* __restrict__ bias, int mode,
    long aStride, long bStride, long cStride,
    const float* __restrict__ attl, const float* __restrict__ attr,
    const float* __restrict__ w2) {
    int bz = blockIdx.z;
    A += (size_t)bz * aStride;
    Bt += (size_t)bz * bStride;
    C += (size_t)bz * cStride;

    __shared__ __align__(16) __half As[2][GBM * SMSH];
    __shared__ __align__(16) __half Bs[2][GBN * SMSH];

    int tid = threadIdx.x;
    int warp = tid >> 5;
    int lane = tid & 31;
    int warpM = warp >> 1;
    int warpN = warp & 1;
    int group = lane >> 2;
    int tig = lane & 3;

    int rowBase = blockIdx.y * GBM;
    int colBase = blockIdx.x * GBN;

    // copy mapping: 2 threads per row, each thread 32B (2x 16B cp.async)
    int cRow = tid >> 1;            // 0..127
    int cHalf = (tid & 1) * 16;     // half offset 0 or 16

    int gaRow = rowBase + cRow;
    uint32_t aSz = (gaRow < Mrows) ? 16u : 0u;
    const __half* aSrcBase = A + (size_t)gaRow * K + cHalf;
    const __half* bSrcBase = Bt + (size_t)(colBase + cRow) * K + cHalf;

    uint32_t AsU = (uint32_t)__cvta_generic_to_shared(&As[0][0]);
    uint32_t BsU = (uint32_t)__cvta_generic_to_shared(&Bs[0][0]);
    uint32_t aDst = AsU + (uint32_t)((cRow * SMSH + cHalf) * 2);
    uint32_t bDst = BsU + (uint32_t)((cRow * SMSH + cHalf) * 2);

    uint32_t aPtr = AsU + (uint32_t)(((warpM * 32 + (lane & 15)) * SMSH) * 2 + (lane >> 4) * 16);
    uint32_t bPtr = BsU + (uint32_t)(((warpN * 64 + (lane >> 4) * 8 + (lane & 7)) * SMSH) * 2
                                     + (((lane >> 3) & 1) * 16));

    float4 acc[2][8];
#pragma unroll
    for (int i = 0; i < 2; i++)
#pragma unroll
        for (int j = 0; j < 8; j++) acc[i][j] = make_float4(0.f, 0.f, 0.f, 0.f);

    // prologue: stage 0
    CP16(aDst, aSrcBase, aSz);
    CP16(aDst + 16, aSrcBase + 8, aSz);
    CP16(bDst, bSrcBase, 16u);
    CP16(bDst + 16, bSrcBase + 8, 16u);
    asm volatile("cp.async.commit_group;");

    int niter = K / GBK;
    for (int i = 0; i < niter; i++) {
        asm volatile("cp.async.wait_group 0;");
        __syncthreads();
        if (i + 1 < niter) {
            int k0 = (i + 1) * GBK;
            uint32_t so = (uint32_t)((i + 1) & 1);
            CP16(aDst + so * ASTGB, aSrcBase + k0, aSz);
            CP16(aDst + so * ASTGB + 16, aSrcBase + k0 + 8, aSz);
            CP16(bDst + so * BSTGB, bSrcBase + k0, 16u);
            CP16(bDst + so * BSTGB + 16, bSrcBase + k0 + 8, 16u);
        }
        asm volatile("cp.async.commit_group;");

        uint32_t aP = aPtr + (i & 1) * ASTGB;
        uint32_t bP = bPtr + (i & 1) * BSTGB;
#pragma unroll
        for (int kk = 0; kk < 2; kk++) {
            uint32_t kb = kk * 32;
            uint32_t af[2][4];
            LDSM4(af[0], aP + kb);
            LDSM4(af[1], aP + 16 * SMSH * 2 + kb);
            uint32_t bfr[4][4];
#pragma unroll
            for (int p = 0; p < 4; p++) LDSM4(bfr[p], bP + p * 16 * SMSH * 2 + kb);
#pragma unroll
            for (int mt = 0; mt < 2; mt++)
#pragma unroll
                for (int nt = 0; nt < 8; nt++)
                    mma_f16(acc[mt][nt], af[mt][0], af[mt][1], af[mt][2], af[mt][3],
                            bfr[nt >> 1][(nt & 1) * 2], bfr[nt >> 1][(nt & 1) * 2 + 1]);
        }
    }

    if (mode == 2) {
        int head = blockIdx.x * 2 + warpN;
        const float* alp = attl + (bz * HH + head) * DD;
        const float* arp = attr + (bz * HH + head) * DD;
        float sl[2][2] = {{0.f, 0.f}, {0.f, 0.f}};
        float sr[2][2] = {{0.f, 0.f}, {0.f, 0.f}};
#pragma unroll
        for (int mt = 0; mt < 2; mt++) {
            int row0 = rowBase + warpM * 32 + mt * 16 + group;
            int row1 = row0 + 8;
#pragma unroll
            for (int nt = 0; nt < 8; nt++) {
                int cl = nt * 8 + 2 * tig;
                float4 v = acc[mt][nt];
                float a0 = alp[cl], a1 = alp[cl + 1];
                float r0 = arp[cl], r1 = arp[cl + 1];
                sl[mt][0] += v.x * a0 + v.y * a1;
                sl[mt][1] += v.z * a0 + v.w * a1;
                sr[mt][0] += v.x * r0 + v.y * r1;
                sr[mt][1] += v.z * r0 + v.w * r1;
                int col = colBase + warpN * 64 + cl;
                if (row0 < Mrows) *(uint32_t*)(C + (size_t)row0 * Ncols + col) = f2h2(v.x, v.y);
                if (row1 < Mrows) *(uint32_t*)(C + (size_t)row1 * Ncols + col) = f2h2(v.z, v.w);
            }
        }
#pragma unroll
        for (int mt = 0; mt < 2; mt++)
#pragma unroll
            for (int r = 0; r < 2; r++) {
                sl[mt][r] += __shfl_xor_sync(0xffffffffu, sl[mt][r], 1);
                sl[mt][r] += __shfl_xor_sync(0xffffffffu, sl[mt][r], 2);
                sr[mt][r] += __shfl_xor_sync(0xffffffffu, sr[mt][r], 1);
                sr[mt][r] += __shfl_xor_sync(0xffffffffu, sr[mt][r], 2);
            }
        if (tig == 0) {
#pragma unroll
            for (int mt = 0; mt < 2; mt++) {
                int row0 = rowBase + warpM * 32 + mt * 16 + group;
                int row1 = row0 + 8;
                if (row0 < Mrows) {
                    g_el[(bz * NN + row0) * HH + head] = sl[mt][0];
                    g_er[(bz * NN + row0) * HH + head] = sr[mt][0];
                }
                if (row1 < Mrows) {
                    g_el[(bz * NN + row1) * HH + head] = sl[mt][1];
                    g_er[(bz * NN + row1) * HH + head] = sr[mt][1];
                }
            }
        }
    } else {
        float sp[2][2] = {{0.f, 0.f}, {0.f, 0.f}};
#pragma unroll
        for (int mt = 0; mt < 2; mt++) {
#pragma unroll
            for (int nt = 0; nt < 8; nt++) {
                int col = colBase + warpN * 64 + nt * 8 + 2 * tig;
                float b0 = bias[col], b1 = bias[col + 1];
                float w0 = w2[col], w1 = w2[col + 1];
                float4 v = acc[mt][nt];
                sp[mt][0] += tanhf(v.x + b0) * w0 + tanhf(v.y + b1) * w1;
                sp[mt][1] += tanhf(v.z + b0) * w0 + tanhf(v.w + b1) * w1;
            }
        }
#pragma unroll
        for (int mt = 0; mt < 2; mt++)
#pragma unroll
            for (int r = 0; r < 2; r++) {
                sp[mt][r] += __shfl_xor_sync(0xffffffffu, sp[mt][r], 1);
                sp[mt][r] += __shfl_xor_sync(0xffffffffu, sp[mt][r], 2);
            }
        if (tig == 0) {
#pragma unroll
            for (int mt = 0; mt < 2; mt++) {
                int row0 = rowBase + warpM * 32 + mt * 16 + group;
                int row1 = row0 + 8;
                if (row0 < Mrows) atomicAdd(&g_s[row0], sp[mt][0]);
                if (row1 < Mrows) atomicAdd(&g_s[row1], sp[mt][1]);
            }
        }
    }
}

// ---------------- edge pass: exp(leaky(el+er)) + CSR scatter (fp16 ex) ------
__global__ void edge_kernel(const int* __restrict__ src, const int* __restrict__ dst) {
    int tid = blockIdx.x * blockDim.x + threadIdx.x;
    if (tid >= MM * EE) return;
    int m = tid / EE;
    int s = src[tid];
    int d = dst[tid];
    const float4* elp = (const float4*)(g_el + (size_t)(m * NN + s) * HH);
    const float4* erp = (const float4*)(g_er + (size_t)(m * NN + d) * HH);
    float4 e0 = elp[0], e1 = elp[1];
    float4 r0 = erp[0], r1 = erp[1];
    float ex[8];
    float v;
    v = e0.x + r0.x; v = v > 0.f ? v : 0.2f * v; ex[0] = expf(v);
    v = e0.y + r0.y; v = v > 0.f ? v : 0.2f * v; ex[1] = expf(v);
    v = e0.z + r0.z; v = v > 0.f ? v : 0.2f * v; ex[2] = expf(v);
    v = e0.w + r0.w; v = v > 0.f ? v : 0.2f * v; ex[3] = expf(v);
    v = e1.x + r1.x; v = v > 0.f ? v : 0.2f * v; ex[4] = expf(v);
    v = e1.y + r1.y; v = v > 0.f ? v : 0.2f * v; ex[5] = expf(v);
    v = e1.z + r1.z; v = v > 0.f ? v : 0.2f * v; ex[6] = expf(v);
    v = e1.w + r1.w; v = v > 0.f ? v : 0.2f * v; ex[7] = expf(v);

    int pos = atomicAdd(&g_cursor[m * NN + d], 1);
    int gp = m * EE + pos;
    g_src_s[gp] = s;
    *(uint4*)(g_ex_s + (size_t)gp * HH) =
        make_uint4(f2h2(ex[0], ex[1]), f2h2(ex[2], ex[3]),
                   f2h2(ex[4], ex[5]), f2h2(ex[6], ex[7]));
}

// ---------------- aggregation + fused per-metapath classifier ----------------
__global__ void agg_kernel(const float* __restrict__ bg, const float* __restrict__ pW) {
    int n = blockIdx.x;
    int m = blockIdx.y;
    int t = threadIdx.x;           // 0..127, owns dims [4t, 4t+4)
    int h = t >> 4;
    int beg = g_rowptr[m * (NN + 1) + n];
    int end = g_rowptr[m * (NN + 1) + n + 1];
    float ax = 0.f, ay = 0.f, az = 0.f, aw = 0.f;
    float dsum = 0.f;
    for (int j = beg; j < end; j++) {
        int gp = m * EE + j;
        int s = g_src_s[gp];
        float exv = __half2float(g_ex_s[(size_t)gp * HH + h]);
        dsum += exv;
        uint2 fv = *(const uint2*)(g_feat + ((size_t)(m * NN + s)) * HD + t * 4);
        float2 f01 = __half22float2(*(__half2*)&fv.x);
        float2 f23 = __half22float2(*(__half2*)&fv.y);
        ax += exv * f01.x; ay += exv * f01.y; az += exv * f23.x; aw += exv * f23.y;
    }
    float inv = 1.0f / fmaxf(dsum, 1e-9f);
    const float* bp = bg + m * HD + t * 4;
    float o0 = ax * inv + bp[0], o1 = ay * inv + bp[1];
    float o2 = az * inv + bp[2], o3 = aw * inv + bp[3];
    o0 = o0 > 0.f ? o0 : expf(o0) - 1.0f;
    o1 = o1 > 0.f ? o1 : expf(o1) - 1.0f;
    o2 = o2 > 0.f ? o2 : expf(o2) - 1.0f;
    o3 = o3 > 0.f ? o3 : expf(o3) - 1.0f;
    *(uint2*)(g_z + ((size_t)(m * NN + n)) * HD + t * 4) =
        make_uint2(f2h2(o0, o1), f2h2(o2, o3));

    const float* w = pW + (size_t)t * 4 * CC;
    float yc[CC];
#pragma unroll
    for (int c = 0; c < CC; c++)
        yc[c] = o0 * w[c] + o1 * w[CC + c] + o2 * w[2 * CC + c] + o3 * w[3 * CC + c];
#pragma unroll
    for (int c = 0; c < CC; c++)
#pragma unroll
        for (int off = 16; off > 0; off >>= 1)
            yc[c] += __shfl_down_sync(0xffffffffu, yc[c], off);
    __shared__ float ysh[4][CC];
    int warp = t >> 5, lane = t & 31;
    if (lane == 0)
#pragma unroll
        for (int c = 0; c < CC; c++) ysh[warp][c] = yc[c];
    __syncthreads();
    if (t < CC) {
        float v = ysh[0][t] + ysh[1][t] + ysh[2][t] + ysh[3][t];
        g_y[((size_t)m * NN + n) * CC + t] = v;
    }
}

// ---------------- mean over nodes per metapath ----------------
__global__ void reduce_kernel() {
    int m = blockIdx.y;
    int t = threadIdx.x;
    float s = 0.f;
    for (int i = blockIdx.x * blockDim.x + t; i < NN; i += gridDim.x * blockDim.x)
        s += g_s[m * NN + i];
    __shared__ float sh[256];
    sh[t] = s;
    __syncthreads();
    for (int off = 128; off > 0; off >>= 1) {
        if (t < off) sh[t] += sh[t + off];
        __syncthreads();
    }
    if (t == 0) atomicAdd(&g_sum[m], sh[0]);
}

__global__ void beta_kernel() {
    float a = g_sum[0] / (float)NN;
    float b = g_sum[1] / (float)NN;
    float mx = fmaxf(a, b);
    float e0 = expf(a - mx), e1 = expf(b - mx);
    float inv = 1.0f / (e0 + e1);
    g_beta[0] = e0 * inv;
    g_beta[1] = e1 * inv;
}

// ---------------- tiny final: out = b0*y0 + b1*y1 + pb ----------------
__global__ void final_kernel(const float* __restrict__ pb, float* __restrict__ out) {
    int tid = blockIdx.x * blockDim.x + threadIdx.x;
    if (tid >= NN * CC) return;
    int c = tid % CC;
    float b0 = g_beta[0], b1 = g_beta[1];
    out[tid] = b0 * g_y[tid] + b1 * g_y[NN * CC + tid] + pb[c];
}

// ---------------- launch ----------------
extern "C" void kernel_launch(void* const* d_in, const int* in_sizes, int n_in,
                              void* d_out, int out_size) {
    const float* h    = (const float*)d_in[0];
    const int*   src  = (const int*)d_in[1];
    const int*   dst  = (const int*)d_in[2];
    const float* W    = (const float*)d_in[3];
    const float* al   = (const float*)d_in[4];
    const float* ar   = (const float*)d_in[5];
    const float* bg   = (const float*)d_in[6];
    const float* sW1  = (const float*)d_in[7];
    const float* sb1  = (const float*)d_in[8];
    const float* sW2  = (const float*)d_in[9];
    const float* pW   = (const float*)d_in[10];
    const float* pb   = (const float*)d_in[11];
    float* out = (float*)d_out;

    __half *p_h16, *p_Wt16, *p_sW1t16, *p_feat, *p_z;
    cudaGetSymbolAddress((void**)&p_h16, g_h16);
    cudaGetSymbolAddress((void**)&p_Wt16, g_Wt16);
    cudaGetSymbolAddress((void**)&p_sW1t16, g_sW1t16);
    cudaGetSymbolAddress((void**)&p_feat, g_feat);
    cudaGetSymbolAddress((void**)&p_z, g_z);

    prep_kernel<<<400, 256>>>(h, W, sW1);                          // 1
    hist_kernel<<<(MM * EE + 255) / 256, 256>>>(dst);              // 2
    scan1_kernel<<<dim3(SB, MM), 512>>>();                         // 3
    scan2_kernel<<<dim3(SB, MM), 512>>>();                         // 4

    // 5: feat[m] = h @ W[m], fused el/er epilogue (2 heads per CTA)
    gemm_mma<<<dim3(HD / GBN, (NN + GBM - 1) / GBM, MM), 256>>>(
        p_h16, p_Wt16, p_feat, NN, FF, HD, nullptr, 2,
        0L, (long)HD * FF, (long)NN * HD, al, ar, nullptr);

    edge_kernel<<<(MM * EE + 255) / 256, 256>>>(src, dst);         // 6
    agg_kernel<<<dim3(NN, MM), 128>>>(bg, pW);                     // 7

    // 8: semantic — s[row] += sum tanh(z@W1 + b1) * W2, no C write
    gemm_mma<<<dim3(HIDD / GBN, (MM * NN + GBM - 1) / GBM, 1), 256>>>(
        p_z, p_sW1t16, nullptr, MM * NN, HD, HIDD, sb1, 3,
        0L, 0L, 0L, nullptr, nullptr, sW2);

    reduce_kernel<<<dim3(40, MM), 256>>>();                        // 9
    beta_kernel<<<1, 1>>>();                                       // 10
    final_kernel<<<(NN * CC + 255) / 256, 256>>>(pb, out);         // 11
}

// round 12
// speedup vs baseline: 4.3583x; 1.0314x over previous
#include <cuda_runtime.h>
#include <cuda_bf16.h>
#include <cuda_fp16.h>
#include <math.h>
#include <stdint.h>

#define NN 20000
#define FF 256
#define HH 8
#define DD 64
#define HD 512
#define MM 2
#define EE 320000
#define CC 5
#define HIDD 128
#define SB 40          // scan blocks per metapath (40*512 >= NN)

// ---------------- scratch (device globals; no allocation) ----------------
__device__ __half g_h16[NN * FF];
__device__ __half g_Wt16[MM * HD * FF];
__device__ __half g_sW1t16[HIDD * HD];
__device__ __half g_feat[MM * NN * HD];
__device__ __half g_z[MM * NN * HD];
__device__ float g_el[MM * NN * HH];
__device__ float g_er[MM * NN * HH];
__device__ int   g_hist[MM * NN];
__device__ int   g_rowptr[MM * (NN + 1)];
__device__ int   g_cursor[MM * NN];
__device__ int   g_bsum[MM * SB];
__device__ int   g_src_s[MM * EE];
__device__ __half g_ex_s[MM * EE * HH];
__device__ float g_s[MM * NN];
__device__ float g_y[MM * NN * CC];
__device__ float g_sum[MM];
__device__ float g_beta[MM];

__device__ __forceinline__ uint32_t f2h2(float a, float b) {
    __half2 h = __floats2half2_rn(a, b);
    return *(uint32_t*)&h;
}

// ---------------- prep: zero hist/s/sum + h fp16 conversion ----------------
__global__ void prep_kernel(const float* __restrict__ h) {
    int stride = gridDim.x * blockDim.x;
    int t0 = blockIdx.x * blockDim.x + threadIdx.x;
    for (int i = t0; i < MM * NN; i += stride) {
        g_hist[i] = 0;
        g_s[i] = 0.0f;
    }
    if (t0 < MM) g_sum[t0] = 0.0f;
    for (int i = t0; i < NN * FF / 4; i += stride) {
        float4 v = ((const float4*)h)[i];
        ((uint2*)g_h16)[i] = make_uint2(f2h2(v.x, v.y), f2h2(v.z, v.w));
    }
}

// ---------------- tiled transpose fp32->fp16: dst[n*K+k] = src[k*N+n] ------
// grid: (N/32, K/32, batch), block 256 (32x8)
__global__ void tr_kernel(const float* __restrict__ src, __half* __restrict__ dst,
                          int K, int N) {
    __shared__ float tile[32][33];
    int b = blockIdx.z;
    src += (size_t)b * K * N;
    dst += (size_t)b * K * N;
    int nt = blockIdx.x * 32, kt = blockIdx.y * 32;
    int tx = threadIdx.x & 31, ty = threadIdx.x >> 5;   // tx 0..31, ty 0..7
#pragma unroll
    for (int i = 0; i < 32; i += 8)
        tile[ty + i][tx] = src[(size_t)(kt + ty + i) * N + nt + tx];
    __syncthreads();
#pragma unroll
    for (int i = 0; i < 32; i += 8)
        dst[(size_t)(nt + ty + i) * K + kt + tx] = __float2half(tile[tx][ty + i]);
}

// ---------------- in-degree histogram ----------------
__global__ void hist_kernel(const int* __restrict__ dst) {
    int tid = blockIdx.x * blockDim.x + threadIdx.x;
    if (tid >= MM * EE) return;
    int m = tid / EE;
    atomicAdd(&g_hist[m * NN + dst[tid]], 1);
}

// ---------------- hierarchical scan: pass 1 (block-local) ----------------
__global__ void scan1_kernel() {
    int m = blockIdx.y, b = blockIdx.x, t = threadIdx.x;
    int idx = b * 512 + t;
    int v = (idx < NN) ? g_hist[m * NN + idx] : 0;
    __shared__ int sh[512];
    sh[t] = v;
    __syncthreads();
    for (int off = 1; off < 512; off <<= 1) {
        int x = (t >= off) ? sh[t - off] : 0;
        __syncthreads();
        sh[t] += x;
        __syncthreads();
    }
    int incl = sh[t];
    if (idx < NN) g_rowptr[m * (NN + 1) + idx] = incl - v;
    if (t == 511) g_bsum[m * SB + b] = incl;
}

// ---------------- hierarchical scan: pass 2 (apply offsets) ----------------
__global__ void scan2_kernel() {
    int m = blockIdx.y, b = blockIdx.x, t = threadIdx.x;
    __shared__ int off;
    if (t == 0) {
        int s = 0;
        for (int i = 0; i < b; i++) s += g_bsum[m * SB + i];
        off = s;
    }
    __syncthreads();
    int idx = b * 512 + t;
    if (idx < NN) {
        int r = g_rowptr[m * (NN + 1) + idx] + off;
        g_rowptr[m * (NN + 1) + idx] = r;
        g_cursor[m * NN + idx] = r;
    }
    if (b == 0 && t == 0) g_rowptr[m * (NN + 1) + NN] = EE;
}

// ---------------- FP16 MMA GEMM, cp.async 2-stage pipeline, GBK=32 ---------
// mode 2: write C (half) + fused el/er;  mode 3: no C write, s[row] atomics
#define GBM 128
#define GBN 128
#define GBK 32
#define SMSH 40                    // smem row stride in halfs (32 + 8 pad)
#define ASTGB (GBM * SMSH * 2)     // bytes per A stage
#define BSTGB (GBN * SMSH * 2)     // bytes per B stage

#define LDSM4(r, addr)                                                          \
    asm volatile("ldmatrix.sync.aligned.m8n8.x4.shared.b16 {%0,%1,%2,%3}, [%4];" \
                 : "=r"((r)[0]), "=r"((r)[1]), "=r"((r)[2]), "=r"((r)[3])        \
                 : "r"(addr))

#define CP16(dst, src, sz)                                                       \
    asm volatile("cp.async.cg.shared.global [%0], [%1], 16, %2;"                 \
                 :: "r"(dst), "l"(src), "r"(sz))

__device__ __forceinline__ void mma_f16(float4& d,
                                        uint32_t a0, uint32_t a1, uint32_t a2, uint32_t a3,
                                        uint32_t b0, uint32_t b1) {
    asm volatile("mma.sync.aligned.m16n8k16.row.col.f32.f16.f16.f32 "
                 "{%0,%1,%2,%3}, {%4,%5,%6,%7}, {%8,%9}, {%0,%1,%2,%3};"
                 : "+f"(d.x), "+f"(d.y), "+f"(d.z), "+f"(d.w)
                 : "r"(a0), "r"(a1), "r"(a2), "r"(a3), "r"(b0), "r"(b1));
}

__global__ __launch_bounds__(256) void gemm_mma(
    const __half* __restrict__ A, const __half* __restrict__ Bt, __half* __restrict__ C,
    int Mrows, int K, int Ncols, const float* __restrict__ bias, int mode,
    long aStride, long bStride, long cStride,
    const float* __restrict__ attl, const float* __restrict__ attr,
    const float* __restrict__ w2) {
    int bz = blockIdx.z;
    A += (size_t)bz * aStride;
    Bt += (size_t)bz * bStride;
    C += (size_t)bz * cStride;

    __shared__ __align__(16) __half As[2][GBM * SMSH];
    __shared__ __align__(16) __half Bs[2][GBN * SMSH];

    int tid = threadIdx.x;
    int warp = tid >> 5;
    int lane = tid & 31;
    int warpM = warp >> 1;
    int warpN = warp & 1;
    int group = lane >> 2;
    int tig = lane & 3;

    int rowBase = blockIdx.y * GBM;
    int colBase = blockIdx.x * GBN;

    int cRow = tid >> 1;
    int cHalf = (tid & 1) * 16;

    int gaRow = rowBase + cRow;
    uint32_t aSz = (gaRow < Mrows) ? 16u : 0u;
    const __half* aSrcBase = A + (size_t)gaRow * K + cHalf;
    const __half* bSrcBase = Bt + (size_t)(colBase + cRow) * K + cHalf;

    uint32_t AsU = (uint32_t)__cvta_generic_to_shared(&As[0][0]);
    uint32_t BsU = (uint32_t)__cvta_generic_to_shared(&Bs[0][0]);
    uint32_t aDst = AsU + (uint32_t)((cRow * SMSH + cHalf) * 2);
    uint32_t bDst = BsU + (uint32_t)((cRow * SMSH + cHalf) * 2);

    uint32_t aPtr = AsU + (uint32_t)(((warpM * 32 + (lane & 15)) * SMSH) * 2 + (lane >> 4) * 16);
    uint32_t bPtr = BsU + (uint32_t)(((warpN * 64 + (lane >> 4) * 8 + (lane & 7)) * SMSH) * 2
                                     + (((lane >> 3) & 1) * 16));

    float4 acc[2][8];
#pragma unroll
    for (int i = 0; i < 2; i++)
#pragma unroll
        for (int j = 0; j < 8; j++) acc[i][j] = make_float4(0.f, 0.f, 0.f, 0.f);

    CP16(aDst, aSrcBase, aSz);
    CP16(aDst + 16, aSrcBase + 8, aSz);
    CP16(bDst, bSrcBase, 16u);
    CP16(bDst + 16, bSrcBase + 8, 16u);
    asm volatile("cp.async.commit_group;");

    int niter = K / GBK;
    for (int i = 0; i < niter; i++) {
        asm volatile("cp.async.wait_group 0;");
        __syncthreads();
        if (i + 1 < niter) {
            int k0 = (i + 1) * GBK;
            uint32_t so = (uint32_t)((i + 1) & 1);
            CP16(aDst + so * ASTGB, aSrcBase + k0, aSz);
            CP16(aDst + so * ASTGB + 16, aSrcBase + k0 + 8, aSz);
            CP16(bDst + so * BSTGB, bSrcBase + k0, 16u);
            CP16(bDst + so * BSTGB + 16, bSrcBase + k0 + 8, 16u);
        }
        asm volatile("cp.async.commit_group;");

        uint32_t aP = aPtr + (i & 1) * ASTGB;
        uint32_t bP = bPtr + (i & 1) * BSTGB;
#pragma unroll
        for (int kk = 0; kk < 2; kk++) {
            uint32_t kb = kk * 32;
            uint32_t af[2][4];
            LDSM4(af[0], aP + kb);
            LDSM4(af[1], aP + 16 * SMSH * 2 + kb);
            uint32_t bfr[4][4];
#pragma unroll
            for (int p = 0; p < 4; p++) LDSM4(bfr[p], bP + p * 16 * SMSH * 2 + kb);
#pragma unroll
            for (int mt = 0; mt < 2; mt++)
#pragma unroll
                for (int nt = 0; nt < 8; nt++)
                    mma_f16(acc[mt][nt], af[mt][0], af[mt][1], af[mt][2], af[mt][3],
                            bfr[nt >> 1][(nt & 1) * 2], bfr[nt >> 1][(nt & 1) * 2 + 1]);
        }
    }

    if (mode == 2) {
        int head = blockIdx.x * 2 + warpN;
        const float* alp = attl + (bz * HH + head) * DD;
        const float* arp = attr + (bz * HH + head) * DD;
        float sl[2][2] = {{0.f, 0.f}, {0.f, 0.f}};
        float sr[2][2] = {{0.f, 0.f}, {0.f, 0.f}};
#pragma unroll
        for (int mt = 0; mt < 2; mt++) {
            int row0 = rowBase + warpM * 32 + mt * 16 + group;
            int row1 = row0 + 8;
#pragma unroll
            for (int nt = 0; nt < 8; nt++) {
                int cl = nt * 8 + 2 * tig;
                float4 v = acc[mt][nt];
                float a0 = alp[cl], a1 = alp[cl + 1];
                float r0 = arp[cl], r1 = arp[cl + 1];
                sl[mt][0] += v.x * a0 + v.y * a1;
                sl[mt][1] += v.z * a0 + v.w * a1;
                sr[mt][0] += v.x * r0 + v.y * r1;
                sr[mt][1] += v.z * r0 + v.w * r1;
                int col = colBase + warpN * 64 + cl;
                if (row0 < Mrows) *(uint32_t*)(C + (size_t)row0 * Ncols + col) = f2h2(v.x, v.y);
                if (row1 < Mrows) *(uint32_t*)(C + (size_t)row1 * Ncols + col) = f2h2(v.z, v.w);
            }
        }
#pragma unroll
        for (int mt = 0; mt < 2; mt++)
#pragma unroll
            for (int r = 0; r < 2; r++) {
                sl[mt][r] += __shfl_xor_sync(0xffffffffu, sl[mt][r], 1);
                sl[mt][r] += __shfl_xor_sync(0xffffffffu, sl[mt][r], 2);
                sr[mt][r] += __shfl_xor_sync(0xffffffffu, sr[mt][r], 1);
                sr[mt][r] += __shfl_xor_sync(0xffffffffu, sr[mt][r], 2);
            }
        if (tig == 0) {
#pragma unroll
            for (int mt = 0; mt < 2; mt++) {
                int row0 = rowBase + warpM * 32 + mt * 16 + group;
                int row1 = row0 + 8;
                if (row0 < Mrows) {
                    g_el[(bz * NN + row0) * HH + head] = sl[mt][0];
                    g_er[(bz * NN + row0) * HH + head] = sr[mt][0];
                }
                if (row1 < Mrows) {
                    g_el[(bz * NN + row1) * HH + head] = sl[mt][1];
                    g_er[(bz * NN + row1) * HH + head] = sr[mt][1];
                }
            }
        }
    } else {
        float sp[2][2] = {{0.f, 0.f}, {0.f, 0.f}};
#pragma unroll
        for (int mt = 0; mt < 2; mt++) {
#pragma unroll
            for (int nt = 0; nt < 8; nt++) {
                int col = colBase + warpN * 64 + nt * 8 + 2 * tig;
                float b0 = bias[col], b1 = bias[col + 1];
                float w0 = w2[col], w1 = w2[col + 1];
                float4 v = acc[mt][nt];
                sp[mt][0] += tanhf(v.x + b0) * w0 + tanhf(v.y + b1) * w1;
                sp[mt][1] += tanhf(v.z + b0) * w0 + tanhf(v.w + b1) * w1;
            }
        }
#pragma unroll
        for (int mt = 0; mt < 2; mt++)
#pragma unroll
            for (int r = 0; r < 2; r++) {
                sp[mt][r] += __shfl_xor_sync(0xffffffffu, sp[mt][r], 1);
                sp[mt][r] += __shfl_xor_sync(0xffffffffu, sp[mt][r], 2);
            }
        if (tig == 0) {
#pragma unroll
            for (int mt = 0; mt < 2; mt++) {
                int row0 = rowBase + warpM * 32 + mt * 16 + group;
                int row1 = row0 + 8;
                if (row0 < Mrows) atomicAdd(&g_s[row0], sp[mt][0]);
                if (row1 < Mrows) atomicAdd(&g_s[row1], sp[mt][1]);
            }
        }
    }
}

// ---------------- edge pass: exp(leaky(el+er)) + CSR scatter (fp16 ex) ------
__global__ void edge_kernel(const int* __restrict__ src, const int* __restrict__ dst) {
    int tid = blockIdx.x * blockDim.x + threadIdx.x;
    if (tid >= MM * EE) return;
    int m = tid / EE;
    int s = src[tid];
    int d = dst[tid];
    const float4* elp = (const float4*)(g_el + (size_t)(m * NN + s) * HH);
    const float4* erp = (const float4*)(g_er + (size_t)(m * NN + d) * HH);
    float4 e0 = elp[0], e1 = elp[1];
    float4 r0 = erp[0], r1 = erp[1];
    float ex[8];
    float v;
    v = e0.x + r0.x; v = v > 0.f ? v : 0.2f * v; ex[0] = expf(v);
    v = e0.y + r0.y; v = v > 0.f ? v : 0.2f * v; ex[1] = expf(v);
    v = e0.z + r0.z; v = v > 0.f ? v : 0.2f * v; ex[2] = expf(v);
    v = e0.w + r0.w; v = v > 0.f ? v : 0.2f * v; ex[3] = expf(v);
    v = e1.x + r1.x; v = v > 0.f ? v : 0.2f * v; ex[4] = expf(v);
    v = e1.y + r1.y; v = v > 0.f ? v : 0.2f * v; ex[5] = expf(v);
    v = e1.z + r1.z; v = v > 0.f ? v : 0.2f * v; ex[6] = expf(v);
    v = e1.w + r1.w; v = v > 0.f ? v : 0.2f * v; ex[7] = expf(v);

    int pos = atomicAdd(&g_cursor[m * NN + d], 1);
    int gp = m * EE + pos;
    g_src_s[gp] = s;
    *(uint4*)(g_ex_s + (size_t)gp * HH) =
        make_uint4(f2h2(ex[0], ex[1]), f2h2(ex[2], ex[3]),
                   f2h2(ex[4], ex[5]), f2h2(ex[6], ex[7]));
}

// ---------------- aggregation + fused classifier (4-wide gather unroll) -----
__global__ void agg_kernel(const float* __restrict__ bg, const float* __restrict__ pW) {
    int n = blockIdx.x;
    int m = blockIdx.y;
    int t = threadIdx.x;           // 0..127, owns dims [4t, 4t+4)
    int h = t >> 4;
    int beg = g_rowptr[m * (NN + 1) + n];
    int end = g_rowptr[m * (NN + 1) + n + 1];
    float ax = 0.f, ay = 0.f, az = 0.f, aw = 0.f;
    float dsum = 0.f;
    const __half* featB = g_feat + (size_t)m * NN * HD + t * 4;
    int j = beg;
    for (; j + 3 < end; j += 4) {
        int gp = m * EE + j;
        int s0 = __ldg(&g_src_s[gp]);
        int s1 = __ldg(&g_src_s[gp + 1]);
        int s2 = __ldg(&g_src_s[gp + 2]);
        int s3 = __ldg(&g_src_s[gp + 3]);
        float e0 = __half2float(g_ex_s[(size_t)gp * HH + h]);
        float e1 = __half2float(g_ex_s[(size_t)(gp + 1) * HH + h]);
        float e2 = __half2float(g_ex_s[(size_t)(gp + 2) * HH + h]);
        float e3 = __half2float(g_ex_s[(size_t)(gp + 3) * HH + h]);
        uint2 v0 = __ldg((const uint2*)(featB + (size_t)s0 * HD));
        uint2 v1 = __ldg((const uint2*)(featB + (size_t)s1 * HD));
        uint2 v2 = __ldg((const uint2*)(featB + (size_t)s2 * HD));
        uint2 v3 = __ldg((const uint2*)(featB + (size_t)s3 * HD));
        dsum += (e0 + e1) + (e2 + e3);
        float2 a01, a23;
        a01 = __half22float2(*(__half2*)&v0.x); a23 = __half22float2(*(__half2*)&v0.y);
        ax += e0 * a01.x; ay += e0 * a01.y; az += e0 * a23.x; aw += e0 * a23.y;
        a01 = __half22float2(*(__half2*)&v1.x); a23 = __half22float2(*(__half2*)&v1.y);
        ax += e1 * a01.x; ay += e1 * a01.y; az += e1 * a23.x; aw += e1 * a23.y;
        a01 = __half22float2(*(__half2*)&v2.x); a23 = __half22float2(*(__half2*)&v2.y);
        ax += e2 * a01.x; ay += e2 * a01.y; az += e2 * a23.x; aw += e2 * a23.y;
        a01 = __half22float2(*(__half2*)&v3.x); a23 = __half22float2(*(__half2*)&v3.y);
        ax += e3 * a01.x; ay += e3 * a01.y; az += e3 * a23.x; aw += e3 * a23.y;
    }
    for (; j < end; j++) {
        int gp = m * EE + j;
        int s = __ldg(&g_src_s[gp]);
        float exv = __half2float(g_ex_s[(size_t)gp * HH + h]);
        dsum += exv;
        uint2 fv = __ldg((const uint2*)(featB + (size_t)s * HD));
        float2 f01 = __half22float2(*(__half2*)&fv.x);
        float2 f23 = __half22float2(*(__half2*)&fv.y);
        ax += exv * f01.x; ay += exv * f01.y; az += exv * f23.x; aw += exv * f23.y;
    }
    float inv = 1.0f / fmaxf(dsum, 1e-9f);
    const float* bp = bg + m * HD + t * 4;
    float o0 = ax * inv + bp[0], o1 = ay * inv + bp[1];
    float o2 = az * inv + bp[2], o3 = aw * inv + bp[3];
    o0 = o0 > 0.f ? o0 : expf(o0) - 1.0f;
    o1 = o1 > 0.f ? o1 : expf(o1) - 1.0f;
    o2 = o2 > 0.f ? o2 : expf(o2) - 1.0f;
    o3 = o3 > 0.f ? o3 : expf(o3) - 1.0f;
    *(uint2*)(g_z + ((size_t)(m * NN + n)) * HD + t * 4) =
        make_uint2(f2h2(o0, o1), f2h2(o2, o3));

    const float* w = pW + (size_t)t * 4 * CC;
    float yc[CC];
#pragma unroll
    for (int c = 0; c < CC; c++)
        yc[c] = o0 * w[c] + o1 * w[CC + c] + o2 * w[2 * CC + c] + o3 * w[3 * CC + c];
#pragma unroll
    for (int c = 0; c < CC; c++)
#pragma unroll
        for (int off = 16; off > 0; off >>= 1)
            yc[c] += __shfl_down_sync(0xffffffffu, yc[c], off);
    __shared__ float ysh[4][CC];
    int warp = t >> 5, lane = t & 31;
    if (lane == 0)
#pragma unroll
        for (int c = 0; c < CC; c++) ysh[warp][c] = yc[c];
    __syncthreads();
    if (t < CC) {
        float v = ysh[0][t] + ysh[1][t] + ysh[2][t] + ysh[3][t];
        g_y[((size_t)m * NN + n) * CC + t] = v;
    }
}

// ---------------- mean over nodes per metapath ----------------
__global__ void reduce_kernel() {
    int m = blockIdx.y;
    int t = threadIdx.x;
    float s = 0.f;
    for (int i = blockIdx.x * blockDim.x + t; i < NN; i += gridDim.x * blockDim.x)
        s += g_s[m * NN + i];
    __shared__ float sh[256];
    sh[t] = s;
    __syncthreads();
    for (int off = 128; off > 0; off >>= 1) {
        if (t < off) sh[t] += sh[t + off];
        __syncthreads();
    }
    if (t == 0) atomicAdd(&g_sum[m], sh[0]);
}

__global__ void beta_kernel() {
    float a = g_sum[0] / (float)NN;
    float b = g_sum[1] / (float)NN;
    float mx = fmaxf(a, b);
    float e0 = expf(a - mx), e1 = expf(b - mx);
    float inv = 1.0f / (e0 + e1);
    g_beta[0] = e0 * inv;
    g_beta[1] = e1 * inv;
}

// ---------------- tiny final: out = b0*y0 + b1*y1 + pb ----------------
__global__ void final_kernel(const float* __restrict__ pb, float* __restrict__ out) {
    int tid = blockIdx.x * blockDim.x + threadIdx.x;
    if (tid >= NN * CC) return;
    int c = tid % CC;
    float b0 = g_beta[0], b1 = g_beta[1];
    out[tid] = b0 * g_y[tid] + b1 * g_y[NN * CC + tid] + pb[c];
}

// ---------------- launch ----------------
extern "C" void kernel_launch(void* const* d_in, const int* in_sizes, int n_in,
                              void* d_out, int out_size) {
    const float* h    = (const float*)d_in[0];
    const int*   src  = (const int*)d_in[1];
    const int*   dst  = (const int*)d_in[2];
    const float* W    = (const float*)d_in[3];
    const float* al   = (const float*)d_in[4];
    const float* ar   = (const float*)d_in[5];
    const float* bg   = (const float*)d_in[6];
    const float* sW1  = (const float*)d_in[7];
    const float* sb1  = (const float*)d_in[8];
    const float* sW2  = (const float*)d_in[9];
    const float* pW   = (const float*)d_in[10];
    const float* pb   = (const float*)d_in[11];
    float* out = (float*)d_out;

    __half *p_h16, *p_Wt16, *p_sW1t16, *p_feat, *p_z;
    cudaGetSymbolAddress((void**)&p_h16, g_h16);
    cudaGetSymbolAddress((void**)&p_Wt16, g_Wt16);
    cudaGetSymbolAddress((void**)&p_sW1t16, g_sW1t16);
    cudaGetSymbolAddress((void**)&p_feat, g_feat);
    cudaGetSymbolAddress((void**)&p_z, g_z);

    prep_kernel<<<400, 256>>>(h);                                  // 1
    tr_kernel<<<dim3(HD / 32, FF / 32, MM), 256>>>(W, p_Wt16, FF, HD);        // 2
    tr_kernel<<<dim3(HIDD / 32, HD / 32, 1), 256>>>(sW1, p_sW1t16, HD, HIDD); // 3
    hist_kernel<<<(MM * EE + 255) / 256, 256>>>(dst);              // 4
    scan1_kernel<<<dim3(SB, MM), 512>>>();                         // 5
    scan2_kernel<<<dim3(SB, MM), 512>>>();                         // 6

    // 7: feat[m] = h @ W[m], fused el/er epilogue (2 heads per CTA)
    gemm_mma<<<dim3(HD / GBN, (NN + GBM - 1) / GBM, MM), 256>>>(
        p_h16, p_Wt16, p_feat, NN, FF, HD, nullptr, 2,
        0L, (long)HD * FF, (long)NN * HD, al, ar, nullptr);

    edge_kernel<<<(MM * EE + 255) / 256, 256>>>(src, dst);         // 8
    agg_kernel<<<dim3(NN, MM), 128>>>(bg, pW);                     // 9

    // 10: semantic — s[row] += sum tanh(z@W1 + b1) * W2, no C write
    gemm_mma<<<dim3(HIDD / GBN, (MM * NN + GBM - 1) / GBM, 1), 256>>>(
        p_z, p_sW1t16, nullptr, MM * NN, HD, HIDD, sb1, 3,
        0L, 0L, 0L, nullptr, nullptr, sW2);

    reduce_kernel<<<dim3(40, MM), 256>>>();                        // 11
    beta_kernel<<<1, 1>>>();                                       // 12
    final_kernel<<<(NN * CC + 255) / 256, 256>>>(pb, out);         // 13
}

// round 14
// speedup vs baseline: 4.4472x; 1.0204x over previous
#include <cuda_runtime.h>
#include <cuda_bf16.h>
#include <cuda_fp16.h>
#include <math.h>
#include <stdint.h>

#define NN 20000
#define FF 256
#define HH 8
#define DD 64
#define HD 512
#define MM 2
#define EE 320000
#define CC 5
#define HIDD 128
#define SB 40          // scan blocks per metapath (40*512 >= NN)

// mega-prep block ranges
#define MP_WTR 256     // W transpose tiles: 16 x 8 x 2
#define MP_STR 64      // sW1 transpose tiles: 4 x 16
#define MP_HCV 400     // h convert blocks
#define MP_HIST 2500   // hist blocks (2500*256 = 640000 edges)
#define MP_TOTAL (MP_WTR + MP_STR + MP_HCV + MP_HIST)

// ---------------- scratch (device globals; no allocation) ----------------
__device__ __half g_h16[NN * FF];
__device__ __half g_Wt16[MM * HD * FF];
__device__ __half g_sW1t16[HIDD * HD];
__device__ __half g_feat[MM * NN * HD];
__device__ __half g_z[MM * NN * HD];
__device__ float g_el[MM * NN * HH];
__device__ float g_er[MM * NN * HH];
__device__ int   g_hist[MM * NN];
__device__ int   g_rowptr[MM * (NN + 1)];
__device__ int   g_cursor[MM * NN];
__device__ int   g_bsum[MM * SB];
__device__ int   g_src_s[MM * EE];
__device__ __half g_ex_s[MM * EE * HH];
__device__ float g_s[MM * NN];
__device__ float g_y[MM * NN * CC];
__device__ float g_sum[MM];

__device__ __forceinline__ uint32_t f2h2(float a, float b) {
    __half2 h = __floats2half2_rn(a, b);
    return *(uint32_t*)&h;
}

// ---------------- zero hist/s/sum (must precede mega_prep's hist atomics) ---
__global__ void zero_hist_kernel() {
    int i = blockIdx.x * blockDim.x + threadIdx.x;
    int total = MM * NN;
    for (; i < total; i += gridDim.x * blockDim.x) {
        g_hist[i] = 0;
        g_s[i] = 0.0f;
    }
    if (blockIdx.x == 0 && threadIdx.x < MM) g_sum[threadIdx.x] = 0.0f;
}

// ---------------- mega-prep: W^T + sW1^T + h convert + hist, one launch -----
// The four jobs are mutually independent; role-split by blockIdx so the
// atomic-latency-bound hist overlaps the bandwidth-bound converts.
__global__ void mega_prep(const float* __restrict__ h, const float* __restrict__ W,
                          const float* __restrict__ sW1, const int* __restrict__ dst) {
    __shared__ float tile[32][33];
    int b = blockIdx.x;
    int t = threadIdx.x;
    if (b < MP_WTR) {
        // W transpose: Wt[m][n][k] = W[m][k][n]; K=FF rows, N=HD cols
        int m = b >> 7;              // /128 tiles per metapath
        int r = b & 127;
        int ky = r >> 4;             // 0..7   (FF/32)
        int nx = r & 15;             // 0..15  (HD/32)
        const float* src = W + (size_t)m * FF * HD;
        __half* dstp = g_Wt16 + (size_t)m * HD * FF;
        int nt = nx * 32, kt = ky * 32;
        int tx = t & 31, ty = t >> 5;
#pragma unroll
        for (int i = 0; i < 32; i += 8)
            tile[ty + i][tx] = src[(size_t)(kt + ty + i) * HD + nt + tx];
        __syncthreads();
#pragma unroll
        for (int i = 0; i < 32; i += 8)
            dstp[(size_t)(nt + ty + i) * FF + kt + tx] = __float2half(tile[tx][ty + i]);
    } else if (b < MP_WTR + MP_STR) {
        // sW1 transpose: K=HD rows, N=HIDD cols
        int r = b - MP_WTR;
        int ky = r >> 2;             // 0..15  (HD/32)
        int nx = r & 3;              // 0..3   (HIDD/32)
        int nt = nx * 32, kt = ky * 32;
        int tx = t & 31, ty = t >> 5;
#pragma unroll
        for (int i = 0; i < 32; i += 8)
            tile[ty + i][tx] = sW1[(size_t)(kt + ty + i) * HIDD + nt + tx];
        __syncthreads();
#pragma unroll
        for (int i = 0; i < 32; i += 8)
            g_sW1t16[(size_t)(nt + ty + i) * HD + kt + tx] = __float2half(tile[tx][ty + i]);
    } else if (b < MP_WTR + MP_STR + MP_HCV) {
        // h convert (grid-stride over this sub-grid)
        int lt = (b - MP_WTR - MP_STR) * 256 + t;
        int stride = MP_HCV * 256;
        for (int i = lt; i < NN * FF / 4; i += stride) {
            float4 v = ((const float4*)h)[i];
            ((uint2*)g_h16)[i] = make_uint2(f2h2(v.x, v.y), f2h2(v.z, v.w));
        }
    } else {
        // hist (g_hist zeroed by zero_hist_kernel launched before)
        int e = (b - MP_WTR - MP_STR - MP_HCV) * 256 + t;
        if (e < MM * EE) {
            int m = e / EE;
            atomicAdd(&g_hist[m * NN + dst[e]], 1);
        }
    }
}

// ---------------- hierarchical scan: pass 1 (block-local) ----------------
__global__ void scan1_kernel() {
    int m = blockIdx.y, b = blockIdx.x, t = threadIdx.x;
    int idx = b * 512 + t;
    int v = (idx < NN) ? g_hist[m * NN + idx] : 0;
    __shared__ int sh[512];
    sh[t] = v;
    __syncthreads();
    for (int off = 1; off < 512; off <<= 1) {
        int x = (t >= off) ? sh[t - off] : 0;
        __syncthreads();
        sh[t] += x;
        __syncthreads();
    }
    int incl = sh[t];
    if (idx < NN) g_rowptr[m * (NN + 1) + idx] = incl - v;
    if (t == 511) g_bsum[m * SB + b] = incl;
}

// ---------------- hierarchical scan: pass 2 (apply offsets) ----------------
__global__ void scan2_kernel() {
    int m = blockIdx.y, b = blockIdx.x, t = threadIdx.x;
    __shared__ int off;
    if (t == 0) {
        int s = 0;
        for (int i = 0; i < b; i++) s += g_bsum[m * SB + i];
        off = s;
    }
    __syncthreads();
    int idx = b * 512 + t;
    if (idx < NN) {
        int r = g_rowptr[m * (NN + 1) + idx] + off;
        g_rowptr[m * (NN + 1) + idx] = r;
        g_cursor[m * NN + idx] = r;
    }
    if (b == 0 && t == 0) g_rowptr[m * (NN + 1) + NN] = EE;
}

// ---------------- FP16 MMA GEMM, cp.async 2-stage pipeline, GBK=32 ---------
#define GBM 128
#define GBN 128
#define GBK 32
#define SMSH 40
#define ASTGB (GBM * SMSH * 2)
#define BSTGB (GBN * SMSH * 2)

#define LDSM4(r, addr)                                                          \
    asm volatile("ldmatrix.sync.aligned.m8n8.x4.shared.b16 {%0,%1,%2,%3}, [%4];" \
                 : "=r"((r)[0]), "=r"((r)[1]), "=r"((r)[2]), "=r"((r)[3])        \
                 : "r"(addr))

#define CP16(dst, src, sz)                                                       \
    asm volatile("cp.async.cg.shared.global [%0], [%1], 16, %2;"                 \
                 :: "r"(dst), "l"(src), "r"(sz))

__device__ __forceinline__ void mma_f16(float4& d,
                                        uint32_t a0, uint32_t a1, uint32_t a2, uint32_t a3,
                                        uint32_t b0, uint32_t b1) {
    asm volatile("mma.sync.aligned.m16n8k16.row.col.f32.f16.f16.f32 "
                 "{%0,%1,%2,%3}, {%4,%5,%6,%7}, {%8,%9}, {%0,%1,%2,%3};"
                 : "+f"(d.x), "+f"(d.y), "+f"(d.z), "+f"(d.w)
                 : "r"(a0), "r"(a1), "r"(a2), "r"(a3), "r"(b0), "r"(b1));
}

__global__ __launch_bounds__(256) void gemm_mma(
    const __half* __restrict__ A, const __half* __restrict__ Bt, __half* __restrict__ C,
    int Mrows, int K, int Ncols, const float* __restrict__ bias, int mode,
    long aStride, long bStride, long cStride,
    const float* __restrict__ attl, const float* __restrict__ attr,
    const float* __restrict__ w2) {
    int bz = blockIdx.z;
    A += (size_t)bz * aStride;
    Bt += (size_t)bz * bStride;
    C += (size_t)bz * cStride;

    __shared__ __align__(16) __half As[2][GBM * SMSH];
    __shared__ __align__(16) __half Bs[2][GBN * SMSH];

    int tid = threadIdx.x;
    int warp = tid >> 5;
    int lane = tid & 31;
    int warpM = warp >> 1;
    int warpN = warp & 1;
    int group = lane >> 2;
    int tig = lane & 3;

    int rowBase = blockIdx.y * GBM;
    int colBase = blockIdx.x * GBN;

    int cRow = tid >> 1;
    int cHalf = (tid & 1) * 16;

    int gaRow = rowBase + cRow;
    uint32_t aSz = (gaRow < Mrows) ? 16u : 0u;
    const __half* aSrcBase = A + (size_t)gaRow * K + cHalf;
    const __half* bSrcBase = Bt + (size_t)(colBase + cRow) * K + cHalf;

    uint32_t AsU = (uint32_t)__cvta_generic_to_shared(&As[0][0]);
    uint32_t BsU = (uint32_t)__cvta_generic_to_shared(&Bs[0][0]);
    uint32_t aDst = AsU + (uint32_t)((cRow * SMSH + cHalf) * 2);
    uint32_t bDst = BsU + (uint32_t)((cRow * SMSH + cHalf) * 2);

    uint32_t aPtr = AsU + (uint32_t)(((warpM * 32 + (lane & 15)) * SMSH) * 2 + (lane >> 4) * 16);
    uint32_t bPtr = BsU + (uint32_t)(((warpN * 64 + (lane >> 4) * 8 + (lane & 7)) * SMSH) * 2
                                     + (((lane >> 3) & 1) * 16));

    float4 acc[2][8];
#pragma unroll
    for (int i = 0; i < 2; i++)
#pragma unroll
        for (int j = 0; j < 8; j++) acc[i][j] = make_float4(0.f, 0.f, 0.f, 0.f);

    CP16(aDst, aSrcBase, aSz);
    CP16(aDst + 16, aSrcBase + 8, aSz);
    CP16(bDst, bSrcBase, 16u);
    CP16(bDst + 16, bSrcBase + 8, 16u);
    asm volatile("cp.async.commit_group;");

    int niter = K / GBK;
    for (int i = 0; i < niter; i++) {
        asm volatile("cp.async.wait_group 0;");
        __syncthreads();
        if (i + 1 < niter) {
            int k0 = (i + 1) * GBK;
            uint32_t so = (uint32_t)((i + 1) & 1);
            CP16(aDst + so * ASTGB, aSrcBase + k0, aSz);
            CP16(aDst + so * ASTGB + 16, aSrcBase + k0 + 8, aSz);
            CP16(bDst + so * BSTGB, bSrcBase + k0, 16u);
            CP16(bDst + so * BSTGB + 16, bSrcBase + k0 + 8, 16u);
        }
        asm volatile("cp.async.commit_group;");

        uint32_t aP = aPtr + (i & 1) * ASTGB;
        uint32_t bP = bPtr + (i & 1) * BSTGB;
#pragma unroll
        for (int kk = 0; kk < 2; kk++) {
            uint32_t kb = kk * 32;
            uint32_t af[2][4];
            LDSM4(af[0], aP + kb);
            LDSM4(af[1], aP + 16 * SMSH * 2 + kb);
            uint32_t bfr[4][4];
#pragma unroll
            for (int p = 0; p < 4; p++) LDSM4(bfr[p], bP + p * 16 * SMSH * 2 + kb);
#pragma unroll
            for (int mt = 0; mt < 2; mt++)
#pragma unroll
                for (int nt = 0; nt < 8; nt++)
                    mma_f16(acc[mt][nt], af[mt][0], af[mt][1], af[mt][2], af[mt][3],
                            bfr[nt >> 1][(nt & 1) * 2], bfr[nt >> 1][(nt & 1) * 2 + 1]);
        }
    }

    if (mode == 2) {
        int head = blockIdx.x * 2 + warpN;
        const float* alp = attl + (bz * HH + head) * DD;
        const float* arp = attr + (bz * HH + head) * DD;
        float sl[2][2] = {{0.f, 0.f}, {0.f, 0.f}};
        float sr[2][2] = {{0.f, 0.f}, {0.f, 0.f}};
#pragma unroll
        for (int mt = 0; mt < 2; mt++) {
            int row0 = rowBase + warpM * 32 + mt * 16 + group;
            int row1 = row0 + 8;
#pragma unroll
            for (int nt = 0; nt < 8; nt++) {
                int cl = nt * 8 + 2 * tig;
                float4 v = acc[mt][nt];
                float a0 = alp[cl], a1 = alp[cl + 1];
                float r0 = arp[cl], r1 = arp[cl + 1];
                sl[mt][0] += v.x * a0 + v.y * a1;
                sl[mt][1] += v.z * a0 + v.w * a1;
                sr[mt][0] += v.x * r0 + v.y * r1;
                sr[mt][1] += v.z * r0 + v.w * r1;
                int col = colBase + warpN * 64 + cl;
                if (row0 < Mrows) *(uint32_t*)(C + (size_t)row0 * Ncols + col) = f2h2(v.x, v.y);
                if (row1 < Mrows) *(uint32_t*)(C + (size_t)row1 * Ncols + col) = f2h2(v.z, v.w);
            }
        }
#pragma unroll
        for (int mt = 0; mt < 2; mt++)
#pragma unroll
            for (int r = 0; r < 2; r++) {
                sl[mt][r] += __shfl_xor_sync(0xffffffffu, sl[mt][r], 1);
                sl[mt][r] += __shfl_xor_sync(0xffffffffu, sl[mt][r], 2);
                sr[mt][r] += __shfl_xor_sync(0xffffffffu, sr[mt][r], 1);
                sr[mt][r] += __shfl_xor_sync(0xffffffffu, sr[mt][r], 2);
            }
        if (tig == 0) {
#pragma unroll
            for (int mt = 0; mt < 2; mt++) {
                int row0 = rowBase + warpM * 32 + mt * 16 + group;
                int row1 = row0 + 8;
                if (row0 < Mrows) {
                    g_el[(bz * NN + row0) * HH + head] = sl[mt][0];
                    g_er[(bz * NN + row0) * HH + head] = sr[mt][0];
                }
                if (row1 < Mrows) {
                    g_el[(bz * NN + row1) * HH + head] = sl[mt][1];
                    g_er[(bz * NN + row1) * HH + head] = sr[mt][1];
                }
            }
        }
    } else {
        float sp[2][2] = {{0.f, 0.f}, {0.f, 0.f}};
#pragma unroll
        for (int mt = 0; mt < 2; mt++) {
#pragma unroll
            for (int nt = 0; nt < 8; nt++) {
                int col = colBase + warpN * 64 + nt * 8 + 2 * tig;
                float b0 = bias[col], b1 = bias[col + 1];
                float w0 = w2[col], w1 = w2[col + 1];
                float4 v = acc[mt][nt];
                sp[mt][0] += tanhf(v.x + b0) * w0 + tanhf(v.y + b1) * w1;
                sp[mt][1] += tanhf(v.z + b0) * w0 + tanhf(v.w + b1) * w1;
            }
        }
#pragma unroll
        for (int mt = 0; mt < 2; mt++)
#pragma unroll
            for (int r = 0; r < 2; r++) {
                sp[mt][r] += __shfl_xor_sync(0xffffffffu, sp[mt][r], 1);
                sp[mt][r] += __shfl_xor_sync(0xffffffffu, sp[mt][r], 2);
            }
        if (tig == 0) {
#pragma unroll
            for (int mt = 0; mt < 2; mt++) {
                int row0 = rowBase + warpM * 32 + mt * 16 + group;
                int row1 = row0 + 8;
                if (row0 < Mrows) atomicAdd(&g_s[row0], sp[mt][0]);
                if (row1 < Mrows) atomicAdd(&g_s[row1], sp[mt][1]);
            }
        }
    }
}

// ---------------- edge pass: 2 edges/thread, front-batched loads ------------
__global__ void edge_kernel(const int* __restrict__ src, const int* __restrict__ dst) {
    int tid = blockIdx.x * blockDim.x + threadIdx.x;
    int e0 = tid * 2;
    if (e0 >= MM * EE) return;
    int e1 = e0 + 1;                     // MM*EE even -> always valid
    int m0 = e0 / EE, m1 = e1 / EE;
    int s0 = src[e0], d0 = dst[e0];
    int s1 = src[e1], d1 = dst[e1];
    const float4* el0 = (const float4*)(g_el + (size_t)(m0 * NN + s0) * HH);
    const float4* er0 = (const float4*)(g_er + (size_t)(m0 * NN + d0) * HH);
    const float4* el1 = (const float4*)(g_el + (size_t)(m1 * NN + s1) * HH);
    const float4* er1 = (const float4*)(g_er + (size_t)(m1 * NN + d1) * HH);
    float4 a0 = el0[0], a1 = el0[1], b0 = er0[0], b1 = er0[1];
    float4 c0 = el1[0], c1 = el1[1], f0 = er1[0], f1 = er1[1];

    float ex0[8], ex1[8];
    float v;
    v = a0.x + b0.x; v = v > 0.f ? v : 0.2f * v; ex0[0] = expf(v);
    v = a0.y + b0.y; v = v > 0.f ? v : 0.2f * v; ex0[1] = expf(v);
    v = a0.z + b0.z; v = v > 0.f ? v : 0.2f * v; ex0[2] = expf(v);
    v = a0.w + b0.w; v = v > 0.f ? v : 0.2f * v; ex0[3] = expf(v);
    v = a1.x + b1.x; v = v > 0.f ? v : 0.2f * v; ex0[4] = expf(v);
    v = a1.y + b1.y; v = v > 0.f ? v : 0.2f * v; ex0[5] = expf(v);
    v = a1.z + b1.z; v = v > 0.f ? v : 0.2f * v; ex0[6] = expf(v);
    v = a1.w + b1.w; v = v > 0.f ? v : 0.2f * v; ex0[7] = expf(v);
    v = c0.x + f0.x; v = v > 0.f ? v : 0.2f * v; ex1[0] = expf(v);
    v = c0.y + f0.y; v = v > 0.f ? v : 0.2f * v; ex1[1] = expf(v);
    v = c0.z + f0.z; v = v > 0.f ? v : 0.2f * v; ex1[2] = expf(v);
    v = c0.w + f0.w; v = v > 0.f ? v : 0.2f * v; ex1[3] = expf(v);
    v = c1.x + f1.x; v = v > 0.f ? v : 0.2f * v; ex1[4] = expf(v);
    v = c1.y + f1.y; v = v > 0.f ? v : 0.2f * v; ex1[5] = expf(v);
    v = c1.z + f1.z; v = v > 0.f ? v : 0.2f * v; ex1[6] = expf(v);
    v = c1.w + f1.w; v = v > 0.f ? v : 0.2f * v; ex1[7] = expf(v);

    int p0 = atomicAdd(&g_cursor[m0 * NN + d0], 1);
    int p1 = atomicAdd(&g_cursor[m1 * NN + d1], 1);
    int gp0 = m0 * EE + p0;
    int gp1 = m1 * EE + p1;
    g_src_s[gp0] = s0;
    g_src_s[gp1] = s1;
    *(uint4*)(g_ex_s + (size_t)gp0 * HH) =
        make_uint4(f2h2(ex0[0], ex0[1]), f2h2(ex0[2], ex0[3]),
                   f2h2(ex0[4], ex0[5]), f2h2(ex0[6], ex0[7]));
    *(uint4*)(g_ex_s + (size_t)gp1 * HH) =
        make_uint4(f2h2(ex1[0], ex1[1]), f2h2(ex1[2], ex1[3]),
                   f2h2(ex1[4], ex1[5]), f2h2(ex1[6], ex1[7]));
}

// ---------------- aggregation + fused classifier (4-wide gather unroll) -----
__global__ void agg_kernel(const float* __restrict__ bg, const float* __restrict__ pW) {
    int n = blockIdx.x;
    int m = blockIdx.y;
    int t = threadIdx.x;
    int h = t >> 4;
    int beg = g_rowptr[m * (NN + 1) + n];
    int end = g_rowptr[m * (NN + 1) + n + 1];
    float ax = 0.f, ay = 0.f, az = 0.f, aw = 0.f;
    float dsum = 0.f;
    const __half* featB = g_feat + (size_t)m * NN * HD + t * 4;
    int j = beg;
    for (; j + 3 < end; j += 4) {
        int gp = m * EE + j;
        int s0 = __ldg(&g_src_s[gp]);
        int s1 = __ldg(&g_src_s[gp + 1]);
        int s2 = __ldg(&g_src_s[gp + 2]);
        int s3 = __ldg(&g_src_s[gp + 3]);
        float e0 = __half2float(g_ex_s[(size_t)gp * HH + h]);
        float e1 = __half2float(g_ex_s[(size_t)(gp + 1) * HH + h]);
        float e2 = __half2float(g_ex_s[(size_t)(gp + 2) * HH + h]);
        float e3 = __half2float(g_ex_s[(size_t)(gp + 3) * HH + h]);
        uint2 v0 = __ldg((const uint2*)(featB + (size_t)s0 * HD));
        uint2 v1 = __ldg((const uint2*)(featB + (size_t)s1 * HD));
        uint2 v2 = __ldg((const uint2*)(featB + (size_t)s2 * HD));
        uint2 v3 = __ldg((const uint2*)(featB + (size_t)s3 * HD));
        dsum += (e0 + e1) + (e2 + e3);
        float2 a01, a23;
        a01 = __half22float2(*(__half2*)&v0.x); a23 = __half22float2(*(__half2*)&v0.y);
        ax += e0 * a01.x; ay += e0 * a01.y; az += e0 * a23.x; aw += e0 * a23.y;
        a01 = __half22float2(*(__half2*)&v1.x); a23 = __half22float2(*(__half2*)&v1.y);
        ax += e1 * a01.x; ay += e1 * a01.y; az += e1 * a23.x; aw += e1 * a23.y;
        a01 = __half22float2(*(__half2*)&v2.x); a23 = __half22float2(*(__half2*)&v2.y);
        ax += e2 * a01.x; ay += e2 * a01.y; az += e2 * a23.x; aw += e2 * a23.y;
        a01 = __half22float2(*(__half2*)&v3.x); a23 = __half22float2(*(__half2*)&v3.y);
        ax += e3 * a01.x; ay += e3 * a01.y; az += e3 * a23.x; aw += e3 * a23.y;
    }
    for (; j < end; j++) {
        int gp = m * EE + j;
        int s = __ldg(&g_src_s[gp]);
        float exv = __half2float(g_ex_s[(size_t)gp * HH + h]);
        dsum += exv;
        uint2 fv = __ldg((const uint2*)(featB + (size_t)s * HD));
        float2 f01 = __half22float2(*(__half2*)&fv.x);
        float2 f23 = __half22float2(*(__half2*)&fv.y);
        ax += exv * f01.x; ay += exv * f01.y; az += exv * f23.x; aw += exv * f23.y;
    }
    float inv = 1.0f / fmaxf(dsum, 1e-9f);
    const float* bp = bg + m * HD + t * 4;
    float o0 = ax * inv + bp[0], o1 = ay * inv + bp[1];
    float o2 = az * inv + bp[2], o3 = aw * inv + bp[3];
    o0 = o0 > 0.f ? o0 : expf(o0) - 1.0f;
    o1 = o1 > 0.f ? o1 : expf(o1) - 1.0f;
    o2 = o2 > 0.f ? o2 : expf(o2) - 1.0f;
    o3 = o3 > 0.f ? o3 : expf(o3) - 1.0f;
    *(uint2*)(g_z + ((size_t)(m * NN + n)) * HD + t * 4) =
        make_uint2(f2h2(o0, o1), f2h2(o2, o3));

    const float* w = pW + (size_t)t * 4 * CC;
    float yc[CC];
#pragma unroll
    for (int c = 0; c < CC; c++)
        yc[c] = o0 * w[c] + o1 * w[CC + c] + o2 * w[2 * CC + c] + o3 * w[3 * CC + c];
#pragma unroll
    for (int c = 0; c < CC; c++)
#pragma unroll
        for (int off = 16; off > 0; off >>= 1)
            yc[c] += __shfl_down_sync(0xffffffffu, yc[c], off);
    __shared__ float ysh[4][CC];
    int warp = t >> 5, lane = t & 31;
    if (lane == 0)
#pragma unroll
        for (int c = 0; c < CC; c++) ysh[warp][c] = yc[c];
    __syncthreads();
    if (t < CC) {
        float v = ysh[0][t] + ysh[1][t] + ysh[2][t] + ysh[3][t];
        g_y[((size_t)m * NN + n) * CC + t] = v;
    }
}

// ---------------- mean over nodes per metapath ----------------
__global__ void reduce_kernel() {
    int m = blockIdx.y;
    int t = threadIdx.x;
    float s = 0.f;
    for (int i = blockIdx.x * blockDim.x + t; i < NN; i += gridDim.x * blockDim.x)
        s += g_s[m * NN + i];
    __shared__ float sh[256];
    sh[t] = s;
    __syncthreads();
    for (int off = 128; off > 0; off >>= 1) {
        if (t < off) sh[t] += sh[t + off];
        __syncthreads();
    }
    if (t == 0) atomicAdd(&g_sum[m], sh[0]);
}

// ---------------- final: beta inline + out = b0*y0 + b1*y1 + pb -------------
__global__ void final_kernel(const float* __restrict__ pb, float* __restrict__ out) {
    int tid = blockIdx.x * blockDim.x + threadIdx.x;
    if (tid >= NN * CC) return;
    float a = g_sum[0] * (1.0f / NN);
    float b = g_sum[1] * (1.0f / NN);
    float mx = fmaxf(a, b);
    float e0 = expf(a - mx), e1 = expf(b - mx);
    float inv = 1.0f / (e0 + e1);
    float b0 = e0 * inv, b1 = e1 * inv;
    int c = tid % CC;
    out[tid] = b0 * g_y[tid] + b1 * g_y[NN * CC + tid] + pb[c];
}

// ---------------- launch ----------------
extern "C" void kernel_launch(void* const* d_in, const int* in_sizes, int n_in,
                              void* d_out, int out_size) {
    const float* h    = (const float*)d_in[0];
    const int*   src  = (const int*)d_in[1];
    const int*   dst  = (const int*)d_in[2];
    const float* W    = (const float*)d_in[3];
    const float* al   = (const float*)d_in[4];
    const float* ar   = (const float*)d_in[5];
    const float* bg   = (const float*)d_in[6];
    const float* sW1  = (const float*)d_in[7];
    const float* sb1  = (const float*)d_in[8];
    const float* sW2  = (const float*)d_in[9];
    const float* pW   = (const float*)d_in[10];
    const float* pb   = (const float*)d_in[11];
    float* out = (float*)d_out;

    __half *p_h16, *p_Wt16, *p_sW1t16, *p_feat, *p_z;
    cudaGetSymbolAddress((void**)&p_h16, g_h16);
    cudaGetSymbolAddress((void**)&p_Wt16, g_Wt16);
    cudaGetSymbolAddress((void**)&p_sW1t16, g_sW1t16);
    cudaGetSymbolAddress((void**)&p_feat, g_feat);
    cudaGetSymbolAddress((void**)&p_z, g_z);

    zero_hist_kernel<<<80, 512>>>();                               // 1
    mega_prep<<<MP_TOTAL, 256>>>(h, W, sW1, dst);                  // 2
    scan1_kernel<<<dim3(SB, MM), 512>>>();                         // 3
    scan2_kernel<<<dim3(SB, MM), 512>>>();                         // 4

    // 5: feat[m] = h @ W[m], fused el/er epilogue (2 heads per CTA)
    gemm_mma<<<dim3(HD / GBN, (NN + GBM - 1) / GBM, MM), 256>>>(
        p_h16, p_Wt16, p_feat, NN, FF, HD, nullptr, 2,
        0L, (long)HD * FF, (long)NN * HD, al, ar, nullptr);

    edge_kernel<<<(MM * EE / 2 + 255) / 256, 256>>>(src, dst);     // 6
    agg_kernel<<<dim3(NN, MM), 128>>>(bg, pW);                     // 7

    // 8: semantic — s[row] += sum tanh(z@W1 + b1) * W2, no C write
    gemm_mma<<<dim3(HIDD / GBN, (MM * NN + GBM - 1) / GBM, 1), 256>>>(
        p_z, p_sW1t16, nullptr, MM * NN, HD, HIDD, sb1, 3,
        0L, 0L, 0L, nullptr, nullptr, sW2);

    reduce_kernel<<<dim3(40, MM), 256>>>();                        // 9
    final_kernel<<<(NN * CC + 255) / 256, 256>>>(pb, out);         // 10
}